// round 4
// baseline (speedup 1.0000x reference)
#include <cuda_runtime.h>
#include <cuda_bf16.h>
#include <math.h>
#include <stdint.h>

// ---------------- problem constants ----------------
#define NB    16
#define LSEQ  128
#define DH    768
#define MSP   8
#define HH    8
#define JR    30
#define RR    49
#define IMGD  2048
#define NM    128            // NB*MSP
#define ROWS  3840           // NM*JR
#define NR    784            // NB*RR

typedef __nv_bfloat16 bf16;

// ---------------- scratch (device globals; no cudaMalloc allowed) ----------------
__device__ bf16 g_enc_hi[NR * IMGD],        g_enc_lo[NR * IMGD];
__device__ bf16 g_WalT_hi[DH * IMGD],       g_WalT_lo[DH * IMGD];
__device__ bf16 g_Wq_hi[DH * HH * DH],      g_Wq_lo[DH * HH * DH];
__device__ bf16 g_Wk_hi[DH * HH * DH],      g_Wk_lo[DH * HH * DH];
__device__ bf16 g_Wv_hi[DH * HH * DH],      g_Wv_lo[DH * HH * DH];
__device__ bf16 g_WfcT_hi[DH * HH * DH],    g_WfcT_lo[DH * HH * DH];
__device__ bf16 g_C1_hi[NR * DH],           g_C1_lo[NR * DH];
__device__ bf16 g_Bqk_hi[HH * DH * DH],     g_Bqk_lo[HH * DH * DH];
__device__ bf16 g_WvfT_hi[HH * DH * DH],    g_WvfT_lo[HH * DH * DH];
__device__ float g_KC[HH * NR * DH];
__device__ float g_VC[HH * NR * DH];
__device__ float g_span[ROWS * DH];
__device__ float g_att[ROWS * DH];
__device__ float g_P[NM * HH * JR * RR];
__device__ bf16 g_cat_hi[ROWS * 2 * DH],    g_cat_lo[ROWS * 2 * DH];
__device__ bf16 g_Wa1T_hi[2*DH * 2*DH],     g_Wa1T_lo[2*DH * 2*DH];
__device__ bf16 g_f1_hi[ROWS * 2 * DH],     g_f1_lo[ROWS * 2 * DH];
__device__ bf16 g_Wa2T_hi[DH * 2*DH],       g_Wa2T_lo[DH * 2*DH];
__device__ float g_fused[ROWS * DH];
__device__ float g_pool[NM * DH];
__device__ float g_hid[NM * DH];

// ---------------- warp-mma helpers ----------------
__device__ __forceinline__ uint32_t smem_u32(const void* p) {
    uint32_t a;
    asm("{ .reg .u64 t; cvta.to.shared.u64 t, %1; cvt.u32.u64 %0, t; }" : "=r"(a) : "l"(p));
    return a;
}

__device__ __forceinline__ void ldm_x4(uint32_t* r, uint32_t addr) {
    asm volatile("ldmatrix.sync.aligned.m8n8.x4.shared.b16 {%0,%1,%2,%3}, [%4];"
                 : "=r"(r[0]), "=r"(r[1]), "=r"(r[2]), "=r"(r[3]) : "r"(addr));
}

__device__ __forceinline__ void mma16816(float* c, const uint32_t* a, uint32_t b0, uint32_t b1) {
    asm volatile(
        "mma.sync.aligned.m16n8k16.row.col.f32.bf16.bf16.f32 "
        "{%0,%1,%2,%3}, {%4,%5,%6,%7}, {%8,%9}, {%0,%1,%2,%3};"
        : "+f"(c[0]), "+f"(c[1]), "+f"(c[2]), "+f"(c[3])
        : "r"(a[0]), "r"(a[1]), "r"(a[2]), "r"(a[3]), "r"(b0), "r"(b1));
}

__device__ __forceinline__ void cpa16(uint32_t dst, const void* src) {
    asm volatile("cp.async.ca.shared.global [%0], [%1], 16;" :: "r"(dst), "l"(src));
}
__device__ __forceinline__ void cpa_commit() {
    asm volatile("cp.async.commit_group;" ::: "memory");
}
template<int N_>
__device__ __forceinline__ void cpa_wait() {
    asm volatile("cp.async.wait_group %0;" :: "n"(N_) : "memory");
}

// ---------------- split-bf16 tensor-core GEMM (double-buffered cp.async) ----------------
// C[M,N] = act( sum_k A[m,k]*B[n,k] + bias[n] ),  A,B as hi/lo bf16.
// Ahi*Bhi + Ahi*Blo + Alo*Bhi. Block 256x128, BK=32, 8 warps (4x2), warp 64x64.
#define BM 256
#define BN 128
#define BK 32
#define SPAD 40                        // padded row (bf16): 80B rows
#define OFF_AL (BM * SPAD)             // elem offsets inside a stage
#define OFF_BH (2 * BM * SPAD)
#define OFF_BL (2 * BM * SPAD + BN * SPAD)
#define STAGE_ELEMS (2 * BM * SPAD + 2 * BN * SPAD)       // 30720
#define STAGE_BYTES (STAGE_ELEMS * 2)                      // 61440
#define MM_SMEM (2 * STAGE_BYTES)                          // 122880

template<bool OUT_BF16, bool BIAS, bool TANH_ACT>
__global__ __launch_bounds__(256, 1)
void mmgemm(const bf16* __restrict__ Ahi, const bf16* __restrict__ Alo, int lda, long sA,
            const bf16* __restrict__ Bhi, const bf16* __restrict__ Blo, int ldb, long sB,
            float* __restrict__ Cf, bf16* __restrict__ Chi, bf16* __restrict__ Clo,
            int ldc, long sC, const float* __restrict__ bias,
            int M, int N, int K)
{
    extern __shared__ char dsm[];
    const uint32_t u_sm = smem_u32(dsm);

    Ahi += (long)blockIdx.z * sA;  Alo += (long)blockIdx.z * sA;
    Bhi += (long)blockIdx.z * sB;  Blo += (long)blockIdx.z * sB;
    const long coff = (long)blockIdx.z * sC;

    const int tid = threadIdx.x, lane = tid & 31, wid = tid >> 5;
    const int wr = wid >> 1, wc = wid & 1;              // 4x2 warps, 64x64 each
    const int m0 = blockIdx.y * BM, n0 = blockIdx.x * BN;

    float acc[4][8][4];
#pragma unroll
    for (int i = 0; i < 4; i++)
#pragma unroll
        for (int j = 0; j < 8; j++)
#pragma unroll
            for (int e = 0; e < 4; e++) acc[i][j][e] = 0.f;

    // ldmatrix per-thread base addresses (stage 0)
    const int lrow = lane & 15;
    const uint32_t lkb = (uint32_t)((lane >> 4) * 16);    // k-half byte offset
    const uint32_t aA = u_sm + (uint32_t)((wr * 64 + lrow) * SPAD * 2) + lkb;
    const uint32_t aB = u_sm + (uint32_t)(OFF_BH * 2) + (uint32_t)((wc * 64 + lrow) * SPAD * 2) + lkb;

    // ---- async stage loader: 12 x 16B per thread ----
    auto load_stage = [&](int st, int k0) {
        const uint32_t sbase = u_sm + (uint32_t)(st * STAGE_BYTES);
#pragma unroll
        for (int i = 0; i < 12; i++) {
            int u = tid + i * 256;
            const bf16* src;
            uint32_t doff;
            if (u < 1024) {
                int r = u >> 2, sg = (u & 3) << 3;
                int ga = m0 + r; if (ga > M - 1) ga = M - 1;
                src = Ahi + (long)ga * lda + k0 + sg;
                doff = (uint32_t)((r * SPAD + sg) * 2);
            } else if (u < 2048) {
                int v = u - 1024; int r = v >> 2, sg = (v & 3) << 3;
                int ga = m0 + r; if (ga > M - 1) ga = M - 1;
                src = Alo + (long)ga * lda + k0 + sg;
                doff = (uint32_t)((OFF_AL + r * SPAD + sg) * 2);
            } else if (u < 2560) {
                int v = u - 2048; int r = v >> 2, sg = (v & 3) << 3;
                int gb = n0 + r; if (gb > N - 1) gb = N - 1;
                src = Bhi + (long)gb * ldb + k0 + sg;
                doff = (uint32_t)((OFF_BH + r * SPAD + sg) * 2);
            } else {
                int v = u - 2560; int r = v >> 2, sg = (v & 3) << 3;
                int gb = n0 + r; if (gb > N - 1) gb = N - 1;
                src = Blo + (long)gb * ldb + k0 + sg;
                doff = (uint32_t)((OFF_BL + r * SPAD + sg) * 2);
            }
            cpa16(sbase + doff, src);
        }
    };

    const int nch = K / BK;
    load_stage(0, 0);
    cpa_commit();

    for (int ch = 0; ch < nch; ch++) {
        const int cur = ch & 1;
        if (ch + 1 < nch) {
            load_stage((ch + 1) & 1, (ch + 1) * BK);
            cpa_commit();
            cpa_wait<1>();
        } else {
            cpa_wait<0>();
        }
        __syncthreads();

        const uint32_t so = (uint32_t)(cur * STAGE_BYTES);
#pragma unroll
        for (int ks = 0; ks < 2; ks++) {
            const uint32_t ko = so + (uint32_t)(ks * 16 * 2);
            uint32_t bh[4][4], bl[4][4];
#pragma unroll
            for (int nt = 0; nt < 4; nt++) {
                ldm_x4(bh[nt], aB + (uint32_t)(nt * 16 * SPAD * 2) + ko);
                ldm_x4(bl[nt], aB + (uint32_t)((BN * SPAD + nt * 16 * SPAD) * 2) + ko);
            }
#pragma unroll
            for (int mi = 0; mi < 4; mi++) {
                uint32_t ah[4], al[4];
                ldm_x4(ah, aA + (uint32_t)(mi * 16 * SPAD * 2) + ko);
                ldm_x4(al, aA + (uint32_t)((OFF_AL + mi * 16 * SPAD) * 2) + ko);
#pragma unroll
                for (int nt = 0; nt < 4; nt++) {
#pragma unroll
                    for (int j = 0; j < 2; j++) {
                        const int nj = nt * 2 + j;
                        mma16816(acc[mi][nj], ah, bh[nt][j], bh[nt][j + 2]);
                        mma16816(acc[mi][nj], ah, bl[nt][j], bl[nt][j + 2]);
                        mma16816(acc[mi][nj], al, bh[nt][j], bh[nt][j + 2]);
                    }
                }
            }
        }
        __syncthreads();
    }

    // epilogue
    const int er = m0 + wr * 64 + (lane >> 2);
    const int ec = n0 + wc * 64 + (lane & 3) * 2;
#pragma unroll
    for (int mi = 0; mi < 4; mi++) {
#pragma unroll
        for (int nj = 0; nj < 8; nj++) {
            const int col = ec + nj * 8;
            float bv0 = 0.f, bv1 = 0.f;
            if (BIAS) { bv0 = bias[col]; bv1 = bias[col + 1]; }
#pragma unroll
            for (int half = 0; half < 2; half++) {
                const int row = er + mi * 16 + half * 8;
                if (row >= M) continue;
                float v0 = acc[mi][nj][half * 2 + 0] + bv0;
                float v1 = acc[mi][nj][half * 2 + 1] + bv1;
                if (TANH_ACT) { v0 = tanhf(v0); v1 = tanhf(v1); }
                const long base = (long)row * ldc + coff + col;
                if (OUT_BF16) {
                    bf16 h0 = __float2bfloat16(v0);
                    bf16 h1 = __float2bfloat16(v1);
                    Chi[base] = h0;     Chi[base + 1] = h1;
                    Clo[base]     = __float2bfloat16(v0 - __bfloat162float(h0));
                    Clo[base + 1] = __float2bfloat16(v1 - __bfloat162float(h1));
                } else {
                    Cf[base] = v0;  Cf[base + 1] = v1;
                }
            }
        }
    }
}

// ---------------- fp32 -> bf16 hi/lo split (elementwise) ----------------
__global__ void split_kernel(const float* __restrict__ in, bf16* __restrict__ hi,
                             bf16* __restrict__ lo, long n)
{
    long i0 = ((long)blockIdx.x * blockDim.x + threadIdx.x) * 4;
    long stride = (long)gridDim.x * blockDim.x * 4;
    for (long i = i0; i < n; i += stride) {
        float4 v = *reinterpret_cast<const float4*>(in + i);
        float vv[4] = {v.x, v.y, v.z, v.w};
#pragma unroll
        for (int j = 0; j < 4; j++) {
            bf16 h = __float2bfloat16(vv[j]);
            hi[i + j] = h;
            lo[i + j] = __float2bfloat16(vv[j] - __bfloat162float(h));
        }
    }
}

// ---------------- fp32 [R,C] -> transposed bf16 hi/lo [C,R] ----------------
__global__ void splitT_kernel(const float* __restrict__ in, bf16* __restrict__ hi,
                              bf16* __restrict__ lo, int R, int C)
{
    __shared__ float t[32][33];
    int c0 = blockIdx.x * 32, r0 = blockIdx.y * 32;
    for (int i = threadIdx.y; i < 32; i += 8)
        t[i][threadIdx.x] = in[(long)(r0 + i) * C + c0 + threadIdx.x];
    __syncthreads();
    for (int i = threadIdx.y; i < 32; i += 8) {
        float v = t[threadIdx.x][i];
        long o = (long)(c0 + i) * R + r0 + threadIdx.x;
        bf16 h = __float2bfloat16(v);
        hi[o] = h;
        lo[o] = __float2bfloat16(v - __bfloat162float(h));
    }
}

// ---------------- concat(span, att) -> bf16 hi/lo ----------------
__global__ void concat_split_kernel()
{
    int row = blockIdx.x, t = threadIdx.x;
    for (int idx = t; idx < 2 * DH; idx += 256) {
        float v = (idx < DH) ? g_span[(long)row * DH + idx]
                             : g_att[(long)row * DH + idx - DH];
        long o = (long)row * 2 * DH + idx;
        bf16 h = __float2bfloat16(v);
        g_cat_hi[o] = h;
        g_cat_lo[o] = __float2bfloat16(v - __bfloat162float(h));
    }
}

// ---------------- span gather ----------------
__global__ void gather_kernel(const float* __restrict__ seq, const int* __restrict__ starts)
{
    int row = blockIdx.x;
    int sp = row / JR, j = row - sp * JR;
    int n = sp >> 3;
    int tok = starts[sp] + n * LSEQ + j;
    if (tok > NB * LSEQ - 1) tok = NB * LSEQ - 1;
    const float4* src = reinterpret_cast<const float4*>(seq + (long)tok * DH);
    float4* dst = reinterpret_cast<float4*>(g_span + (long)row * DH);
    int t = threadIdx.x;
    if (t < DH / 4) dst[t] = src[t];
}

// ---------------- attention scores + softmax (per span, head) ----------------
__global__ void att_scores_kernel()
{
    const int h = blockIdx.x, s = blockIdx.y;
    const int b = s >> 3;
    __shared__ float sQ[JR][129];
    __shared__ float sK[RR][129];
    __shared__ float sS[JR * RR];
    const int t = threadIdx.x;
    const int q = t % JR, rg = t / JR;

    int rr[7];
#pragma unroll
    for (int i = 0; i < 7; i++) { int r = rg + i * 8; rr[i] = (r < RR) ? r : 0; }
    float acc[7];
#pragma unroll
    for (int i = 0; i < 7; i++) acc[i] = 0.f;

    const float* Qp = g_span + (long)s * JR * DH;
    const float* Kp = g_KC + ((long)h * NR + (long)b * RR) * DH;

    for (int k0 = 0; k0 < DH; k0 += 128) {
        for (int e = t; e < JR * 128; e += 256)
            sQ[e >> 7][e & 127] = Qp[(long)(e >> 7) * DH + k0 + (e & 127)];
        for (int e = t; e < RR * 128; e += 256)
            sK[e >> 7][e & 127] = Kp[(long)(e >> 7) * DH + k0 + (e & 127)];
        __syncthreads();
        if (t < 240) {
            for (int kk = 0; kk < 128; kk++) {
                float a = sQ[q][kk];
#pragma unroll
                for (int i = 0; i < 7; i++) acc[i] += a * sK[rr[i]][kk];
            }
        }
        __syncthreads();
    }

    const float scale = 1.0f / sqrtf((float)DH);
    if (t < 240) {
#pragma unroll
        for (int i = 0; i < 7; i++) {
            int r = rg + i * 8;
            if (r < RR) sS[q * RR + r] = acc[i] * scale;
        }
    }
    __syncthreads();

    if (t < JR) {
        float* row = sS + t * RR;
        float mx = row[0];
        for (int r = 1; r < RR; r++) mx = fmaxf(mx, row[r]);
        float sum = 0.f;
        for (int r = 0; r < RR; r++) { float e = expf(row[r] - mx); row[r] = e; sum += e; }
        float inv = 1.f / sum;
        float* out = g_P + (((long)s * HH + h) * JR + t) * RR;
        for (int r = 0; r < RR; r++) out[r] = row[r] * inv;
    }
}

// ---------------- out = sum_h P_h @ VC_h + residual (per span) ----------------
__global__ void att_out_kernel()
{
    const int s = blockIdx.x, b = s >> 3, t = threadIdx.x;
    __shared__ float sP[HH * JR * RR];
    for (int e = t; e < HH * JR * RR; e += 256)
        sP[e] = g_P[(long)s * HH * JR * RR + e];
    __syncthreads();

    for (int dc = 0; dc < 3; dc++) {
        int d = dc * 256 + t;
        float acc[JR];
#pragma unroll
        for (int q = 0; q < JR; q++) acc[q] = 0.f;
        for (int h = 0; h < HH; h++) {
            const float* V = g_VC + ((long)h * NR + (long)b * RR) * DH + d;
            const float* P = sP + h * JR * RR;
            for (int r = 0; r < RR; r++) {
                float v = V[(long)r * DH];
#pragma unroll
                for (int q = 0; q < JR; q++) acc[q] += P[q * RR + r] * v;
            }
        }
        for (int q = 0; q < JR; q++) {
            long idx = ((long)s * JR + q) * DH + d;
            g_att[idx] = acc[q] + g_span[idx];
        }
    }
}

// ---------------- layernorm (in place on g_att) ----------------
__global__ void ln_kernel(const float* __restrict__ gam, const float* __restrict__ bet)
{
    int row = blockIdx.x, t = threadIdx.x;
    float* x = g_att + (long)row * DH;
    float v0 = x[t], v1 = x[t + 256], v2 = x[t + 512];
    __shared__ float red[256];
    red[t] = v0 + v1 + v2;
    __syncthreads();
    for (int o = 128; o > 0; o >>= 1) { if (t < o) red[t] += red[t + o]; __syncthreads(); }
    float mu = red[0] * (1.f / DH);
    __syncthreads();
    float d0 = v0 - mu, d1 = v1 - mu, d2 = v2 - mu;
    red[t] = d0 * d0 + d1 * d1 + d2 * d2;
    __syncthreads();
    for (int o = 128; o > 0; o >>= 1) { if (t < o) red[t] += red[t + o]; __syncthreads(); }
    float rstd = rsqrtf(red[0] * (1.f / DH) + 1e-5f);
    x[t]       = d0 * rstd * gam[t]       + bet[t];
    x[t + 256] = d1 * rstd * gam[t + 256] + bet[t + 256];
    x[t + 512] = d2 * rstd * gam[t + 512] + bet[t + 512];
}

// ---------------- unary score + masked softmax pooling ----------------
__global__ void pool_kernel(const float* __restrict__ W_un, const float* __restrict__ b_un,
                            const int* __restrict__ starts, const int* __restrict__ ends)
{
    int sp = blockIdx.x, t = threadIdx.x;
    int lane = t & 31, w = t >> 5;
    __shared__ float sS[JR];
    __shared__ float sProb[JR];

    for (int j = w; j < JR; j += 8) {
        const float* fr = g_fused + ((long)sp * JR + j) * DH;
        float acc = 0.f;
        for (int k = lane; k < DH; k += 32) acc += fr[k] * W_un[k];
        for (int o = 16; o; o >>= 1) acc += __shfl_xor_sync(0xffffffffu, acc, o);
        if (lane == 0) sS[j] = acc + b_un[0];
    }
    __syncthreads();
    if (t == 0) {
        int width = ends[sp] - starts[sp] + 1;
        float mx = -1e30f;
        for (int j = 0; j < JR; j++) {
            float v = sS[j] + ((j < width) ? 0.f : -10000.f);
            sS[j] = v; mx = fmaxf(mx, v);
        }
        float sum = 0.f;
        for (int j = 0; j < JR; j++) { float e = expf(sS[j] - mx); sProb[j] = e; sum += e; }
        float inv = 1.f / sum;
        for (int j = 0; j < JR; j++) sProb[j] *= inv;
    }
    __syncthreads();
    for (int d = t; d < DH; d += 256) {
        float acc = 0.f;
        for (int j = 0; j < JR; j++) acc += sProb[j] * g_fused[((long)sp * JR + j) * DH + d];
        g_pool[(long)sp * DH + d] = acc;
    }
}

// ---------------- small fp32 sgemm (tiny dense layer only) ----------------
template<bool TRANSB, bool BIAS, bool TANH_ACT>
__global__ void sgemm(const float* __restrict__ A, int lda, long sA,
                      const float* __restrict__ B, int ldb, long sB,
                      float* __restrict__ C, int ldc, long sC,
                      const float* __restrict__ bias,
                      int M, int N, int K)
{
    A += (long)blockIdx.z * sA;
    B += (long)blockIdx.z * sB;
    C += (long)blockIdx.z * sC;
    __shared__ float As[16][128];
    __shared__ float Bs[16][128];
    const int tid = threadIdx.x;
    const int m0 = blockIdx.y * 128;
    const int n0 = blockIdx.x * 128;
    const int tx = tid & 15;
    const int ty = tid >> 4;
    float acc[8][8];
#pragma unroll
    for (int i = 0; i < 8; i++)
#pragma unroll
        for (int j = 0; j < 8; j++) acc[i][j] = 0.f;

    for (int k0 = 0; k0 < K; k0 += 16) {
#pragma unroll
        for (int i = 0; i < 2; i++) {
            int li = tid + i * 256;
            int row = li >> 2;
            int kk  = (li & 3) << 2;
            float4 v = make_float4(0.f, 0.f, 0.f, 0.f);
            if (m0 + row < M)
                v = *reinterpret_cast<const float4*>(&A[(long)(m0 + row) * lda + k0 + kk]);
            As[kk + 0][row] = v.x; As[kk + 1][row] = v.y;
            As[kk + 2][row] = v.z; As[kk + 3][row] = v.w;
        }
        if (!TRANSB) {
#pragma unroll
            for (int i = 0; i < 2; i++) {
                int li = tid + i * 256;
                int kr = li >> 5;
                int nn = (li & 31) << 2;
                float4 v = *reinterpret_cast<const float4*>(&B[(long)(k0 + kr) * ldb + n0 + nn]);
                *reinterpret_cast<float4*>(&Bs[kr][nn]) = v;
            }
        } else {
#pragma unroll
            for (int i = 0; i < 2; i++) {
                int li = tid + i * 256;
                int nr = li >> 2;
                int kk = (li & 3) << 2;
                float4 v = make_float4(0.f, 0.f, 0.f, 0.f);
                if (n0 + nr < N)
                    v = *reinterpret_cast<const float4*>(&B[(long)(n0 + nr) * ldb + k0 + kk]);
                Bs[kk + 0][nr] = v.x; Bs[kk + 1][nr] = v.y;
                Bs[kk + 2][nr] = v.z; Bs[kk + 3][nr] = v.w;
            }
        }
        __syncthreads();
#pragma unroll
        for (int k = 0; k < 16; k++) {
            float a[8], b[8];
#pragma unroll
            for (int i = 0; i < 8; i++) a[i] = As[k][ty * 8 + i];
#pragma unroll
            for (int j = 0; j < 8; j++) b[j] = Bs[k][tx * 8 + j];
#pragma unroll
            for (int i = 0; i < 8; i++)
#pragma unroll
                for (int j = 0; j < 8; j++) acc[i][j] += a[i] * b[j];
        }
        __syncthreads();
    }
#pragma unroll
    for (int i = 0; i < 8; i++) {
        int m = m0 + ty * 8 + i;
        if (m >= M) continue;
#pragma unroll
        for (int j = 0; j < 8; j++) {
            int n = n0 + tx * 8 + j;
            float v = acc[i][j];
            if (BIAS) v += bias[n];
            if (TANH_ACT) v = tanhf(v);
            C[(long)m * ldc + n] = v;
        }
    }
}

// ---------------- classifier ----------------
__global__ void cls_kernel(const float* __restrict__ W_cls, const float* __restrict__ b_cls,
                           float* __restrict__ out)
{
    int row = blockIdx.x, t = threadIdx.x;
    int lane = t & 31, c = t >> 5;
    const float* hr = g_hid + (long)row * DH;
    float acc = 0.f;
    for (int k = lane; k < DH; k += 32) acc += hr[k] * W_cls[k * 4 + c];
    for (int o = 16; o; o >>= 1) acc += __shfl_xor_sync(0xffffffffu, acc, o);
    if (lane == 0) out[row * 4 + c] = acc + b_cls[c];
}

// ---------------- launcher ----------------
extern "C" void kernel_launch(void* const* d_in, const int* in_sizes, int n_in,
                              void* d_out, int out_size)
{
    const float* enc_img  = (const float*)d_in[0];
    const float* seq      = (const float*)d_in[1];
    const int*   starts   = (const int*)d_in[3];
    const int*   ends     = (const int*)d_in[4];
    const float* W_align  = (const float*)d_in[5];
    const float* b_align  = (const float*)d_in[6];
    const float* Wq       = (const float*)d_in[7];
    const float* Wk       = (const float*)d_in[8];
    const float* Wv       = (const float*)d_in[9];
    const float* Wfc      = (const float*)d_in[10];
    const float* ln_g     = (const float*)d_in[11];
    const float* ln_b     = (const float*)d_in[12];
    const float* W_a1     = (const float*)d_in[13];
    const float* b_a1     = (const float*)d_in[14];
    const float* W_a2     = (const float*)d_in[15];
    const float* b_a2     = (const float*)d_in[16];
    const float* W_un     = (const float*)d_in[17];
    const float* b_un     = (const float*)d_in[18];
    const float* W_dense  = (const float*)d_in[19];
    const float* b_dense  = (const float*)d_in[20];
    const float* W_cls    = (const float*)d_in[21];
    const float* b_cls    = (const float*)d_in[22];

    bf16 *eh, *el, *wath, *watl, *wqh, *wql, *wkh, *wkl, *wvh, *wvl, *wfh, *wfl;
    bf16 *c1h, *c1l, *bqh, *bql, *wvfh, *wvfl;
    bf16 *cth, *ctl, *wa1h, *wa1l, *f1h, *f1l, *wa2h, *wa2l;
    float *pKC, *pVC, *pFused, *pPool, *pHid;
    cudaGetSymbolAddress((void**)&eh,   g_enc_hi);  cudaGetSymbolAddress((void**)&el,   g_enc_lo);
    cudaGetSymbolAddress((void**)&wath, g_WalT_hi); cudaGetSymbolAddress((void**)&watl, g_WalT_lo);
    cudaGetSymbolAddress((void**)&wqh,  g_Wq_hi);   cudaGetSymbolAddress((void**)&wql,  g_Wq_lo);
    cudaGetSymbolAddress((void**)&wkh,  g_Wk_hi);   cudaGetSymbolAddress((void**)&wkl,  g_Wk_lo);
    cudaGetSymbolAddress((void**)&wvh,  g_Wv_hi);   cudaGetSymbolAddress((void**)&wvl,  g_Wv_lo);
    cudaGetSymbolAddress((void**)&wfh,  g_WfcT_hi); cudaGetSymbolAddress((void**)&wfl,  g_WfcT_lo);
    cudaGetSymbolAddress((void**)&c1h,  g_C1_hi);   cudaGetSymbolAddress((void**)&c1l,  g_C1_lo);
    cudaGetSymbolAddress((void**)&bqh,  g_Bqk_hi);  cudaGetSymbolAddress((void**)&bql,  g_Bqk_lo);
    cudaGetSymbolAddress((void**)&wvfh, g_WvfT_hi); cudaGetSymbolAddress((void**)&wvfl, g_WvfT_lo);
    cudaGetSymbolAddress((void**)&cth,  g_cat_hi);  cudaGetSymbolAddress((void**)&ctl,  g_cat_lo);
    cudaGetSymbolAddress((void**)&wa1h, g_Wa1T_hi); cudaGetSymbolAddress((void**)&wa1l, g_Wa1T_lo);
    cudaGetSymbolAddress((void**)&f1h,  g_f1_hi);   cudaGetSymbolAddress((void**)&f1l,  g_f1_lo);
    cudaGetSymbolAddress((void**)&wa2h, g_Wa2T_hi); cudaGetSymbolAddress((void**)&wa2l, g_Wa2T_lo);
    cudaGetSymbolAddress((void**)&pKC, g_KC);       cudaGetSymbolAddress((void**)&pVC, g_VC);
    cudaGetSymbolAddress((void**)&pFused, g_fused);
    cudaGetSymbolAddress((void**)&pPool, g_pool);   cudaGetSymbolAddress((void**)&pHid, g_hid);

    // opt-in to 120KB dynamic smem per instantiation
    cudaFuncSetAttribute(mmgemm<true,  true,  false>, cudaFuncAttributeMaxDynamicSharedMemorySize, MM_SMEM);
    cudaFuncSetAttribute(mmgemm<true,  false, false>, cudaFuncAttributeMaxDynamicSharedMemorySize, MM_SMEM);
    cudaFuncSetAttribute(mmgemm<false, false, false>, cudaFuncAttributeMaxDynamicSharedMemorySize, MM_SMEM);
    cudaFuncSetAttribute(mmgemm<true,  true,  true >, cudaFuncAttributeMaxDynamicSharedMemorySize, MM_SMEM);
    cudaFuncSetAttribute(mmgemm<false, true,  false>, cudaFuncAttributeMaxDynamicSharedMemorySize, MM_SMEM);

    const dim3 blk(256);
    const long HD2 = (long)DH * DH;      // 589824
    const long NRD = (long)NR * DH;      // 602112

    // ---- operand conversions ----
    split_kernel<<<1024, 256>>>(enc_img, eh, el, (long)NR * IMGD);
    splitT_kernel<<<dim3(DH / 32, IMGD / 32), dim3(32, 8)>>>(W_align, wath, watl, IMGD, DH);
    split_kernel<<<1024, 256>>>(Wq, wqh, wql, (long)DH * HH * DH);
    split_kernel<<<1024, 256>>>(Wk, wkh, wkl, (long)DH * HH * DH);
    split_kernel<<<1024, 256>>>(Wv, wvh, wvl, (long)DH * HH * DH);
    splitT_kernel<<<dim3(DH / 32, (HH * DH) / 32), dim3(32, 8)>>>(Wfc, wfh, wfl, HH * DH, DH);
    splitT_kernel<<<dim3((2*DH) / 32, (2*DH) / 32), dim3(32, 8)>>>(W_a1, wa1h, wa1l, 2*DH, 2*DH);
    splitT_kernel<<<dim3(DH / 32, (2*DH) / 32), dim3(32, 8)>>>(W_a2, wa2h, wa2l, 2*DH, DH);

    // ---- G1: C1 = enc_img @ W_align + b_align -> bf16 hi/lo [784,768] ----
    mmgemm<true, true, false><<<dim3(6, 4, 1), blk, MM_SMEM>>>(
        eh, el, IMGD, 0, wath, watl, IMGD, 0,
        nullptr, c1h, c1l, DH, 0, b_align, NR, DH, IMGD);

    // ---- G2: Bqk_h = Wq_h @ Wk_h^T -> bf16 hi/lo [8][768,768] ----
    mmgemm<true, false, false><<<dim3(6, 3, HH), blk, MM_SMEM>>>(
        wqh, wql, HH * DH, DH, wkh, wkl, HH * DH, DH,
        nullptr, bqh, bql, DH, HD2, nullptr, DH, DH, DH);

    // ---- G3: WvfT_h = (Wv_h @ Wfc_h)^T -> bf16 hi/lo ----
    mmgemm<true, false, false><<<dim3(6, 3, HH), blk, MM_SMEM>>>(
        wfh, wfl, HH * DH, DH, wvh, wvl, HH * DH, DH,
        nullptr, wvfh, wvfl, DH, HD2, nullptr, DH, DH, DH);

    // ---- G4: KC_h = C1 @ Bqk_h^T -> fp32 [8][784,768] ----
    mmgemm<false, false, false><<<dim3(6, 4, HH), blk, MM_SMEM>>>(
        c1h, c1l, DH, 0, bqh, bql, DH, HD2,
        pKC, nullptr, nullptr, DH, NRD, nullptr, NR, DH, DH);

    // ---- G5: VC_h = C1 @ WvfT_h^T -> fp32 [8][784,768] ----
    mmgemm<false, false, false><<<dim3(6, 4, HH), blk, MM_SMEM>>>(
        c1h, c1l, DH, 0, wvfh, wvfl, DH, HD2,
        pVC, nullptr, nullptr, DH, NRD, nullptr, NR, DH, DH);

    // ---- span gather + attention + LN ----
    gather_kernel<<<ROWS, 192>>>(seq, starts);
    att_scores_kernel<<<dim3(HH, NM), 256>>>();
    att_out_kernel<<<NM, 256>>>();
    ln_kernel<<<ROWS, 256>>>(ln_g, ln_b);

    // ---- fusion MLP ----
    concat_split_kernel<<<ROWS, 256>>>();
    mmgemm<true, true, true><<<dim3(12, 15, 1), blk, MM_SMEM>>>(
        cth, ctl, 2 * DH, 0, wa1h, wa1l, 2 * DH, 0,
        nullptr, f1h, f1l, 2 * DH, 0, b_a1, ROWS, 2 * DH, 2 * DH);
    mmgemm<false, true, false><<<dim3(6, 15, 1), blk, MM_SMEM>>>(
        f1h, f1l, 2 * DH, 0, wa2h, wa2l, 2 * DH, 0,
        pFused, nullptr, nullptr, DH, 0, b_a2, ROWS, DH, 2 * DH);

    // ---- pooling + head ----
    pool_kernel<<<NM, 256>>>(W_un, b_un, starts, ends);
    sgemm<false, true, true><<<dim3(6, 1, 1), blk>>>(
        pPool, DH, 0, W_dense, DH, 0, pHid, DH, 0, b_dense, NM, DH, DH);
    cls_kernel<<<NM, 128>>>(W_cls, b_cls, (float*)d_out);
}

// round 5
// speedup vs baseline: 1.1326x; 1.1326x over previous
#include <cuda_runtime.h>
#include <cuda_bf16.h>
#include <math.h>
#include <stdint.h>

// ---------------- problem constants ----------------
#define NB    16
#define LSEQ  128
#define DH    768
#define MSP   8
#define HH    8
#define JR    30
#define RR    49
#define IMGD  2048
#define NM    128            // NB*MSP
#define ROWS  3840           // NM*JR
#define NR    784            // NB*RR

typedef __nv_bfloat16 bf16;

// ---------------- scratch (device globals; no cudaMalloc allowed) ----------------
__device__ bf16 g_enc_hi[NR * IMGD],        g_enc_lo[NR * IMGD];
__device__ bf16 g_WalT_hi[DH * IMGD],       g_WalT_lo[DH * IMGD];
__device__ bf16 g_Wq_hi[DH * HH * DH],      g_Wq_lo[DH * HH * DH];
__device__ bf16 g_Wk_hi[DH * HH * DH],      g_Wk_lo[DH * HH * DH];
__device__ bf16 g_Wv_hi[DH * HH * DH],      g_Wv_lo[DH * HH * DH];
__device__ bf16 g_WfcT_hi[DH * HH * DH],    g_WfcT_lo[DH * HH * DH];
__device__ bf16 g_C1_hi[NR * DH],           g_C1_lo[NR * DH];
__device__ bf16 g_Bqk_hi[HH * DH * DH],     g_Bqk_lo[HH * DH * DH];
__device__ bf16 g_WvfT_hi[HH * DH * DH],    g_WvfT_lo[HH * DH * DH];
__device__ float g_KC[HH * NR * DH];
__device__ float g_VC[HH * NR * DH];
__device__ float g_span[ROWS * DH];
__device__ float g_att[ROWS * DH];
__device__ float g_P[NM * HH * JR * RR];
__device__ bf16 g_cat_hi[ROWS * 2 * DH],    g_cat_lo[ROWS * 2 * DH];
__device__ bf16 g_Wa1T_hi[2*DH * 2*DH],     g_Wa1T_lo[2*DH * 2*DH];
__device__ bf16 g_f1_hi[ROWS * 2 * DH],     g_f1_lo[ROWS * 2 * DH];
__device__ bf16 g_Wa2T_hi[DH * 2*DH],       g_Wa2T_lo[DH * 2*DH];
__device__ float g_fused[ROWS * DH];
__device__ float g_pool[NM * DH];
__device__ float g_hid[NM * DH];

// ---------------- warp-mma helpers ----------------
__device__ __forceinline__ uint32_t smem_u32(const void* p) {
    uint32_t a;
    asm("{ .reg .u64 t; cvta.to.shared.u64 t, %1; cvt.u32.u64 %0, t; }" : "=r"(a) : "l"(p));
    return a;
}

__device__ __forceinline__ void ldm_x4(uint32_t* r, uint32_t addr) {
    asm volatile("ldmatrix.sync.aligned.m8n8.x4.shared.b16 {%0,%1,%2,%3}, [%4];"
                 : "=r"(r[0]), "=r"(r[1]), "=r"(r[2]), "=r"(r[3]) : "r"(addr));
}

__device__ __forceinline__ void mma16816(float* c, const uint32_t* a, uint32_t b0, uint32_t b1) {
    asm volatile(
        "mma.sync.aligned.m16n8k16.row.col.f32.bf16.bf16.f32 "
        "{%0,%1,%2,%3}, {%4,%5,%6,%7}, {%8,%9}, {%0,%1,%2,%3};"
        : "+f"(c[0]), "+f"(c[1]), "+f"(c[2]), "+f"(c[3])
        : "r"(a[0]), "r"(a[1]), "r"(a[2]), "r"(a[3]), "r"(b0), "r"(b1));
}

__device__ __forceinline__ void cpa16(uint32_t dst, const void* src) {
    asm volatile("cp.async.ca.shared.global [%0], [%1], 16;" :: "r"(dst), "l"(src));
}
__device__ __forceinline__ void cpa_commit() {
    asm volatile("cp.async.commit_group;" ::: "memory");
}
template<int N_>
__device__ __forceinline__ void cpa_wait() {
    asm volatile("cp.async.wait_group %0;" :: "n"(N_) : "memory");
}

// ---------------- split-bf16 tensor-core GEMM (double-buffered, 2 CTA/SM) ----------------
// C[M,N] = act( sum_k A[m,k]*B[n,k] + bias[n] ),  A,B as hi/lo bf16.
// Ahi*Bhi + Ahi*Blo + Alo*Bhi. Block 128x128, BK=32, 8 warps (2x4), warp 64x32.
#define BM 128
#define BN 128
#define BK 32
#define SPAD 40                                  // padded row (bf16): 80B rows
#define OFF_AL (BM * SPAD)
#define OFF_BH (2 * BM * SPAD)
#define OFF_BL (3 * BM * SPAD)
#define STAGE_ELEMS (4 * BM * SPAD)              // 20480
#define STAGE_BYTES (STAGE_ELEMS * 2)            // 40960
#define MM_SMEM (2 * STAGE_BYTES)                // 81920

template<bool OUT_BF16, bool BIAS, bool TANH_ACT>
__global__ __launch_bounds__(256, 2)
void mmgemm(const bf16* __restrict__ Ahi, const bf16* __restrict__ Alo, int lda, long sA,
            const bf16* __restrict__ Bhi, const bf16* __restrict__ Blo, int ldb, long sB,
            float* __restrict__ Cf, bf16* __restrict__ Chi, bf16* __restrict__ Clo,
            int ldc, long sC, const float* __restrict__ bias,
            int M, int N, int K)
{
    extern __shared__ char dsm[];
    const uint32_t u_sm = smem_u32(dsm);

    Ahi += (long)blockIdx.z * sA;  Alo += (long)blockIdx.z * sA;
    Bhi += (long)blockIdx.z * sB;  Blo += (long)blockIdx.z * sB;
    const long coff = (long)blockIdx.z * sC;

    const int tid = threadIdx.x, lane = tid & 31, wid = tid >> 5;
    const int wr = wid >> 2, wc = wid & 3;              // 2x4 warps, 64x32 each
    const int m0 = blockIdx.y * BM, n0 = blockIdx.x * BN;

    float acc[4][4][4];
#pragma unroll
    for (int i = 0; i < 4; i++)
#pragma unroll
        for (int j = 0; j < 4; j++)
#pragma unroll
            for (int e = 0; e < 4; e++) acc[i][j][e] = 0.f;

    // ldmatrix per-thread base addresses (relative to stage base)
    const int lrow = lane & 15;
    const uint32_t lkb = (uint32_t)((lane >> 4) * 16);
    const uint32_t aA = (uint32_t)((wr * 64 + lrow) * SPAD * 2) + lkb;
    const uint32_t aB = (uint32_t)(OFF_BH * 2) + (uint32_t)((wc * 32 + lrow) * SPAD * 2) + lkb;

    // async stage loader: 8 x 16B per thread (2048 ops total)
    auto load_stage = [&](int st, int k0) {
        const uint32_t sbase = u_sm + (uint32_t)(st * STAGE_BYTES);
#pragma unroll
        for (int i = 0; i < 8; i++) {
            int u = tid + i * 256;             // 0..2047
            int r  = (u & 511) >> 2;
            int sg = (u & 3) << 3;
            const bf16* src;
            uint32_t doff;
            if (u < 512) {
                int ga = m0 + r; if (ga > M - 1) ga = M - 1;
                src = Ahi + (long)ga * lda + k0 + sg;
                doff = (uint32_t)((r * SPAD + sg) * 2);
            } else if (u < 1024) {
                int ga = m0 + r; if (ga > M - 1) ga = M - 1;
                src = Alo + (long)ga * lda + k0 + sg;
                doff = (uint32_t)((OFF_AL + r * SPAD + sg) * 2);
            } else if (u < 1536) {
                int gb = n0 + r; if (gb > N - 1) gb = N - 1;
                src = Bhi + (long)gb * ldb + k0 + sg;
                doff = (uint32_t)((OFF_BH + r * SPAD + sg) * 2);
            } else {
                int gb = n0 + r; if (gb > N - 1) gb = N - 1;
                src = Blo + (long)gb * ldb + k0 + sg;
                doff = (uint32_t)((OFF_BL + r * SPAD + sg) * 2);
            }
            cpa16(sbase + doff, src);
        }
    };

    const int nch = K / BK;
    load_stage(0, 0);
    cpa_commit();

    for (int ch = 0; ch < nch; ch++) {
        if (ch + 1 < nch) {
            load_stage((ch + 1) & 1, (ch + 1) * BK);
            cpa_commit();
            cpa_wait<1>();
        } else {
            cpa_wait<0>();
        }
        __syncthreads();

        const uint32_t so = u_sm + (uint32_t)((ch & 1) * STAGE_BYTES);
#pragma unroll
        for (int ks = 0; ks < 2; ks++) {
            const uint32_t ko = so + (uint32_t)(ks * 16 * 2);
            uint32_t bh[2][4], bl[2][4];
#pragma unroll
            for (int nt = 0; nt < 2; nt++) {
                ldm_x4(bh[nt], aB + (uint32_t)(nt * 16 * SPAD * 2) + ko);
                ldm_x4(bl[nt], aB + (uint32_t)((BM * SPAD + nt * 16 * SPAD) * 2) + ko);
            }
#pragma unroll
            for (int mi = 0; mi < 4; mi++) {
                uint32_t ah[4], al[4];
                ldm_x4(ah, aA + (uint32_t)(mi * 16 * SPAD * 2) + ko);
                ldm_x4(al, aA + (uint32_t)((OFF_AL + mi * 16 * SPAD) * 2) + ko);
#pragma unroll
                for (int nt = 0; nt < 2; nt++) {
#pragma unroll
                    for (int j = 0; j < 2; j++) {
                        const int nj = nt * 2 + j;
                        mma16816(acc[mi][nj], ah, bh[nt][j], bh[nt][j + 2]);
                        mma16816(acc[mi][nj], ah, bl[nt][j], bl[nt][j + 2]);
                        mma16816(acc[mi][nj], al, bh[nt][j], bh[nt][j + 2]);
                    }
                }
            }
        }
        __syncthreads();
    }

    // epilogue
    const int er = m0 + wr * 64 + (lane >> 2);
    const int ec = n0 + wc * 32 + (lane & 3) * 2;
#pragma unroll
    for (int mi = 0; mi < 4; mi++) {
#pragma unroll
        for (int nj = 0; nj < 4; nj++) {
            const int col = ec + nj * 8;
            float bv0 = 0.f, bv1 = 0.f;
            if (BIAS) { bv0 = bias[col]; bv1 = bias[col + 1]; }
#pragma unroll
            for (int half = 0; half < 2; half++) {
                const int row = er + mi * 16 + half * 8;
                if (row >= M) continue;
                float v0 = acc[mi][nj][half * 2 + 0] + bv0;
                float v1 = acc[mi][nj][half * 2 + 1] + bv1;
                if (TANH_ACT) { v0 = tanhf(v0); v1 = tanhf(v1); }
                const long base = (long)row * ldc + coff + col;
                if (OUT_BF16) {
                    bf16 h0 = __float2bfloat16(v0);
                    bf16 h1 = __float2bfloat16(v1);
                    Chi[base] = h0;     Chi[base + 1] = h1;
                    Clo[base]     = __float2bfloat16(v0 - __bfloat162float(h0));
                    Clo[base + 1] = __float2bfloat16(v1 - __bfloat162float(h1));
                } else {
                    Cf[base] = v0;  Cf[base + 1] = v1;
                }
            }
        }
    }
}

// ---------------- fp32 -> bf16 hi/lo split (elementwise) ----------------
__global__ void split_kernel(const float* __restrict__ in, bf16* __restrict__ hi,
                             bf16* __restrict__ lo, long n)
{
    long i0 = ((long)blockIdx.x * blockDim.x + threadIdx.x) * 4;
    long stride = (long)gridDim.x * blockDim.x * 4;
    for (long i = i0; i < n; i += stride) {
        float4 v = *reinterpret_cast<const float4*>(in + i);
        float vv[4] = {v.x, v.y, v.z, v.w};
#pragma unroll
        for (int j = 0; j < 4; j++) {
            bf16 h = __float2bfloat16(vv[j]);
            hi[i + j] = h;
            lo[i + j] = __float2bfloat16(vv[j] - __bfloat162float(h));
        }
    }
}

// ---------------- fp32 [R,C] -> transposed bf16 hi/lo [C,R] ----------------
__global__ void splitT_kernel(const float* __restrict__ in, bf16* __restrict__ hi,
                              bf16* __restrict__ lo, int R, int C)
{
    __shared__ float t[32][33];
    int c0 = blockIdx.x * 32, r0 = blockIdx.y * 32;
    for (int i = threadIdx.y; i < 32; i += 8)
        t[i][threadIdx.x] = in[(long)(r0 + i) * C + c0 + threadIdx.x];
    __syncthreads();
    for (int i = threadIdx.y; i < 32; i += 8) {
        float v = t[threadIdx.x][i];
        long o = (long)(c0 + i) * R + r0 + threadIdx.x;
        bf16 h = __float2bfloat16(v);
        hi[o] = h;
        lo[o] = __float2bfloat16(v - __bfloat162float(h));
    }
}

// ---------------- concat(span, att) -> bf16 hi/lo ----------------
__global__ void concat_split_kernel()
{
    int row = blockIdx.x, t = threadIdx.x;
    for (int idx = t; idx < 2 * DH; idx += 256) {
        float v = (idx < DH) ? g_span[(long)row * DH + idx]
                             : g_att[(long)row * DH + idx - DH];
        long o = (long)row * 2 * DH + idx;
        bf16 h = __float2bfloat16(v);
        g_cat_hi[o] = h;
        g_cat_lo[o] = __float2bfloat16(v - __bfloat162float(h));
    }
}

// ---------------- span gather ----------------
__global__ void gather_kernel(const float* __restrict__ seq, const int* __restrict__ starts)
{
    int row = blockIdx.x;
    int sp = row / JR, j = row - sp * JR;
    int n = sp >> 3;
    int tok = starts[sp] + n * LSEQ + j;
    if (tok > NB * LSEQ - 1) tok = NB * LSEQ - 1;
    const float4* src = reinterpret_cast<const float4*>(seq + (long)tok * DH);
    float4* dst = reinterpret_cast<float4*>(g_span + (long)row * DH);
    int t = threadIdx.x;
    if (t < DH / 4) dst[t] = src[t];
}

// ---------------- attention scores + softmax (per span, head) ----------------
__global__ void att_scores_kernel()
{
    const int h = blockIdx.x, s = blockIdx.y;
    const int b = s >> 3;
    __shared__ float sQ[JR][129];
    __shared__ float sK[RR][129];
    __shared__ float sS[JR * RR];
    const int t = threadIdx.x;
    const int q = t % JR, rg = t / JR;

    int rr[7];
#pragma unroll
    for (int i = 0; i < 7; i++) { int r = rg + i * 8; rr[i] = (r < RR) ? r : 0; }
    float acc[7];
#pragma unroll
    for (int i = 0; i < 7; i++) acc[i] = 0.f;

    const float* Qp = g_span + (long)s * JR * DH;
    const float* Kp = g_KC + ((long)h * NR + (long)b * RR) * DH;

    for (int k0 = 0; k0 < DH; k0 += 128) {
        for (int e = t; e < JR * 128; e += 256)
            sQ[e >> 7][e & 127] = Qp[(long)(e >> 7) * DH + k0 + (e & 127)];
        for (int e = t; e < RR * 128; e += 256)
            sK[e >> 7][e & 127] = Kp[(long)(e >> 7) * DH + k0 + (e & 127)];
        __syncthreads();
        if (t < 240) {
            for (int kk = 0; kk < 128; kk++) {
                float a = sQ[q][kk];
#pragma unroll
                for (int i = 0; i < 7; i++) acc[i] += a * sK[rr[i]][kk];
            }
        }
        __syncthreads();
    }

    const float scale = 1.0f / sqrtf((float)DH);
    if (t < 240) {
#pragma unroll
        for (int i = 0; i < 7; i++) {
            int r = rg + i * 8;
            if (r < RR) sS[q * RR + r] = acc[i] * scale;
        }
    }
    __syncthreads();

    if (t < JR) {
        float* row = sS + t * RR;
        float mx = row[0];
        for (int r = 1; r < RR; r++) mx = fmaxf(mx, row[r]);
        float sum = 0.f;
        for (int r = 0; r < RR; r++) { float e = expf(row[r] - mx); row[r] = e; sum += e; }
        float inv = 1.f / sum;
        float* out = g_P + (((long)s * HH + h) * JR + t) * RR;
        for (int r = 0; r < RR; r++) out[r] = row[r] * inv;
    }
}

// ---------------- out = sum_h P_h @ VC_h + residual (per span) ----------------
__global__ void att_out_kernel()
{
    const int s = blockIdx.x, b = s >> 3, t = threadIdx.x;
    __shared__ float sP[HH * JR * RR];
    for (int e = t; e < HH * JR * RR; e += 256)
        sP[e] = g_P[(long)s * HH * JR * RR + e];
    __syncthreads();

    for (int dc = 0; dc < 3; dc++) {
        int d = dc * 256 + t;
        float acc[JR];
#pragma unroll
        for (int q = 0; q < JR; q++) acc[q] = 0.f;
        for (int h = 0; h < HH; h++) {
            const float* V = g_VC + ((long)h * NR + (long)b * RR) * DH + d;
            const float* P = sP + h * JR * RR;
            for (int r = 0; r < RR; r++) {
                float v = V[(long)r * DH];
#pragma unroll
                for (int q = 0; q < JR; q++) acc[q] += P[q * RR + r] * v;
            }
        }
        for (int q = 0; q < JR; q++) {
            long idx = ((long)s * JR + q) * DH + d;
            g_att[idx] = acc[q] + g_span[idx];
        }
    }
}

// ---------------- layernorm (in place on g_att) ----------------
__global__ void ln_kernel(const float* __restrict__ gam, const float* __restrict__ bet)
{
    int row = blockIdx.x, t = threadIdx.x;
    float* x = g_att + (long)row * DH;
    float v0 = x[t], v1 = x[t + 256], v2 = x[t + 512];
    __shared__ float red[256];
    red[t] = v0 + v1 + v2;
    __syncthreads();
    for (int o = 128; o > 0; o >>= 1) { if (t < o) red[t] += red[t + o]; __syncthreads(); }
    float mu = red[0] * (1.f / DH);
    __syncthreads();
    float d0 = v0 - mu, d1 = v1 - mu, d2 = v2 - mu;
    red[t] = d0 * d0 + d1 * d1 + d2 * d2;
    __syncthreads();
    for (int o = 128; o > 0; o >>= 1) { if (t < o) red[t] += red[t + o]; __syncthreads(); }
    float rstd = rsqrtf(red[0] * (1.f / DH) + 1e-5f);
    x[t]       = d0 * rstd * gam[t]       + bet[t];
    x[t + 256] = d1 * rstd * gam[t + 256] + bet[t + 256];
    x[t + 512] = d2 * rstd * gam[t + 512] + bet[t + 512];
}

// ---------------- unary score + masked softmax pooling ----------------
__global__ void pool_kernel(const float* __restrict__ W_un, const float* __restrict__ b_un,
                            const int* __restrict__ starts, const int* __restrict__ ends)
{
    int sp = blockIdx.x, t = threadIdx.x;
    int lane = t & 31, w = t >> 5;
    __shared__ float sS[JR];
    __shared__ float sProb[JR];

    for (int j = w; j < JR; j += 8) {
        const float* fr = g_fused + ((long)sp * JR + j) * DH;
        float acc = 0.f;
        for (int k = lane; k < DH; k += 32) acc += fr[k] * W_un[k];
        for (int o = 16; o; o >>= 1) acc += __shfl_xor_sync(0xffffffffu, acc, o);
        if (lane == 0) sS[j] = acc + b_un[0];
    }
    __syncthreads();
    if (t == 0) {
        int width = ends[sp] - starts[sp] + 1;
        float mx = -1e30f;
        for (int j = 0; j < JR; j++) {
            float v = sS[j] + ((j < width) ? 0.f : -10000.f);
            sS[j] = v; mx = fmaxf(mx, v);
        }
        float sum = 0.f;
        for (int j = 0; j < JR; j++) { float e = expf(sS[j] - mx); sProb[j] = e; sum += e; }
        float inv = 1.f / sum;
        for (int j = 0; j < JR; j++) sProb[j] *= inv;
    }
    __syncthreads();
    for (int d = t; d < DH; d += 256) {
        float acc = 0.f;
        for (int j = 0; j < JR; j++) acc += sProb[j] * g_fused[((long)sp * JR + j) * DH + d];
        g_pool[(long)sp * DH + d] = acc;
    }
}

// ---------------- small fp32 sgemm (tiny dense layer only) ----------------
template<bool TRANSB, bool BIAS, bool TANH_ACT>
__global__ void sgemm(const float* __restrict__ A, int lda, long sA,
                      const float* __restrict__ B, int ldb, long sB,
                      float* __restrict__ C, int ldc, long sC,
                      const float* __restrict__ bias,
                      int M, int N, int K)
{
    A += (long)blockIdx.z * sA;
    B += (long)blockIdx.z * sB;
    C += (long)blockIdx.z * sC;
    __shared__ float As[16][128];
    __shared__ float Bs[16][128];
    const int tid = threadIdx.x;
    const int m0 = blockIdx.y * 128;
    const int n0 = blockIdx.x * 128;
    const int tx = tid & 15;
    const int ty = tid >> 4;
    float acc[8][8];
#pragma unroll
    for (int i = 0; i < 8; i++)
#pragma unroll
        for (int j = 0; j < 8; j++) acc[i][j] = 0.f;

    for (int k0 = 0; k0 < K; k0 += 16) {
#pragma unroll
        for (int i = 0; i < 2; i++) {
            int li = tid + i * 256;
            int row = li >> 2;
            int kk  = (li & 3) << 2;
            float4 v = make_float4(0.f, 0.f, 0.f, 0.f);
            if (m0 + row < M)
                v = *reinterpret_cast<const float4*>(&A[(long)(m0 + row) * lda + k0 + kk]);
            As[kk + 0][row] = v.x; As[kk + 1][row] = v.y;
            As[kk + 2][row] = v.z; As[kk + 3][row] = v.w;
        }
        if (!TRANSB) {
#pragma unroll
            for (int i = 0; i < 2; i++) {
                int li = tid + i * 256;
                int kr = li >> 5;
                int nn = (li & 31) << 2;
                float4 v = *reinterpret_cast<const float4*>(&B[(long)(k0 + kr) * ldb + n0 + nn]);
                *reinterpret_cast<float4*>(&Bs[kr][nn]) = v;
            }
        } else {
#pragma unroll
            for (int i = 0; i < 2; i++) {
                int li = tid + i * 256;
                int nr = li >> 2;
                int kk = (li & 3) << 2;
                float4 v = make_float4(0.f, 0.f, 0.f, 0.f);
                if (n0 + nr < N)
                    v = *reinterpret_cast<const float4*>(&B[(long)(n0 + nr) * ldb + k0 + kk]);
                Bs[kk + 0][nr] = v.x; Bs[kk + 1][nr] = v.y;
                Bs[kk + 2][nr] = v.z; Bs[kk + 3][nr] = v.w;
            }
        }
        __syncthreads();
#pragma unroll
        for (int k = 0; k < 16; k++) {
            float a[8], b[8];
#pragma unroll
            for (int i = 0; i < 8; i++) a[i] = As[k][ty * 8 + i];
#pragma unroll
            for (int j = 0; j < 8; j++) b[j] = Bs[k][tx * 8 + j];
#pragma unroll
            for (int i = 0; i < 8; i++)
#pragma unroll
                for (int j = 0; j < 8; j++) acc[i][j] += a[i] * b[j];
        }
        __syncthreads();
    }
#pragma unroll
    for (int i = 0; i < 8; i++) {
        int m = m0 + ty * 8 + i;
        if (m >= M) continue;
#pragma unroll
        for (int j = 0; j < 8; j++) {
            int n = n0 + tx * 8 + j;
            float v = acc[i][j];
            if (BIAS) v += bias[n];
            if (TANH_ACT) v = tanhf(v);
            C[(long)m * ldc + n] = v;
        }
    }
}

// ---------------- classifier ----------------
__global__ void cls_kernel(const float* __restrict__ W_cls, const float* __restrict__ b_cls,
                           float* __restrict__ out)
{
    int row = blockIdx.x, t = threadIdx.x;
    int lane = t & 31, c = t >> 5;
    const float* hr = g_hid + (long)row * DH;
    float acc = 0.f;
    for (int k = lane; k < DH; k += 32) acc += hr[k] * W_cls[k * 4 + c];
    for (int o = 16; o; o >>= 1) acc += __shfl_xor_sync(0xffffffffu, acc, o);
    if (lane == 0) out[row * 4 + c] = acc + b_cls[c];
}

// ---------------- launcher ----------------
extern "C" void kernel_launch(void* const* d_in, const int* in_sizes, int n_in,
                              void* d_out, int out_size)
{
    const float* enc_img  = (const float*)d_in[0];
    const float* seq      = (const float*)d_in[1];
    const int*   starts   = (const int*)d_in[3];
    const int*   ends     = (const int*)d_in[4];
    const float* W_align  = (const float*)d_in[5];
    const float* b_align  = (const float*)d_in[6];
    const float* Wq       = (const float*)d_in[7];
    const float* Wk       = (const float*)d_in[8];
    const float* Wv       = (const float*)d_in[9];
    const float* Wfc      = (const float*)d_in[10];
    const float* ln_g     = (const float*)d_in[11];
    const float* ln_b     = (const float*)d_in[12];
    const float* W_a1     = (const float*)d_in[13];
    const float* b_a1     = (const float*)d_in[14];
    const float* W_a2     = (const float*)d_in[15];
    const float* b_a2     = (const float*)d_in[16];
    const float* W_un     = (const float*)d_in[17];
    const float* b_un     = (const float*)d_in[18];
    const float* W_dense  = (const float*)d_in[19];
    const float* b_dense  = (const float*)d_in[20];
    const float* W_cls    = (const float*)d_in[21];
    const float* b_cls    = (const float*)d_in[22];

    bf16 *eh, *el, *wath, *watl, *wqh, *wql, *wkh, *wkl, *wvh, *wvl, *wfh, *wfl;
    bf16 *c1h, *c1l, *bqh, *bql, *wvfh, *wvfl;
    bf16 *cth, *ctl, *wa1h, *wa1l, *f1h, *f1l, *wa2h, *wa2l;
    float *pKC, *pVC, *pFused, *pPool, *pHid;
    cudaGetSymbolAddress((void**)&eh,   g_enc_hi);  cudaGetSymbolAddress((void**)&el,   g_enc_lo);
    cudaGetSymbolAddress((void**)&wath, g_WalT_hi); cudaGetSymbolAddress((void**)&watl, g_WalT_lo);
    cudaGetSymbolAddress((void**)&wqh,  g_Wq_hi);   cudaGetSymbolAddress((void**)&wql,  g_Wq_lo);
    cudaGetSymbolAddress((void**)&wkh,  g_Wk_hi);   cudaGetSymbolAddress((void**)&wkl,  g_Wk_lo);
    cudaGetSymbolAddress((void**)&wvh,  g_Wv_hi);   cudaGetSymbolAddress((void**)&wvl,  g_Wv_lo);
    cudaGetSymbolAddress((void**)&wfh,  g_WfcT_hi); cudaGetSymbolAddress((void**)&wfl,  g_WfcT_lo);
    cudaGetSymbolAddress((void**)&c1h,  g_C1_hi);   cudaGetSymbolAddress((void**)&c1l,  g_C1_lo);
    cudaGetSymbolAddress((void**)&bqh,  g_Bqk_hi);  cudaGetSymbolAddress((void**)&bql,  g_Bqk_lo);
    cudaGetSymbolAddress((void**)&wvfh, g_WvfT_hi); cudaGetSymbolAddress((void**)&wvfl, g_WvfT_lo);
    cudaGetSymbolAddress((void**)&cth,  g_cat_hi);  cudaGetSymbolAddress((void**)&ctl,  g_cat_lo);
    cudaGetSymbolAddress((void**)&wa1h, g_Wa1T_hi); cudaGetSymbolAddress((void**)&wa1l, g_Wa1T_lo);
    cudaGetSymbolAddress((void**)&f1h,  g_f1_hi);   cudaGetSymbolAddress((void**)&f1l,  g_f1_lo);
    cudaGetSymbolAddress((void**)&wa2h, g_Wa2T_hi); cudaGetSymbolAddress((void**)&wa2l, g_Wa2T_lo);
    cudaGetSymbolAddress((void**)&pKC, g_KC);       cudaGetSymbolAddress((void**)&pVC, g_VC);
    cudaGetSymbolAddress((void**)&pFused, g_fused);
    cudaGetSymbolAddress((void**)&pPool, g_pool);   cudaGetSymbolAddress((void**)&pHid, g_hid);

    // opt-in to 80KB dynamic smem per instantiation
    cudaFuncSetAttribute(mmgemm<true,  true,  false>, cudaFuncAttributeMaxDynamicSharedMemorySize, MM_SMEM);
    cudaFuncSetAttribute(mmgemm<true,  false, false>, cudaFuncAttributeMaxDynamicSharedMemorySize, MM_SMEM);
    cudaFuncSetAttribute(mmgemm<false, false, false>, cudaFuncAttributeMaxDynamicSharedMemorySize, MM_SMEM);
    cudaFuncSetAttribute(mmgemm<true,  true,  true >, cudaFuncAttributeMaxDynamicSharedMemorySize, MM_SMEM);
    cudaFuncSetAttribute(mmgemm<false, true,  false>, cudaFuncAttributeMaxDynamicSharedMemorySize, MM_SMEM);

    const dim3 blk(256);
    const long HD2 = (long)DH * DH;      // 589824
    const long NRD = (long)NR * DH;      // 602112

    // ---- operand conversions ----
    split_kernel<<<1024, 256>>>(enc_img, eh, el, (long)NR * IMGD);
    splitT_kernel<<<dim3(DH / 32, IMGD / 32), dim3(32, 8)>>>(W_align, wath, watl, IMGD, DH);
    split_kernel<<<1024, 256>>>(Wq, wqh, wql, (long)DH * HH * DH);
    split_kernel<<<1024, 256>>>(Wk, wkh, wkl, (long)DH * HH * DH);
    split_kernel<<<1024, 256>>>(Wv, wvh, wvl, (long)DH * HH * DH);
    splitT_kernel<<<dim3(DH / 32, (HH * DH) / 32), dim3(32, 8)>>>(Wfc, wfh, wfl, HH * DH, DH);
    splitT_kernel<<<dim3((2*DH) / 32, (2*DH) / 32), dim3(32, 8)>>>(W_a1, wa1h, wa1l, 2*DH, 2*DH);
    splitT_kernel<<<dim3(DH / 32, (2*DH) / 32), dim3(32, 8)>>>(W_a2, wa2h, wa2l, 2*DH, DH);

    // ---- G1: C1 = enc_img @ W_align + b_align -> bf16 hi/lo [784,768] ----
    mmgemm<true, true, false><<<dim3(6, 7, 1), blk, MM_SMEM>>>(
        eh, el, IMGD, 0, wath, watl, IMGD, 0,
        nullptr, c1h, c1l, DH, 0, b_align, NR, DH, IMGD);

    // ---- G2: Bqk_h = Wq_h @ Wk_h^T -> bf16 hi/lo [8][768,768] ----
    mmgemm<true, false, false><<<dim3(6, 6, HH), blk, MM_SMEM>>>(
        wqh, wql, HH * DH, DH, wkh, wkl, HH * DH, DH,
        nullptr, bqh, bql, DH, HD2, nullptr, DH, DH, DH);

    // ---- G3: WvfT_h = (Wv_h @ Wfc_h)^T -> bf16 hi/lo ----
    mmgemm<true, false, false><<<dim3(6, 6, HH), blk, MM_SMEM>>>(
        wfh, wfl, HH * DH, DH, wvh, wvl, HH * DH, DH,
        nullptr, wvfh, wvfl, DH, HD2, nullptr, DH, DH, DH);

    // ---- G4: KC_h = C1 @ Bqk_h^T -> fp32 [8][784,768] ----
    mmgemm<false, false, false><<<dim3(6, 7, HH), blk, MM_SMEM>>>(
        c1h, c1l, DH, 0, bqh, bql, DH, HD2,
        pKC, nullptr, nullptr, DH, NRD, nullptr, NR, DH, DH);

    // ---- G5: VC_h = C1 @ WvfT_h^T -> fp32 [8][784,768] ----
    mmgemm<false, false, false><<<dim3(6, 7, HH), blk, MM_SMEM>>>(
        c1h, c1l, DH, 0, wvfh, wvfl, DH, HD2,
        pVC, nullptr, nullptr, DH, NRD, nullptr, NR, DH, DH);

    // ---- span gather + attention + LN ----
    gather_kernel<<<ROWS, 192>>>(seq, starts);
    att_scores_kernel<<<dim3(HH, NM), 256>>>();
    att_out_kernel<<<NM, 256>>>();
    ln_kernel<<<ROWS, 256>>>(ln_g, ln_b);

    // ---- fusion MLP ----
    concat_split_kernel<<<ROWS, 256>>>();
    mmgemm<true, true, true><<<dim3(12, 30, 1), blk, MM_SMEM>>>(
        cth, ctl, 2 * DH, 0, wa1h, wa1l, 2 * DH, 0,
        nullptr, f1h, f1l, 2 * DH, 0, b_a1, ROWS, 2 * DH, 2 * DH);
    mmgemm<false, true, false><<<dim3(6, 30, 1), blk, MM_SMEM>>>(
        f1h, f1l, 2 * DH, 0, wa2h, wa2l, 2 * DH, 0,
        pFused, nullptr, nullptr, DH, 0, b_a2, ROWS, DH, 2 * DH);

    // ---- pooling + head ----
    pool_kernel<<<NM, 256>>>(W_un, b_un, starts, ends);
    sgemm<false, true, true><<<dim3(6, 1, 1), blk>>>(
        pPool, DH, 0, W_dense, DH, 0, pHid, DH, 0, b_dense, NM, DH, DH);
    cls_kernel<<<NM, 128>>>(W_cls, b_cls, (float*)d_out);
}

// round 6
// speedup vs baseline: 1.6104x; 1.4219x over previous
#include <cuda_runtime.h>
#include <cuda_bf16.h>
#include <math.h>
#include <stdint.h>

// ---------------- problem constants ----------------
#define NB    16
#define LSEQ  128
#define DH    768
#define MSP   8
#define HH    8
#define JR    30
#define RR    49
#define IMGD  2048
#define NM    128            // NB*MSP
#define UU    2048           // NB*LSEQ distinct tokens
#define NR    784            // NB*RR

typedef __nv_bfloat16 bf16;

// ---------------- scratch (device globals; no cudaMalloc allowed) ----------------
__device__ bf16 g_enc_hi[NR * IMGD],        g_enc_lo[NR * IMGD];
__device__ bf16 g_WalT_hi[DH * IMGD],       g_WalT_lo[DH * IMGD];
__device__ bf16 g_Wq_hi[DH * HH * DH],      g_Wq_lo[DH * HH * DH];
__device__ bf16 g_Wk_hi[DH * HH * DH],      g_Wk_lo[DH * HH * DH];
__device__ bf16 g_Wv_hi[DH * HH * DH],      g_Wv_lo[DH * HH * DH];
__device__ bf16 g_WfcT_hi[DH * HH * DH],    g_WfcT_lo[DH * HH * DH];
__device__ bf16 g_C1_hi[NR * DH],           g_C1_lo[NR * DH];
__device__ bf16 g_Bqk_hi[HH * DH * DH],     g_Bqk_lo[HH * DH * DH];
__device__ bf16 g_WvfT_hi[HH * DH * DH],    g_WvfT_lo[HH * DH * DH];
__device__ float g_KC[HH * NR * DH];
__device__ float g_VC[HH * NR * DH];
__device__ float g_P[NB * HH * LSEQ * RR];            // per (n,h,token,region)
__device__ bf16 g_cat_hi[UU * 2 * DH],      g_cat_lo[UU * 2 * DH];
__device__ bf16 g_Wa1T_hi[2*DH * 2*DH],     g_Wa1T_lo[2*DH * 2*DH];
__device__ bf16 g_f1_hi[UU * 2 * DH],       g_f1_lo[UU * 2 * DH];
__device__ bf16 g_Wa2T_hi[DH * 2*DH],       g_Wa2T_lo[DH * 2*DH];
__device__ float g_fused[UU * DH];
__device__ float g_pool[NM * DH];
__device__ float g_hid[NM * DH];

// ---------------- warp-mma helpers ----------------
__device__ __forceinline__ uint32_t smem_u32(const void* p) {
    uint32_t a;
    asm("{ .reg .u64 t; cvta.to.shared.u64 t, %1; cvt.u32.u64 %0, t; }" : "=r"(a) : "l"(p));
    return a;
}

__device__ __forceinline__ void ldm_x4(uint32_t* r, uint32_t addr) {
    asm volatile("ldmatrix.sync.aligned.m8n8.x4.shared.b16 {%0,%1,%2,%3}, [%4];"
                 : "=r"(r[0]), "=r"(r[1]), "=r"(r[2]), "=r"(r[3]) : "r"(addr));
}

__device__ __forceinline__ void mma16816(float* c, const uint32_t* a, uint32_t b0, uint32_t b1) {
    asm volatile(
        "mma.sync.aligned.m16n8k16.row.col.f32.bf16.bf16.f32 "
        "{%0,%1,%2,%3}, {%4,%5,%6,%7}, {%8,%9}, {%0,%1,%2,%3};"
        : "+f"(c[0]), "+f"(c[1]), "+f"(c[2]), "+f"(c[3])
        : "r"(a[0]), "r"(a[1]), "r"(a[2]), "r"(a[3]), "r"(b0), "r"(b1));
}

__device__ __forceinline__ void cpa16(uint32_t dst, const void* src) {
    asm volatile("cp.async.ca.shared.global [%0], [%1], 16;" :: "r"(dst), "l"(src));
}
__device__ __forceinline__ void cpa_commit() {
    asm volatile("cp.async.commit_group;" ::: "memory");
}
template<int N_>
__device__ __forceinline__ void cpa_wait() {
    asm volatile("cp.async.wait_group %0;" :: "n"(N_) : "memory");
}

// ---------------- split-bf16 tensor-core GEMM ----------------
// Block 128x128, BK=32, 4 warps (2x2), warp tile 64x64, double-buffered cp.async.
#define BM 128
#define BN 128
#define BK 32
#define SPAD 40
#define OFF_AL (BM * SPAD)
#define OFF_BH (2 * BM * SPAD)
#define OFF_BL (3 * BM * SPAD)
#define STAGE_BYTES (4 * BM * SPAD * 2)          // 40960
#define MM_SMEM (2 * STAGE_BYTES)                // 81920

template<bool OUT_BF16, bool BIAS, bool TANH_ACT>
__global__ __launch_bounds__(128, 2)
void mmgemm(const bf16* __restrict__ Ahi, const bf16* __restrict__ Alo, int lda, long sA,
            const bf16* __restrict__ Bhi, const bf16* __restrict__ Blo, int ldb, long sB,
            float* __restrict__ Cf, bf16* __restrict__ Chi, bf16* __restrict__ Clo,
            int ldc, long sC, const float* __restrict__ bias,
            int M, int N, int K)
{
    extern __shared__ char dsm[];
    const uint32_t u_sm = smem_u32(dsm);

    Ahi += (long)blockIdx.z * sA;  Alo += (long)blockIdx.z * sA;
    Bhi += (long)blockIdx.z * sB;  Blo += (long)blockIdx.z * sB;
    const long coff = (long)blockIdx.z * sC;

    const int tid = threadIdx.x, lane = tid & 31, wid = tid >> 5;
    const int wr = wid >> 1, wc = wid & 1;              // 2x2 warps, 64x64 each
    const int m0 = blockIdx.y * BM, n0 = blockIdx.x * BN;

    float acc[4][8][4];
#pragma unroll
    for (int i = 0; i < 4; i++)
#pragma unroll
        for (int j = 0; j < 8; j++)
#pragma unroll
            for (int e = 0; e < 4; e++) acc[i][j][e] = 0.f;

    const int lrow = lane & 15;
    const uint32_t lkb = (uint32_t)((lane >> 4) * 16);
    const uint32_t aA = (uint32_t)((wr * 64 + lrow) * SPAD * 2) + lkb;
    const uint32_t aB = (uint32_t)(OFF_BH * 2) + (uint32_t)((wc * 64 + lrow) * SPAD * 2) + lkb;

    // async stage loader: 16 x 16B per thread (2048 total)
    auto load_stage = [&](int st, int k0) {
        const uint32_t sbase = u_sm + (uint32_t)(st * STAGE_BYTES);
#pragma unroll
        for (int i = 0; i < 16; i++) {
            int u = tid + i * 128;             // 0..2047
            int r  = (u & 511) >> 2;
            int sg = (u & 3) << 3;
            const bf16* src;
            uint32_t doff;
            if (u < 512) {
                int ga = m0 + r; if (ga > M - 1) ga = M - 1;
                src = Ahi + (long)ga * lda + k0 + sg;
                doff = (uint32_t)((r * SPAD + sg) * 2);
            } else if (u < 1024) {
                int ga = m0 + r; if (ga > M - 1) ga = M - 1;
                src = Alo + (long)ga * lda + k0 + sg;
                doff = (uint32_t)((OFF_AL + r * SPAD + sg) * 2);
            } else if (u < 1536) {
                int gb = n0 + r; if (gb > N - 1) gb = N - 1;
                src = Bhi + (long)gb * ldb + k0 + sg;
                doff = (uint32_t)((OFF_BH + r * SPAD + sg) * 2);
            } else {
                int gb = n0 + r; if (gb > N - 1) gb = N - 1;
                src = Blo + (long)gb * ldb + k0 + sg;
                doff = (uint32_t)((OFF_BL + r * SPAD + sg) * 2);
            }
            cpa16(sbase + doff, src);
        }
    };

    const int nch = K / BK;
    load_stage(0, 0);
    cpa_commit();

    for (int ch = 0; ch < nch; ch++) {
        if (ch + 1 < nch) {
            load_stage((ch + 1) & 1, (ch + 1) * BK);
            cpa_commit();
            cpa_wait<1>();
        } else {
            cpa_wait<0>();
        }
        __syncthreads();

        const uint32_t so = u_sm + (uint32_t)((ch & 1) * STAGE_BYTES);
#pragma unroll
        for (int ks = 0; ks < 2; ks++) {
            const uint32_t ko = so + (uint32_t)(ks * 16 * 2);
            uint32_t bh[4][4], bl[4][4];
#pragma unroll
            for (int nt = 0; nt < 4; nt++) {
                ldm_x4(bh[nt], aB + (uint32_t)(nt * 16 * SPAD * 2) + ko);
                ldm_x4(bl[nt], aB + (uint32_t)((BM * SPAD + nt * 16 * SPAD) * 2) + ko);
            }
#pragma unroll
            for (int mi = 0; mi < 4; mi++) {
                uint32_t ah[4], al[4];
                ldm_x4(ah, aA + (uint32_t)(mi * 16 * SPAD * 2) + ko);
                ldm_x4(al, aA + (uint32_t)((OFF_AL + mi * 16 * SPAD) * 2) + ko);
#pragma unroll
                for (int nt = 0; nt < 4; nt++) {
#pragma unroll
                    for (int j = 0; j < 2; j++) {
                        const int nj = nt * 2 + j;
                        mma16816(acc[mi][nj], ah, bh[nt][j], bh[nt][j + 2]);
                        mma16816(acc[mi][nj], ah, bl[nt][j], bl[nt][j + 2]);
                        mma16816(acc[mi][nj], al, bh[nt][j], bh[nt][j + 2]);
                    }
                }
            }
        }
        __syncthreads();
    }

    const int er = m0 + wr * 64 + (lane >> 2);
    const int ec = n0 + wc * 64 + (lane & 3) * 2;
#pragma unroll
    for (int mi = 0; mi < 4; mi++) {
#pragma unroll
        for (int nj = 0; nj < 8; nj++) {
            const int col = ec + nj * 8;
            float bv0 = 0.f, bv1 = 0.f;
            if (BIAS) { bv0 = bias[col]; bv1 = bias[col + 1]; }
#pragma unroll
            for (int half = 0; half < 2; half++) {
                const int row = er + mi * 16 + half * 8;
                if (row >= M) continue;
                float v0 = acc[mi][nj][half * 2 + 0] + bv0;
                float v1 = acc[mi][nj][half * 2 + 1] + bv1;
                if (TANH_ACT) { v0 = tanhf(v0); v1 = tanhf(v1); }
                const long base = (long)row * ldc + coff + col;
                if (OUT_BF16) {
                    bf16 h0 = __float2bfloat16(v0);
                    bf16 h1 = __float2bfloat16(v1);
                    Chi[base] = h0;     Chi[base + 1] = h1;
                    Clo[base]     = __float2bfloat16(v0 - __bfloat162float(h0));
                    Clo[base + 1] = __float2bfloat16(v1 - __bfloat162float(h1));
                } else {
                    Cf[base] = v0;  Cf[base + 1] = v1;
                }
            }
        }
    }
}

// ---------------- fp32 -> bf16 hi/lo split (elementwise) ----------------
__global__ void split_kernel(const float* __restrict__ in, bf16* __restrict__ hi,
                             bf16* __restrict__ lo, long n)
{
    long i0 = ((long)blockIdx.x * blockDim.x + threadIdx.x) * 4;
    long stride = (long)gridDim.x * blockDim.x * 4;
    for (long i = i0; i < n; i += stride) {
        float4 v = *reinterpret_cast<const float4*>(in + i);
        float vv[4] = {v.x, v.y, v.z, v.w};
#pragma unroll
        for (int j = 0; j < 4; j++) {
            bf16 h = __float2bfloat16(vv[j]);
            hi[i + j] = h;
            lo[i + j] = __float2bfloat16(vv[j] - __bfloat162float(h));
        }
    }
}

// ---------------- fp32 [R,C] -> transposed bf16 hi/lo [C,R] ----------------
__global__ void splitT_kernel(const float* __restrict__ in, bf16* __restrict__ hi,
                              bf16* __restrict__ lo, int R, int C)
{
    __shared__ float t[32][33];
    int c0 = blockIdx.x * 32, r0 = blockIdx.y * 32;
    for (int i = threadIdx.y; i < 32; i += 8)
        t[i][threadIdx.x] = in[(long)(r0 + i) * C + c0 + threadIdx.x];
    __syncthreads();
    for (int i = threadIdx.y; i < 32; i += 8) {
        float v = t[threadIdx.x][i];
        long o = (long)(c0 + i) * R + r0 + threadIdx.x;
        bf16 h = __float2bfloat16(v);
        hi[o] = h;
        lo[o] = __float2bfloat16(v - __bfloat162float(h));
    }
}

// ---------------- seq -> cat[:, 0:768] hi/lo ----------------
__global__ void seq_split_kernel(const float* __restrict__ seq)
{
    int row = blockIdx.x, t = threadIdx.x;
    for (int idx = t; idx < DH; idx += 256) {
        float v = seq[(long)row * DH + idx];
        long o = (long)row * 2 * DH + idx;
        bf16 h = __float2bfloat16(v);
        g_cat_hi[o] = h;
        g_cat_lo[o] = __float2bfloat16(v - __bfloat162float(h));
    }
}

// ---------------- attention scores + softmax per token (dedup) ----------------
// grid (HH, NB); block 256. q rows = 128 tokens of batch n (seq directly).
__global__ __launch_bounds__(256) void att_scores_u(const float* __restrict__ seq)
{
    const int h = blockIdx.x, n = blockIdx.y;
    __shared__ float buf[128 * 65 + 49 * 65];          // sQ | sK ; sS aliases sQ
    float (*sQ)[65] = reinterpret_cast<float(*)[65]>(buf);
    float (*sK)[65] = reinterpret_cast<float(*)[65]>(buf + 128 * 65);
    float* sS = buf;
    const int t = threadIdx.x;
    const int qg = t & 31, rg = t >> 5;                // q = qg + 32*qi ; r = rg*7+i (rg<7)

    float acc[4][7];
#pragma unroll
    for (int a = 0; a < 4; a++)
#pragma unroll
        for (int b = 0; b < 7; b++) acc[a][b] = 0.f;

    const float* Qp = seq + (long)n * LSEQ * DH;
    const float* Kp = g_KC + ((long)h * NR + (long)n * RR) * DH;

    for (int kc = 0; kc < DH / 64; kc++) {
        const int k0 = kc * 64;
        for (int e = t; e < 128 * 64; e += 256)
            sQ[e >> 6][e & 63] = Qp[(long)(e >> 6) * DH + k0 + (e & 63)];
        for (int e = t; e < 49 * 64; e += 256)
            sK[e / 64][e % 64] = Kp[(long)(e / 64) * DH + k0 + (e % 64)];
        __syncthreads();
        if (rg < 7) {
            for (int kk = 0; kk < 64; kk++) {
                float kv[7];
#pragma unroll
                for (int i = 0; i < 7; i++) kv[i] = sK[rg * 7 + i][kk];
#pragma unroll
                for (int qi = 0; qi < 4; qi++) {
                    float qv = sQ[qg + 32 * qi][kk];
#pragma unroll
                    for (int i = 0; i < 7; i++) acc[qi][i] += qv * kv[i];
                }
            }
        }
        __syncthreads();
    }

    const float scale = 1.0f / sqrtf((float)DH);
    if (rg < 7) {
#pragma unroll
        for (int qi = 0; qi < 4; qi++)
#pragma unroll
            for (int i = 0; i < 7; i++)
                sS[(qg + 32 * qi) * 49 + rg * 7 + i] = acc[qi][i] * scale;
    }
    __syncthreads();

    if (t < 128) {
        float* row = sS + t * 49;
        float mx = row[0];
        for (int r = 1; r < RR; r++) mx = fmaxf(mx, row[r]);
        float sum = 0.f;
        float ex[49];
        for (int r = 0; r < RR; r++) { ex[r] = expf(row[r] - mx); sum += ex[r]; }
        float inv = 1.f / sum;
        float* out = g_P + (((long)(n * HH + h)) * LSEQ + t) * RR;
        for (int r = 0; r < RR; r++) out[r] = ex[r] * inv;
    }
}

// ---------------- out = LN(sum_h P_h @ VC_h + seq) -> cat[:, 768:1536] hi/lo ----------------
// grid (8, NB): block (n, qg) handles 16 tokens x 768 dims. 256 threads.
#define AOL_SMEM ((8 * 16 * 49 + 16 * 768) * 4)       // 74240 bytes
__global__ __launch_bounds__(256) void att_out_ln_u(const float* __restrict__ seq,
                                                    const float* __restrict__ gam,
                                                    const float* __restrict__ bet)
{
    extern __shared__ float ds[];
    float* sP = ds;                 // [8][16][49]
    float* sX = ds + 8 * 16 * 49;   // [16][768]
    const int qg = blockIdx.x, n = blockIdx.y;
    const int t = threadIdx.x;

    for (int e = t; e < 8 * 16 * 49; e += 256) {
        int h = e / (16 * 49), rem = e % (16 * 49);
        int q = rem / 49, r = rem % 49;
        sP[e] = g_P[(((long)(n * HH + h)) * LSEQ + qg * 16 + q) * RR + r];
    }
    __syncthreads();

    float acc[16][3];
#pragma unroll
    for (int q = 0; q < 16; q++) { acc[q][0] = 0.f; acc[q][1] = 0.f; acc[q][2] = 0.f; }

    for (int h = 0; h < HH; h++) {
        const float* Vb = g_VC + ((long)h * NR + (long)n * RR) * DH;
        const float* Ph = sP + h * 16 * 49;
        for (int r = 0; r < RR; r++) {
            float v0 = Vb[(long)r * DH + t];
            float v1 = Vb[(long)r * DH + 256 + t];
            float v2 = Vb[(long)r * DH + 512 + t];
            const float* Pr = Ph + r;
#pragma unroll
            for (int q = 0; q < 16; q++) {
                float p = Pr[q * 49];
                acc[q][0] += p * v0; acc[q][1] += p * v1; acc[q][2] += p * v2;
            }
        }
    }

#pragma unroll
    for (int q = 0; q < 16; q++) {
        long srow = ((long)n * LSEQ + qg * 16 + q) * DH;
        sX[q * 768 + t]       = acc[q][0] + seq[srow + t];
        sX[q * 768 + 256 + t] = acc[q][1] + seq[srow + 256 + t];
        sX[q * 768 + 512 + t] = acc[q][2] + seq[srow + 512 + t];
    }
    __syncthreads();

    // LN per row: 8 warps x 2 rows
    const int wid = t >> 5, lane = t & 31;
    for (int qq = wid * 2; qq < wid * 2 + 2; qq++) {
        float* row = sX + qq * 768;
        float s = 0.f;
        for (int k = lane; k < DH; k += 32) s += row[k];
        for (int o = 16; o; o >>= 1) s += __shfl_xor_sync(0xffffffffu, s, o);
        float mu = s * (1.f / DH);
        float v = 0.f;
        for (int k = lane; k < DH; k += 32) { float d = row[k] - mu; v += d * d; }
        for (int o = 16; o; o >>= 1) v += __shfl_xor_sync(0xffffffffu, v, o);
        float rstd = rsqrtf(v * (1.f / DH) + 1e-5f);
        long orow = ((long)n * LSEQ + qg * 16 + qq) * 2 * DH + DH;
        for (int k = lane; k < DH; k += 32) {
            float val = (row[k] - mu) * rstd * gam[k] + bet[k];
            bf16 h = __float2bfloat16(val);
            g_cat_hi[orow + k] = h;
            g_cat_lo[orow + k] = __float2bfloat16(val - __bfloat162float(h));
        }
    }
}

// ---------------- unary score + masked softmax pooling (token-indexed) ----------------
__global__ void pool_kernel(const float* __restrict__ W_un, const float* __restrict__ b_un,
                            const int* __restrict__ starts, const int* __restrict__ ends)
{
    int sp = blockIdx.x, t = threadIdx.x;
    int lane = t & 31, w = t >> 5;
    int n = sp >> 3;
    int base = n * LSEQ + starts[sp];
    __shared__ float sS[JR];
    __shared__ float sProb[JR];

    for (int j = w; j < JR; j += 8) {
        int u = base + j; if (u > UU - 1) u = UU - 1;
        const float* fr = g_fused + (long)u * DH;
        float acc = 0.f;
        for (int k = lane; k < DH; k += 32) acc += fr[k] * W_un[k];
        for (int o = 16; o; o >>= 1) acc += __shfl_xor_sync(0xffffffffu, acc, o);
        if (lane == 0) sS[j] = acc + b_un[0];
    }
    __syncthreads();
    if (t == 0) {
        int width = ends[sp] - starts[sp] + 1;
        float mx = -1e30f;
        for (int j = 0; j < JR; j++) {
            float v = sS[j] + ((j < width) ? 0.f : -10000.f);
            sS[j] = v; mx = fmaxf(mx, v);
        }
        float sum = 0.f;
        for (int j = 0; j < JR; j++) { float e = expf(sS[j] - mx); sProb[j] = e; sum += e; }
        float inv = 1.f / sum;
        for (int j = 0; j < JR; j++) sProb[j] *= inv;
    }
    __syncthreads();
    for (int d = t; d < DH; d += 256) {
        float acc = 0.f;
        for (int j = 0; j < JR; j++) {
            int u = base + j; if (u > UU - 1) u = UU - 1;
            acc += sProb[j] * g_fused[(long)u * DH + d];
        }
        g_pool[(long)sp * DH + d] = acc;
    }
}

// ---------------- small fp32 sgemm (tiny dense layer only) ----------------
template<bool TRANSB, bool BIAS, bool TANH_ACT>
__global__ void sgemm(const float* __restrict__ A, int lda, long sA,
                      const float* __restrict__ B, int ldb, long sB,
                      float* __restrict__ C, int ldc, long sC,
                      const float* __restrict__ bias,
                      int M, int N, int K)
{
    A += (long)blockIdx.z * sA;
    B += (long)blockIdx.z * sB;
    C += (long)blockIdx.z * sC;
    __shared__ float As[16][128];
    __shared__ float Bs[16][128];
    const int tid = threadIdx.x;
    const int m0 = blockIdx.y * 128;
    const int n0 = blockIdx.x * 128;
    const int tx = tid & 15;
    const int ty = tid >> 4;
    float acc[8][8];
#pragma unroll
    for (int i = 0; i < 8; i++)
#pragma unroll
        for (int j = 0; j < 8; j++) acc[i][j] = 0.f;

    for (int k0 = 0; k0 < K; k0 += 16) {
#pragma unroll
        for (int i = 0; i < 2; i++) {
            int li = tid + i * 256;
            int row = li >> 2;
            int kk  = (li & 3) << 2;
            float4 v = make_float4(0.f, 0.f, 0.f, 0.f);
            if (m0 + row < M)
                v = *reinterpret_cast<const float4*>(&A[(long)(m0 + row) * lda + k0 + kk]);
            As[kk + 0][row] = v.x; As[kk + 1][row] = v.y;
            As[kk + 2][row] = v.z; As[kk + 3][row] = v.w;
        }
        if (!TRANSB) {
#pragma unroll
            for (int i = 0; i < 2; i++) {
                int li = tid + i * 256;
                int kr = li >> 5;
                int nn = (li & 31) << 2;
                float4 v = *reinterpret_cast<const float4*>(&B[(long)(k0 + kr) * ldb + n0 + nn]);
                *reinterpret_cast<float4*>(&Bs[kr][nn]) = v;
            }
        } else {
#pragma unroll
            for (int i = 0; i < 2; i++) {
                int li = tid + i * 256;
                int nr = li >> 2;
                int kk = (li & 3) << 2;
                float4 v = make_float4(0.f, 0.f, 0.f, 0.f);
                if (n0 + nr < N)
                    v = *reinterpret_cast<const float4*>(&B[(long)(n0 + nr) * ldb + k0 + kk]);
                Bs[kk + 0][nr] = v.x; Bs[kk + 1][nr] = v.y;
                Bs[kk + 2][nr] = v.z; Bs[kk + 3][nr] = v.w;
            }
        }
        __syncthreads();
#pragma unroll
        for (int k = 0; k < 16; k++) {
            float a[8], b[8];
#pragma unroll
            for (int i = 0; i < 8; i++) a[i] = As[k][ty * 8 + i];
#pragma unroll
            for (int j = 0; j < 8; j++) b[j] = Bs[k][tx * 8 + j];
#pragma unroll
            for (int i = 0; i < 8; i++)
#pragma unroll
                for (int j = 0; j < 8; j++) acc[i][j] += a[i] * b[j];
        }
        __syncthreads();
    }
#pragma unroll
    for (int i = 0; i < 8; i++) {
        int m = m0 + ty * 8 + i;
        if (m >= M) continue;
#pragma unroll
        for (int j = 0; j < 8; j++) {
            int n = n0 + tx * 8 + j;
            float v = acc[i][j];
            if (BIAS) v += bias[n];
            if (TANH_ACT) v = tanhf(v);
            C[(long)m * ldc + n] = v;
        }
    }
}

// ---------------- classifier ----------------
__global__ void cls_kernel(const float* __restrict__ W_cls, const float* __restrict__ b_cls,
                           float* __restrict__ out)
{
    int row = blockIdx.x, t = threadIdx.x;
    int lane = t & 31, c = t >> 5;
    const float* hr = g_hid + (long)row * DH;
    float acc = 0.f;
    for (int k = lane; k < DH; k += 32) acc += hr[k] * W_cls[k * 4 + c];
    for (int o = 16; o; o >>= 1) acc += __shfl_xor_sync(0xffffffffu, acc, o);
    if (lane == 0) out[row * 4 + c] = acc + b_cls[c];
}

// ---------------- launcher ----------------
extern "C" void kernel_launch(void* const* d_in, const int* in_sizes, int n_in,
                              void* d_out, int out_size)
{
    const float* enc_img  = (const float*)d_in[0];
    const float* seq      = (const float*)d_in[1];
    const int*   starts   = (const int*)d_in[3];
    const int*   ends     = (const int*)d_in[4];
    const float* W_align  = (const float*)d_in[5];
    const float* b_align  = (const float*)d_in[6];
    const float* Wq       = (const float*)d_in[7];
    const float* Wk       = (const float*)d_in[8];
    const float* Wv       = (const float*)d_in[9];
    const float* Wfc      = (const float*)d_in[10];
    const float* ln_g     = (const float*)d_in[11];
    const float* ln_b     = (const float*)d_in[12];
    const float* W_a1     = (const float*)d_in[13];
    const float* b_a1     = (const float*)d_in[14];
    const float* W_a2     = (const float*)d_in[15];
    const float* b_a2     = (const float*)d_in[16];
    const float* W_un     = (const float*)d_in[17];
    const float* b_un     = (const float*)d_in[18];
    const float* W_dense  = (const float*)d_in[19];
    const float* b_dense  = (const float*)d_in[20];
    const float* W_cls    = (const float*)d_in[21];
    const float* b_cls    = (const float*)d_in[22];

    bf16 *eh, *el, *wath, *watl, *wqh, *wql, *wkh, *wkl, *wvh, *wvl, *wfh, *wfl;
    bf16 *c1h, *c1l, *bqh, *bql, *wvfh, *wvfl;
    bf16 *cth, *ctl, *wa1h, *wa1l, *f1h, *f1l, *wa2h, *wa2l;
    float *pKC, *pVC, *pFused, *pPool, *pHid;
    cudaGetSymbolAddress((void**)&eh,   g_enc_hi);  cudaGetSymbolAddress((void**)&el,   g_enc_lo);
    cudaGetSymbolAddress((void**)&wath, g_WalT_hi); cudaGetSymbolAddress((void**)&watl, g_WalT_lo);
    cudaGetSymbolAddress((void**)&wqh,  g_Wq_hi);   cudaGetSymbolAddress((void**)&wql,  g_Wq_lo);
    cudaGetSymbolAddress((void**)&wkh,  g_Wk_hi);   cudaGetSymbolAddress((void**)&wkl,  g_Wk_lo);
    cudaGetSymbolAddress((void**)&wvh,  g_Wv_hi);   cudaGetSymbolAddress((void**)&wvl,  g_Wv_lo);
    cudaGetSymbolAddress((void**)&wfh,  g_WfcT_hi); cudaGetSymbolAddress((void**)&wfl,  g_WfcT_lo);
    cudaGetSymbolAddress((void**)&c1h,  g_C1_hi);   cudaGetSymbolAddress((void**)&c1l,  g_C1_lo);
    cudaGetSymbolAddress((void**)&bqh,  g_Bqk_hi);  cudaGetSymbolAddress((void**)&bql,  g_Bqk_lo);
    cudaGetSymbolAddress((void**)&wvfh, g_WvfT_hi); cudaGetSymbolAddress((void**)&wvfl, g_WvfT_lo);
    cudaGetSymbolAddress((void**)&cth,  g_cat_hi);  cudaGetSymbolAddress((void**)&ctl,  g_cat_lo);
    cudaGetSymbolAddress((void**)&wa1h, g_Wa1T_hi); cudaGetSymbolAddress((void**)&wa1l, g_Wa1T_lo);
    cudaGetSymbolAddress((void**)&f1h,  g_f1_hi);   cudaGetSymbolAddress((void**)&f1l,  g_f1_lo);
    cudaGetSymbolAddress((void**)&wa2h, g_Wa2T_hi); cudaGetSymbolAddress((void**)&wa2l, g_Wa2T_lo);
    cudaGetSymbolAddress((void**)&pKC, g_KC);       cudaGetSymbolAddress((void**)&pVC, g_VC);
    cudaGetSymbolAddress((void**)&pFused, g_fused);
    cudaGetSymbolAddress((void**)&pPool, g_pool);   cudaGetSymbolAddress((void**)&pHid, g_hid);

    cudaFuncSetAttribute(mmgemm<true,  true,  false>, cudaFuncAttributeMaxDynamicSharedMemorySize, MM_SMEM);
    cudaFuncSetAttribute(mmgemm<true,  false, false>, cudaFuncAttributeMaxDynamicSharedMemorySize, MM_SMEM);
    cudaFuncSetAttribute(mmgemm<false, false, false>, cudaFuncAttributeMaxDynamicSharedMemorySize, MM_SMEM);
    cudaFuncSetAttribute(mmgemm<true,  true,  true >, cudaFuncAttributeMaxDynamicSharedMemorySize, MM_SMEM);
    cudaFuncSetAttribute(mmgemm<false, true,  false>, cudaFuncAttributeMaxDynamicSharedMemorySize, MM_SMEM);
    cudaFuncSetAttribute(att_out_ln_u, cudaFuncAttributeMaxDynamicSharedMemorySize, AOL_SMEM);

    const dim3 blk(128);
    const long HD2 = (long)DH * DH;
    const long NRD = (long)NR * DH;

    // ---- operand conversions ----
    split_kernel<<<1024, 256>>>(enc_img, eh, el, (long)NR * IMGD);
    splitT_kernel<<<dim3(DH / 32, IMGD / 32), dim3(32, 8)>>>(W_align, wath, watl, IMGD, DH);
    split_kernel<<<1024, 256>>>(Wq, wqh, wql, (long)DH * HH * DH);
    split_kernel<<<1024, 256>>>(Wk, wkh, wkl, (long)DH * HH * DH);
    split_kernel<<<1024, 256>>>(Wv, wvh, wvl, (long)DH * HH * DH);
    splitT_kernel<<<dim3(DH / 32, (HH * DH) / 32), dim3(32, 8)>>>(Wfc, wfh, wfl, HH * DH, DH);
    splitT_kernel<<<dim3((2*DH) / 32, (2*DH) / 32), dim3(32, 8)>>>(W_a1, wa1h, wa1l, 2*DH, 2*DH);
    splitT_kernel<<<dim3(DH / 32, (2*DH) / 32), dim3(32, 8)>>>(W_a2, wa2h, wa2l, 2*DH, DH);
    seq_split_kernel<<<UU, 256>>>(seq);

    // ---- G1: C1 = enc_img @ W_align + b_align -> bf16 hi/lo [784,768] ----
    mmgemm<true, true, false><<<dim3(6, 7, 1), blk, MM_SMEM>>>(
        eh, el, IMGD, 0, wath, watl, IMGD, 0,
        nullptr, c1h, c1l, DH, 0, b_align, NR, DH, IMGD);

    // ---- G2: Bqk_h = Wq_h @ Wk_h^T -> bf16 hi/lo [8][768,768] ----
    mmgemm<true, false, false><<<dim3(6, 6, HH), blk, MM_SMEM>>>(
        wqh, wql, HH * DH, DH, wkh, wkl, HH * DH, DH,
        nullptr, bqh, bql, DH, HD2, nullptr, DH, DH, DH);

    // ---- G3: WvfT_h = (Wv_h @ Wfc_h)^T -> bf16 hi/lo ----
    mmgemm<true, false, false><<<dim3(6, 6, HH), blk, MM_SMEM>>>(
        wfh, wfl, HH * DH, DH, wvh, wvl, HH * DH, DH,
        nullptr, wvfh, wvfl, DH, HD2, nullptr, DH, DH, DH);

    // ---- G4: KC_h = C1 @ Bqk_h^T -> fp32 [8][784,768] ----
    mmgemm<false, false, false><<<dim3(6, 7, HH), blk, MM_SMEM>>>(
        c1h, c1l, DH, 0, bqh, bql, DH, HD2,
        pKC, nullptr, nullptr, DH, NRD, nullptr, NR, DH, DH);

    // ---- G5: VC_h = C1 @ WvfT_h^T -> fp32 [8][784,768] ----
    mmgemm<false, false, false><<<dim3(6, 7, HH), blk, MM_SMEM>>>(
        c1h, c1l, DH, 0, wvfh, wvfl, DH, HD2,
        pVC, nullptr, nullptr, DH, NRD, nullptr, NR, DH, DH);

    // ---- attention on 2048 distinct tokens ----
    att_scores_u<<<dim3(HH, NB), 256>>>(seq);
    att_out_ln_u<<<dim3(8, NB), 256, AOL_SMEM>>>(seq, ln_g, ln_b);

    // ---- fusion MLP on 2048 tokens ----
    mmgemm<true, true, true><<<dim3(12, 16, 1), blk, MM_SMEM>>>(
        cth, ctl, 2 * DH, 0, wa1h, wa1l, 2 * DH, 0,
        nullptr, f1h, f1l, 2 * DH, 0, b_a1, UU, 2 * DH, 2 * DH);
    mmgemm<false, true, false><<<dim3(6, 16, 1), blk, MM_SMEM>>>(
        f1h, f1l, 2 * DH, 0, wa2h, wa2l, 2 * DH, 0,
        pFused, nullptr, nullptr, DH, 0, b_a2, UU, DH, 2 * DH);

    // ---- pooling + head ----
    pool_kernel<<<NM, 256>>>(W_un, b_un, starts, ends);
    sgemm<false, true, true><<<dim3(6, 1, 1), dim3(256)>>>(
        pPool, DH, 0, W_dense, DH, 0, pHid, DH, 0, b_dense, NM, DH, DH);
    cls_kernel<<<NM, 128>>>(W_cls, b_cls, (float*)d_out);
}

// round 7
// speedup vs baseline: 1.8180x; 1.1289x over previous
#include <cuda_runtime.h>
#include <cuda_bf16.h>
#include <math.h>
#include <stdint.h>

// ---------------- problem constants ----------------
#define NB    16
#define LSEQ  128
#define DH    768
#define MSP   8
#define HH    8
#define JR    30
#define RR    49
#define IMGD  2048
#define NM    128            // NB*MSP
#define UU    2048           // NB*LSEQ distinct tokens
#define NR    784            // NB*RR

typedef __nv_bfloat16 bf16;

// ---------------- scratch (device globals; no cudaMalloc allowed) ----------------
__device__ bf16 g_enc_hi[NR * IMGD],        g_enc_lo[NR * IMGD];
__device__ bf16 g_WalT_hi[DH * IMGD],       g_WalT_lo[DH * IMGD];
__device__ bf16 g_Wq_hi[DH * HH * DH],      g_Wq_lo[DH * HH * DH];
__device__ bf16 g_Wk_hi[DH * HH * DH],      g_Wk_lo[DH * HH * DH];
__device__ bf16 g_Wv_hi[DH * HH * DH],      g_Wv_lo[DH * HH * DH];
__device__ bf16 g_WfcT_hi[DH * HH * DH],    g_WfcT_lo[DH * HH * DH];
__device__ bf16 g_C1_hi[NR * DH],           g_C1_lo[NR * DH];
__device__ bf16 g_Bqk_hi[HH * DH * DH],     g_Bqk_lo[HH * DH * DH];
__device__ bf16 g_WvfT_hi[HH * DH * DH],    g_WvfT_lo[HH * DH * DH];
__device__ float g_KC[HH * NR * DH];
__device__ float g_VC[HH * NR * DH];
__device__ float g_P[NB * HH * LSEQ * RR];
__device__ bf16 g_cat_hi[UU * 2 * DH],      g_cat_lo[UU * 2 * DH];
__device__ bf16 g_Wa1T_hi[2*DH * 2*DH],     g_Wa1T_lo[2*DH * 2*DH];
__device__ bf16 g_f1_hi[UU * 2 * DH],       g_f1_lo[UU * 2 * DH];
__device__ bf16 g_Wa2T_hi[DH * 2*DH],       g_Wa2T_lo[DH * 2*DH];
__device__ float g_fused[UU * DH];
__device__ float g_pool[NM * DH];
__device__ float g_hid[NM * DH];

// ---------------- helpers ----------------
__device__ __forceinline__ uint32_t smem_u32(const void* p) {
    uint32_t a;
    asm("{ .reg .u64 t; cvta.to.shared.u64 t, %1; cvt.u32.u64 %0, t; }" : "=r"(a) : "l"(p));
    return a;
}

__device__ __forceinline__ void ldm_x4(uint32_t* r, uint32_t addr) {
    asm volatile("ldmatrix.sync.aligned.m8n8.x4.shared.b16 {%0,%1,%2,%3}, [%4];"
                 : "=r"(r[0]), "=r"(r[1]), "=r"(r[2]), "=r"(r[3]) : "r"(addr));
}

__device__ __forceinline__ void mma16816(float* c, const uint32_t* a, uint32_t b0, uint32_t b1) {
    asm volatile(
        "mma.sync.aligned.m16n8k16.row.col.f32.bf16.bf16.f32 "
        "{%0,%1,%2,%3}, {%4,%5,%6,%7}, {%8,%9}, {%0,%1,%2,%3};"
        : "+f"(c[0]), "+f"(c[1]), "+f"(c[2]), "+f"(c[3])
        : "r"(a[0]), "r"(a[1]), "r"(a[2]), "r"(a[3]), "r"(b0), "r"(b1));
}

__device__ __forceinline__ void cpa16(uint32_t dst, const void* src) {
    asm volatile("cp.async.ca.shared.global [%0], [%1], 16;" :: "r"(dst), "l"(src));
}
__device__ __forceinline__ void cpa_commit() {
    asm volatile("cp.async.commit_group;" ::: "memory");
}
template<int N_>
__device__ __forceinline__ void cpa_wait() {
    asm volatile("cp.async.wait_group %0;" :: "n"(N_) : "memory");
}

__device__ __forceinline__ uint32_t pack_bf2(float a, float b) {
    __nv_bfloat162 h = __floats2bfloat162_rn(a, b);
    return reinterpret_cast<uint32_t&>(h);
}

// ---------------- split-bf16 tensor-core GEMM body ----------------
// Block 128x128, BK=32, 4 warps (2x2), warp tile 64x64, double-buffered cp.async.
#define BM 128
#define BN 128
#define BK 32
#define SPAD 40
#define OFF_AL (BM * SPAD)
#define OFF_BH (2 * BM * SPAD)
#define OFF_BL (3 * BM * SPAD)
#define STAGE_BYTES (4 * BM * SPAD * 2)          // 40960
#define MM_SMEM (2 * STAGE_BYTES)                // 81920

template<bool OUT_BF16, bool BIAS, bool TANH_ACT>
__device__ __forceinline__ void mm_body(
    const bf16* __restrict__ Ahi, const bf16* __restrict__ Alo, int lda,
    const bf16* __restrict__ Bhi, const bf16* __restrict__ Blo, int ldb,
    float* __restrict__ Cf, bf16* __restrict__ Chi, bf16* __restrict__ Clo, int ldc,
    const float* __restrict__ bias, int M, int N, int K)
{
    extern __shared__ char dsm[];
    const uint32_t u_sm = smem_u32(dsm);

    const int tid = threadIdx.x, lane = tid & 31, wid = tid >> 5;
    const int wr = wid >> 1, wc = wid & 1;
    const int m0 = blockIdx.y * BM, n0 = blockIdx.x * BN;

    float acc[4][8][4];
#pragma unroll
    for (int i = 0; i < 4; i++)
#pragma unroll
        for (int j = 0; j < 8; j++)
#pragma unroll
            for (int e = 0; e < 4; e++) acc[i][j][e] = 0.f;

    const int lrow = lane & 15;
    const uint32_t lkb = (uint32_t)((lane >> 4) * 16);
    const uint32_t aA = (uint32_t)((wr * 64 + lrow) * SPAD * 2) + lkb;
    const uint32_t aB = (uint32_t)(OFF_BH * 2) + (uint32_t)((wc * 64 + lrow) * SPAD * 2) + lkb;

    auto load_stage = [&](int st, int k0) {
        const uint32_t sbase = u_sm + (uint32_t)(st * STAGE_BYTES);
#pragma unroll
        for (int i = 0; i < 16; i++) {
            int u = tid + i * 128;
            int r  = (u & 511) >> 2;
            int sg = (u & 3) << 3;
            const bf16* src;
            uint32_t doff;
            if (u < 512) {
                int ga = m0 + r; if (ga > M - 1) ga = M - 1;
                src = Ahi + (long)ga * lda + k0 + sg;
                doff = (uint32_t)((r * SPAD + sg) * 2);
            } else if (u < 1024) {
                int ga = m0 + r; if (ga > M - 1) ga = M - 1;
                src = Alo + (long)ga * lda + k0 + sg;
                doff = (uint32_t)((OFF_AL + r * SPAD + sg) * 2);
            } else if (u < 1536) {
                int gb = n0 + r; if (gb > N - 1) gb = N - 1;
                src = Bhi + (long)gb * ldb + k0 + sg;
                doff = (uint32_t)((OFF_BH + r * SPAD + sg) * 2);
            } else {
                int gb = n0 + r; if (gb > N - 1) gb = N - 1;
                src = Blo + (long)gb * ldb + k0 + sg;
                doff = (uint32_t)((OFF_BL + r * SPAD + sg) * 2);
            }
            cpa16(sbase + doff, src);
        }
    };

    const int nch = K / BK;
    load_stage(0, 0);
    cpa_commit();

    for (int ch = 0; ch < nch; ch++) {
        if (ch + 1 < nch) {
            load_stage((ch + 1) & 1, (ch + 1) * BK);
            cpa_commit();
            cpa_wait<1>();
        } else {
            cpa_wait<0>();
        }
        __syncthreads();

        const uint32_t so = u_sm + (uint32_t)((ch & 1) * STAGE_BYTES);
#pragma unroll
        for (int ks = 0; ks < 2; ks++) {
            const uint32_t ko = so + (uint32_t)(ks * 16 * 2);
            uint32_t bh[4][4], bl[4][4];
#pragma unroll
            for (int nt = 0; nt < 4; nt++) {
                ldm_x4(bh[nt], aB + (uint32_t)(nt * 16 * SPAD * 2) + ko);
                ldm_x4(bl[nt], aB + (uint32_t)((BM * SPAD + nt * 16 * SPAD) * 2) + ko);
            }
#pragma unroll
            for (int mi = 0; mi < 4; mi++) {
                uint32_t ah[4], al[4];
                ldm_x4(ah, aA + (uint32_t)(mi * 16 * SPAD * 2) + ko);
                ldm_x4(al, aA + (uint32_t)((OFF_AL + mi * 16 * SPAD) * 2) + ko);
#pragma unroll
                for (int nt = 0; nt < 4; nt++) {
#pragma unroll
                    for (int j = 0; j < 2; j++) {
                        const int nj = nt * 2 + j;
                        mma16816(acc[mi][nj], ah, bh[nt][j], bh[nt][j + 2]);
                        mma16816(acc[mi][nj], ah, bl[nt][j], bl[nt][j + 2]);
                        mma16816(acc[mi][nj], al, bh[nt][j], bh[nt][j + 2]);
                    }
                }
            }
        }
        __syncthreads();
    }

    const int er = m0 + wr * 64 + (lane >> 2);
    const int ec = n0 + wc * 64 + (lane & 3) * 2;
#pragma unroll
    for (int mi = 0; mi < 4; mi++) {
#pragma unroll
        for (int nj = 0; nj < 8; nj++) {
            const int col = ec + nj * 8;
            float bv0 = 0.f, bv1 = 0.f;
            if (BIAS) { bv0 = bias[col]; bv1 = bias[col + 1]; }
#pragma unroll
            for (int half = 0; half < 2; half++) {
                const int row = er + mi * 16 + half * 8;
                if (row >= M) continue;
                float v0 = acc[mi][nj][half * 2 + 0] + bv0;
                float v1 = acc[mi][nj][half * 2 + 1] + bv1;
                if (TANH_ACT) { v0 = tanhf(v0); v1 = tanhf(v1); }
                const long base = (long)row * ldc + col;
                if (OUT_BF16) {
                    __nv_bfloat162 h = __floats2bfloat162_rn(v0, v1);
                    __nv_bfloat162 l = __floats2bfloat162_rn(
                        v0 - __bfloat162float(h.x), v1 - __bfloat162float(h.y));
                    *reinterpret_cast<uint32_t*>(Chi + base) = reinterpret_cast<uint32_t&>(h);
                    *reinterpret_cast<uint32_t*>(Clo + base) = reinterpret_cast<uint32_t&>(l);
                } else {
                    *reinterpret_cast<float2*>(Cf + base) = make_float2(v0, v1);
                }
            }
        }
    }
}

template<bool OUT_BF16, bool BIAS, bool TANH_ACT>
__global__ __launch_bounds__(128, 2)
void mmgemm(const bf16* __restrict__ Ahi, const bf16* __restrict__ Alo, int lda, long sA,
            const bf16* __restrict__ Bhi, const bf16* __restrict__ Blo, int ldb, long sB,
            float* __restrict__ Cf, bf16* __restrict__ Chi, bf16* __restrict__ Clo,
            int ldc, long sC, const float* __restrict__ bias,
            int M, int N, int K)
{
    const long za = (long)blockIdx.z * sA, zb = (long)blockIdx.z * sB, zc = (long)blockIdx.z * sC;
    mm_body<OUT_BF16, BIAS, TANH_ACT>(
        Ahi + za, Alo + za, lda, Bhi + zb, Blo + zb, ldb,
        Cf ? Cf + zc : nullptr, Chi ? Chi + zc : nullptr, Clo ? Clo + zc : nullptr,
        ldc, bias, M, N, K);
}

// dual-set batched GEMM: z < zsplit uses set0[z], else set1[z - zsplit]
template<bool OUT_BF16>
__global__ __launch_bounds__(128, 2)
void mmgemm_dual(
    const bf16* __restrict__ A0h, const bf16* __restrict__ A0l, int lda0, long sA0,
    const bf16* __restrict__ B0h, const bf16* __restrict__ B0l, int ldb0, long sB0,
    float* __restrict__ C0f, bf16* __restrict__ C0h, bf16* __restrict__ C0l, int ldc0, long sC0,
    const bf16* __restrict__ A1h, const bf16* __restrict__ A1l, int lda1, long sA1,
    const bf16* __restrict__ B1h, const bf16* __restrict__ B1l, int ldb1, long sB1,
    float* __restrict__ C1f, bf16* __restrict__ C1hh, bf16* __restrict__ C1ll, int ldc1, long sC1,
    int zsplit, int M, int N, int K)
{
    int z = blockIdx.z;
    if (z < zsplit) {
        const long za = (long)z * sA0, zb = (long)z * sB0, zc = (long)z * sC0;
        mm_body<OUT_BF16, false, false>(
            A0h + za, A0l + za, lda0, B0h + zb, B0l + zb, ldb0,
            C0f ? C0f + zc : nullptr, C0h ? C0h + zc : nullptr, C0l ? C0l + zc : nullptr,
            ldc0, nullptr, M, N, K);
    } else {
        z -= zsplit;
        const long za = (long)z * sA1, zb = (long)z * sB1, zc = (long)z * sC1;
        mm_body<OUT_BF16, false, false>(
            A1h + za, A1l + za, lda1, B1h + zb, B1l + zb, ldb1,
            C1f ? C1f + zc : nullptr, C1hh ? C1hh + zc : nullptr, C1ll ? C1ll + zc : nullptr,
            ldc1, nullptr, M, N, K);
    }
}

// ---------------- fp32 -> bf16 hi/lo split (vectorized) ----------------
__global__ void split_kernel(const float* __restrict__ in, bf16* __restrict__ hi,
                             bf16* __restrict__ lo, long n)
{
    long i0 = ((long)blockIdx.x * blockDim.x + threadIdx.x) * 4;
    long stride = (long)gridDim.x * blockDim.x * 4;
    for (long i = i0; i < n; i += stride) {
        float4 v = *reinterpret_cast<const float4*>(in + i);
        __nv_bfloat162 h0 = __floats2bfloat162_rn(v.x, v.y);
        __nv_bfloat162 h1 = __floats2bfloat162_rn(v.z, v.w);
        __nv_bfloat162 l0 = __floats2bfloat162_rn(v.x - __bfloat162float(h0.x),
                                                  v.y - __bfloat162float(h0.y));
        __nv_bfloat162 l1 = __floats2bfloat162_rn(v.z - __bfloat162float(h1.x),
                                                  v.w - __bfloat162float(h1.y));
        *reinterpret_cast<uint2*>(hi + i) =
            make_uint2(reinterpret_cast<uint32_t&>(h0), reinterpret_cast<uint32_t&>(h1));
        *reinterpret_cast<uint2*>(lo + i) =
            make_uint2(reinterpret_cast<uint32_t&>(l0), reinterpret_cast<uint32_t&>(l1));
    }
}

// ---------------- fp32 [R,C] -> transposed bf16 hi/lo [C,R] (packed stores) ----------------
__global__ void splitT_kernel(const float* __restrict__ in, bf16* __restrict__ hi,
                              bf16* __restrict__ lo, int R, int C)
{
    __shared__ float t[32][33];
    int c0 = blockIdx.x * 32, r0 = blockIdx.y * 32;
    for (int i = threadIdx.y; i < 32; i += 8)
        t[i][threadIdx.x] = in[(long)(r0 + i) * C + c0 + threadIdx.x];
    __syncthreads();
    if (threadIdx.x < 16) {
        for (int i = threadIdx.y; i < 32; i += 8) {
            float va = t[2 * threadIdx.x][i];
            float vb = t[2 * threadIdx.x + 1][i];
            __nv_bfloat162 h = __floats2bfloat162_rn(va, vb);
            __nv_bfloat162 l = __floats2bfloat162_rn(va - __bfloat162float(h.x),
                                                     vb - __bfloat162float(h.y));
            long o = (long)(c0 + i) * R + r0 + 2 * threadIdx.x;
            *reinterpret_cast<uint32_t*>(hi + o) = reinterpret_cast<uint32_t&>(h);
            *reinterpret_cast<uint32_t*>(lo + o) = reinterpret_cast<uint32_t&>(l);
        }
    }
}

// ---------------- seq -> cat[:, 0:768] hi/lo (vectorized) ----------------
__global__ void seq_split_kernel(const float* __restrict__ seq)
{
    int row = blockIdx.x, t = threadIdx.x;
    for (int idx = t * 4; idx < DH; idx += 256 * 4) {
        float4 v = *reinterpret_cast<const float4*>(seq + (long)row * DH + idx);
        __nv_bfloat162 h0 = __floats2bfloat162_rn(v.x, v.y);
        __nv_bfloat162 h1 = __floats2bfloat162_rn(v.z, v.w);
        __nv_bfloat162 l0 = __floats2bfloat162_rn(v.x - __bfloat162float(h0.x),
                                                  v.y - __bfloat162float(h0.y));
        __nv_bfloat162 l1 = __floats2bfloat162_rn(v.z - __bfloat162float(h1.x),
                                                  v.w - __bfloat162float(h1.y));
        long o = (long)row * 2 * DH + idx;
        *reinterpret_cast<uint2*>(g_cat_hi + o) =
            make_uint2(reinterpret_cast<uint32_t&>(h0), reinterpret_cast<uint32_t&>(h1));
        *reinterpret_cast<uint2*>(g_cat_lo + o) =
            make_uint2(reinterpret_cast<uint32_t&>(l0), reinterpret_cast<uint32_t&>(l1));
    }
}

// ---------------- attention scores + softmax per token (dedup) ----------------
__global__ __launch_bounds__(256) void att_scores_u(const float* __restrict__ seq)
{
    const int h = blockIdx.x, n = blockIdx.y;
    __shared__ float buf[128 * 65 + 49 * 65];
    float (*sQ)[65] = reinterpret_cast<float(*)[65]>(buf);
    float (*sK)[65] = reinterpret_cast<float(*)[65]>(buf + 128 * 65);
    float* sS = buf;
    const int t = threadIdx.x;
    const int qg = t & 31, rg = t >> 5;

    float acc[4][7];
#pragma unroll
    for (int a = 0; a < 4; a++)
#pragma unroll
        for (int b = 0; b < 7; b++) acc[a][b] = 0.f;

    const float* Qp = seq + (long)n * LSEQ * DH;
    const float* Kp = g_KC + ((long)h * NR + (long)n * RR) * DH;

    for (int kc = 0; kc < DH / 64; kc++) {
        const int k0 = kc * 64;
        for (int e = t; e < 128 * 64; e += 256)
            sQ[e >> 6][e & 63] = Qp[(long)(e >> 6) * DH + k0 + (e & 63)];
        for (int e = t; e < 49 * 64; e += 256)
            sK[e / 64][e % 64] = Kp[(long)(e / 64) * DH + k0 + (e % 64)];
        __syncthreads();
        if (rg < 7) {
            for (int kk = 0; kk < 64; kk++) {
                float kv[7];
#pragma unroll
                for (int i = 0; i < 7; i++) kv[i] = sK[rg * 7 + i][kk];
#pragma unroll
                for (int qi = 0; qi < 4; qi++) {
                    float qv = sQ[qg + 32 * qi][kk];
#pragma unroll
                    for (int i = 0; i < 7; i++) acc[qi][i] += qv * kv[i];
                }
            }
        }
        __syncthreads();
    }

    const float scale = 1.0f / sqrtf((float)DH);
    if (rg < 7) {
#pragma unroll
        for (int qi = 0; qi < 4; qi++)
#pragma unroll
            for (int i = 0; i < 7; i++)
                sS[(qg + 32 * qi) * 49 + rg * 7 + i] = acc[qi][i] * scale;
    }
    __syncthreads();

    if (t < 128) {
        float* row = sS + t * 49;
        float mx = row[0];
        for (int r = 1; r < RR; r++) mx = fmaxf(mx, row[r]);
        float sum = 0.f;
        float ex[49];
        for (int r = 0; r < RR; r++) { ex[r] = expf(row[r] - mx); sum += ex[r]; }
        float inv = 1.f / sum;
        float* out = g_P + (((long)(n * HH + h)) * LSEQ + t) * RR;
        for (int r = 0; r < RR; r++) out[r] = ex[r] * inv;
    }
}

// ---------------- out = LN(sum_h P_h @ VC_h + seq) -> cat[:, 768:1536] hi/lo ----------------
#define AOL_SMEM ((8 * 16 * 49 + 16 * 768) * 4)
__global__ __launch_bounds__(256) void att_out_ln_u(const float* __restrict__ seq,
                                                    const float* __restrict__ gam,
                                                    const float* __restrict__ bet)
{
    extern __shared__ float ds[];
    float* sP = ds;
    float* sX = ds + 8 * 16 * 49;
    const int qg = blockIdx.x, n = blockIdx.y;
    const int t = threadIdx.x;

    for (int e = t; e < 8 * 16 * 49; e += 256) {
        int h = e / (16 * 49), rem = e % (16 * 49);
        int q = rem / 49, r = rem % 49;
        sP[e] = g_P[(((long)(n * HH + h)) * LSEQ + qg * 16 + q) * RR + r];
    }
    __syncthreads();

    float acc[16][3];
#pragma unroll
    for (int q = 0; q < 16; q++) { acc[q][0] = 0.f; acc[q][1] = 0.f; acc[q][2] = 0.f; }

    for (int h = 0; h < HH; h++) {
        const float* Vb = g_VC + ((long)h * NR + (long)n * RR) * DH;
        const float* Ph = sP + h * 16 * 49;
        for (int r = 0; r < RR; r++) {
            float v0 = Vb[(long)r * DH + t];
            float v1 = Vb[(long)r * DH + 256 + t];
            float v2 = Vb[(long)r * DH + 512 + t];
            const float* Pr = Ph + r;
#pragma unroll
            for (int q = 0; q < 16; q++) {
                float p = Pr[q * 49];
                acc[q][0] += p * v0; acc[q][1] += p * v1; acc[q][2] += p * v2;
            }
        }
    }

#pragma unroll
    for (int q = 0; q < 16; q++) {
        long srow = ((long)n * LSEQ + qg * 16 + q) * DH;
        sX[q * 768 + t]       = acc[q][0] + seq[srow + t];
        sX[q * 768 + 256 + t] = acc[q][1] + seq[srow + 256 + t];
        sX[q * 768 + 512 + t] = acc[q][2] + seq[srow + 512 + t];
    }
    __syncthreads();

    const int wid = t >> 5, lane = t & 31;
    for (int qq = wid * 2; qq < wid * 2 + 2; qq++) {
        float* row = sX + qq * 768;
        float s = 0.f;
        for (int k = lane; k < DH; k += 32) s += row[k];
        for (int o = 16; o; o >>= 1) s += __shfl_xor_sync(0xffffffffu, s, o);
        float mu = s * (1.f / DH);
        float v = 0.f;
        for (int k = lane; k < DH; k += 32) { float d = row[k] - mu; v += d * d; }
        for (int o = 16; o; o >>= 1) v += __shfl_xor_sync(0xffffffffu, v, o);
        float rstd = rsqrtf(v * (1.f / DH) + 1e-5f);
        long orow = ((long)n * LSEQ + qg * 16 + qq) * 2 * DH + DH;
        for (int k = lane * 2; k < DH; k += 64) {
            float a = (row[k]     - mu) * rstd * gam[k]     + bet[k];
            float b = (row[k + 1] - mu) * rstd * gam[k + 1] + bet[k + 1];
            __nv_bfloat162 h = __floats2bfloat162_rn(a, b);
            __nv_bfloat162 l = __floats2bfloat162_rn(a - __bfloat162float(h.x),
                                                     b - __bfloat162float(h.y));
            *reinterpret_cast<uint32_t*>(g_cat_hi + orow + k) = reinterpret_cast<uint32_t&>(h);
            *reinterpret_cast<uint32_t*>(g_cat_lo + orow + k) = reinterpret_cast<uint32_t&>(l);
        }
    }
}

// ---------------- unary score + masked softmax pooling (token-indexed) ----------------
__global__ void pool_kernel(const float* __restrict__ W_un, const float* __restrict__ b_un,
                            const int* __restrict__ starts, const int* __restrict__ ends)
{
    int sp = blockIdx.x, t = threadIdx.x;
    int lane = t & 31, w = t >> 5;
    int n = sp >> 3;
    int base = n * LSEQ + starts[sp];
    __shared__ float sS[JR];
    __shared__ float sProb[JR];

    for (int j = w; j < JR; j += 8) {
        int u = base + j; if (u > UU - 1) u = UU - 1;
        const float* fr = g_fused + (long)u * DH;
        float acc = 0.f;
        for (int k = lane; k < DH; k += 32) acc += fr[k] * W_un[k];
        for (int o = 16; o; o >>= 1) acc += __shfl_xor_sync(0xffffffffu, acc, o);
        if (lane == 0) sS[j] = acc + b_un[0];
    }
    __syncthreads();
    if (t == 0) {
        int width = ends[sp] - starts[sp] + 1;
        float mx = -1e30f;
        for (int j = 0; j < JR; j++) {
            float v = sS[j] + ((j < width) ? 0.f : -10000.f);
            sS[j] = v; mx = fmaxf(mx, v);
        }
        float sum = 0.f;
        for (int j = 0; j < JR; j++) { float e = expf(sS[j] - mx); sProb[j] = e; sum += e; }
        float inv = 1.f / sum;
        for (int j = 0; j < JR; j++) sProb[j] *= inv;
    }
    __syncthreads();
    for (int d = t; d < DH; d += 256) {
        float acc = 0.f;
        for (int j = 0; j < JR; j++) {
            int u = base + j; if (u > UU - 1) u = UU - 1;
            acc += sProb[j] * g_fused[(long)u * DH + d];
        }
        g_pool[(long)sp * DH + d] = acc;
    }
}

// ---------------- small fp32 sgemm (tiny dense layer only) ----------------
template<bool TRANSB, bool BIAS, bool TANH_ACT>
__global__ void sgemm(const float* __restrict__ A, int lda, long sA,
                      const float* __restrict__ B, int ldb, long sB,
                      float* __restrict__ C, int ldc, long sC,
                      const float* __restrict__ bias,
                      int M, int N, int K)
{
    A += (long)blockIdx.z * sA;
    B += (long)blockIdx.z * sB;
    C += (long)blockIdx.z * sC;
    __shared__ float As[16][128];
    __shared__ float Bs[16][128];
    const int tid = threadIdx.x;
    const int m0 = blockIdx.y * 128;
    const int n0 = blockIdx.x * 128;
    const int tx = tid & 15;
    const int ty = tid >> 4;
    float acc[8][8];
#pragma unroll
    for (int i = 0; i < 8; i++)
#pragma unroll
        for (int j = 0; j < 8; j++) acc[i][j] = 0.f;

    for (int k0 = 0; k0 < K; k0 += 16) {
#pragma unroll
        for (int i = 0; i < 2; i++) {
            int li = tid + i * 256;
            int row = li >> 2;
            int kk  = (li & 3) << 2;
            float4 v = make_float4(0.f, 0.f, 0.f, 0.f);
            if (m0 + row < M)
                v = *reinterpret_cast<const float4*>(&A[(long)(m0 + row) * lda + k0 + kk]);
            As[kk + 0][row] = v.x; As[kk + 1][row] = v.y;
            As[kk + 2][row] = v.z; As[kk + 3][row] = v.w;
        }
        if (!TRANSB) {
#pragma unroll
            for (int i = 0; i < 2; i++) {
                int li = tid + i * 256;
                int kr = li >> 5;
                int nn = (li & 31) << 2;
                float4 v = *reinterpret_cast<const float4*>(&B[(long)(k0 + kr) * ldb + n0 + nn]);
                *reinterpret_cast<float4*>(&Bs[kr][nn]) = v;
            }
        } else {
#pragma unroll
            for (int i = 0; i < 2; i++) {
                int li = tid + i * 256;
                int nr = li >> 2;
                int kk = (li & 3) << 2;
                float4 v = make_float4(0.f, 0.f, 0.f, 0.f);
                if (n0 + nr < N)
                    v = *reinterpret_cast<const float4*>(&B[(long)(n0 + nr) * ldb + k0 + kk]);
                Bs[kk + 0][nr] = v.x; Bs[kk + 1][nr] = v.y;
                Bs[kk + 2][nr] = v.z; Bs[kk + 3][nr] = v.w;
            }
        }
        __syncthreads();
#pragma unroll
        for (int k = 0; k < 16; k++) {
            float a[8], b[8];
#pragma unroll
            for (int i = 0; i < 8; i++) a[i] = As[k][ty * 8 + i];
#pragma unroll
            for (int j = 0; j < 8; j++) b[j] = Bs[k][tx * 8 + j];
#pragma unroll
            for (int i = 0; i < 8; i++)
#pragma unroll
                for (int j = 0; j < 8; j++) acc[i][j] += a[i] * b[j];
        }
        __syncthreads();
    }
#pragma unroll
    for (int i = 0; i < 8; i++) {
        int m = m0 + ty * 8 + i;
        if (m >= M) continue;
#pragma unroll
        for (int j = 0; j < 8; j++) {
            int n = n0 + tx * 8 + j;
            float v = acc[i][j];
            if (BIAS) v += bias[n];
            if (TANH_ACT) v = tanhf(v);
            C[(long)m * ldc + n] = v;
        }
    }
}

// ---------------- classifier ----------------
__global__ void cls_kernel(const float* __restrict__ W_cls, const float* __restrict__ b_cls,
                           float* __restrict__ out)
{
    int row = blockIdx.x, t = threadIdx.x;
    int lane = t & 31, c = t >> 5;
    const float* hr = g_hid + (long)row * DH;
    float acc = 0.f;
    for (int k = lane; k < DH; k += 32) acc += hr[k] * W_cls[k * 4 + c];
    for (int o = 16; o; o >>= 1) acc += __shfl_xor_sync(0xffffffffu, acc, o);
    if (lane == 0) out[row * 4 + c] = acc + b_cls[c];
}

// ---------------- launcher ----------------
extern "C" void kernel_launch(void* const* d_in, const int* in_sizes, int n_in,
                              void* d_out, int out_size)
{
    const float* enc_img  = (const float*)d_in[0];
    const float* seq      = (const float*)d_in[1];
    const int*   starts   = (const int*)d_in[3];
    const int*   ends     = (const int*)d_in[4];
    const float* W_align  = (const float*)d_in[5];
    const float* b_align  = (const float*)d_in[6];
    const float* Wq       = (const float*)d_in[7];
    const float* Wk       = (const float*)d_in[8];
    const float* Wv       = (const float*)d_in[9];
    const float* Wfc      = (const float*)d_in[10];
    const float* ln_g     = (const float*)d_in[11];
    const float* ln_b     = (const float*)d_in[12];
    const float* W_a1     = (const float*)d_in[13];
    const float* b_a1     = (const float*)d_in[14];
    const float* W_a2     = (const float*)d_in[15];
    const float* b_a2     = (const float*)d_in[16];
    const float* W_un     = (const float*)d_in[17];
    const float* b_un     = (const float*)d_in[18];
    const float* W_dense  = (const float*)d_in[19];
    const float* b_dense  = (const float*)d_in[20];
    const float* W_cls    = (const float*)d_in[21];
    const float* b_cls    = (const float*)d_in[22];

    bf16 *eh, *el, *wath, *watl, *wqh, *wql, *wkh, *wkl, *wvh, *wvl, *wfh, *wfl;
    bf16 *c1h, *c1l, *bqh, *bql, *wvfh, *wvfl;
    bf16 *cth, *ctl, *wa1h, *wa1l, *f1h, *f1l, *wa2h, *wa2l;
    float *pKC, *pVC, *pFused, *pPool, *pHid;
    cudaGetSymbolAddress((void**)&eh,   g_enc_hi);  cudaGetSymbolAddress((void**)&el,   g_enc_lo);
    cudaGetSymbolAddress((void**)&wath, g_WalT_hi); cudaGetSymbolAddress((void**)&watl, g_WalT_lo);
    cudaGetSymbolAddress((void**)&wqh,  g_Wq_hi);   cudaGetSymbolAddress((void**)&wql,  g_Wq_lo);
    cudaGetSymbolAddress((void**)&wkh,  g_Wk_hi);   cudaGetSymbolAddress((void**)&wkl,  g_Wk_lo);
    cudaGetSymbolAddress((void**)&wvh,  g_Wv_hi);   cudaGetSymbolAddress((void**)&wvl,  g_Wv_lo);
    cudaGetSymbolAddress((void**)&wfh,  g_WfcT_hi); cudaGetSymbolAddress((void**)&wfl,  g_WfcT_lo);
    cudaGetSymbolAddress((void**)&c1h,  g_C1_hi);   cudaGetSymbolAddress((void**)&c1l,  g_C1_lo);
    cudaGetSymbolAddress((void**)&bqh,  g_Bqk_hi);  cudaGetSymbolAddress((void**)&bql,  g_Bqk_lo);
    cudaGetSymbolAddress((void**)&wvfh, g_WvfT_hi); cudaGetSymbolAddress((void**)&wvfl, g_WvfT_lo);
    cudaGetSymbolAddress((void**)&cth,  g_cat_hi);  cudaGetSymbolAddress((void**)&ctl,  g_cat_lo);
    cudaGetSymbolAddress((void**)&wa1h, g_Wa1T_hi); cudaGetSymbolAddress((void**)&wa1l, g_Wa1T_lo);
    cudaGetSymbolAddress((void**)&f1h,  g_f1_hi);   cudaGetSymbolAddress((void**)&f1l,  g_f1_lo);
    cudaGetSymbolAddress((void**)&wa2h, g_Wa2T_hi); cudaGetSymbolAddress((void**)&wa2l, g_Wa2T_lo);
    cudaGetSymbolAddress((void**)&pKC, g_KC);       cudaGetSymbolAddress((void**)&pVC, g_VC);
    cudaGetSymbolAddress((void**)&pFused, g_fused);
    cudaGetSymbolAddress((void**)&pPool, g_pool);   cudaGetSymbolAddress((void**)&pHid, g_hid);

    cudaFuncSetAttribute(mmgemm<true,  true,  false>, cudaFuncAttributeMaxDynamicSharedMemorySize, MM_SMEM);
    cudaFuncSetAttribute(mmgemm<true,  true,  true >, cudaFuncAttributeMaxDynamicSharedMemorySize, MM_SMEM);
    cudaFuncSetAttribute(mmgemm<false, true,  false>, cudaFuncAttributeMaxDynamicSharedMemorySize, MM_SMEM);
    cudaFuncSetAttribute(mmgemm_dual<true >, cudaFuncAttributeMaxDynamicSharedMemorySize, MM_SMEM);
    cudaFuncSetAttribute(mmgemm_dual<false>, cudaFuncAttributeMaxDynamicSharedMemorySize, MM_SMEM);
    cudaFuncSetAttribute(att_out_ln_u, cudaFuncAttributeMaxDynamicSharedMemorySize, AOL_SMEM);

    const dim3 blk(128);
    const long HD2 = (long)DH * DH;
    const long NRD = (long)NR * DH;

    // ---- operand conversions ----
    split_kernel<<<1024, 256>>>(enc_img, eh, el, (long)NR * IMGD);
    splitT_kernel<<<dim3(DH / 32, IMGD / 32), dim3(32, 8)>>>(W_align, wath, watl, IMGD, DH);
    split_kernel<<<1024, 256>>>(Wq, wqh, wql, (long)DH * HH * DH);
    split_kernel<<<1024, 256>>>(Wk, wkh, wkl, (long)DH * HH * DH);
    split_kernel<<<1024, 256>>>(Wv, wvh, wvl, (long)DH * HH * DH);
    splitT_kernel<<<dim3(DH / 32, (HH * DH) / 32), dim3(32, 8)>>>(Wfc, wfh, wfl, HH * DH, DH);
    splitT_kernel<<<dim3((2*DH) / 32, (2*DH) / 32), dim3(32, 8)>>>(W_a1, wa1h, wa1l, 2*DH, 2*DH);
    splitT_kernel<<<dim3(DH / 32, (2*DH) / 32), dim3(32, 8)>>>(W_a2, wa2h, wa2l, 2*DH, DH);
    seq_split_kernel<<<UU, 256>>>(seq);

    // ---- G1: C1 = enc_img @ W_align + b_align -> bf16 hi/lo [784,768] ----
    mmgemm<true, true, false><<<dim3(6, 7, 1), blk, MM_SMEM>>>(
        eh, el, IMGD, 0, wath, watl, IMGD, 0,
        nullptr, c1h, c1l, DH, 0, b_align, NR, DH, IMGD);

    // ---- G2+G3 fused: Bqk_h = Wq_h @ Wk_h^T ; WvfT_h = (Wv_h @ Wfc_h)^T ----
    mmgemm_dual<true><<<dim3(6, 6, 16), blk, MM_SMEM>>>(
        wqh, wql, HH * DH, DH,  wkh, wkl, HH * DH, DH,  nullptr, bqh, bql, DH, HD2,
        wfh, wfl, HH * DH, DH,  wvh, wvl, HH * DH, DH,  nullptr, wvfh, wvfl, DH, HD2,
        HH, DH, DH, DH);

    // ---- G4+G5 fused: KC_h = C1 @ Bqk_h^T ; VC_h = C1 @ WvfT_h^T ----
    mmgemm_dual<false><<<dim3(6, 7, 16), blk, MM_SMEM>>>(
        c1h, c1l, DH, 0,  bqh, bql, DH, HD2,  pKC, nullptr, nullptr, DH, NRD,
        c1h, c1l, DH, 0,  wvfh, wvfl, DH, HD2,  pVC, nullptr, nullptr, DH, NRD,
        HH, NR, DH, DH);

    // ---- attention on 2048 distinct tokens ----
    att_scores_u<<<dim3(HH, NB), 256>>>(seq);
    att_out_ln_u<<<dim3(8, NB), 256, AOL_SMEM>>>(seq, ln_g, ln_b);

    // ---- fusion MLP on 2048 tokens ----
    mmgemm<true, true, true><<<dim3(12, 16, 1), blk, MM_SMEM>>>(
        cth, ctl, 2 * DH, 0, wa1h, wa1l, 2 * DH, 0,
        nullptr, f1h, f1l, 2 * DH, 0, b_a1, UU, 2 * DH, 2 * DH);
    mmgemm<false, true, false><<<dim3(6, 16, 1), blk, MM_SMEM>>>(
        f1h, f1l, 2 * DH, 0, wa2h, wa2l, 2 * DH, 0,
        pFused, nullptr, nullptr, DH, 0, b_a2, UU, DH, 2 * DH);

    // ---- pooling + head ----
    pool_kernel<<<NM, 256>>>(W_un, b_un, starts, ends);
    sgemm<false, true, true><<<dim3(6, 1, 1), dim3(256)>>>(
        pPool, DH, 0, W_dense, DH, 0, pHid, DH, 0, b_dense, NM, DH, DH);
    cls_kernel<<<NM, 128>>>(W_cls, b_cls, (float*)d_out);
}

// round 8
// speedup vs baseline: 1.9351x; 1.0644x over previous
#include <cuda_runtime.h>
#include <cuda_bf16.h>
#include <math.h>
#include <stdint.h>

// ---------------- problem constants ----------------
#define NB    16
#define LSEQ  128
#define DH    768
#define MSP   8
#define HH    8
#define JR    30
#define RR    49
#define IMGD  2048
#define NM    128            // NB*MSP
#define UU    2048           // NB*LSEQ distinct tokens
#define NR    784            // NB*RR

typedef __nv_bfloat16 bf16;

// ---------------- scratch (device globals; no cudaMalloc allowed) ----------------
__device__ bf16 g_enc_hi[NR * IMGD],        g_enc_lo[NR * IMGD];
__device__ bf16 g_WalT_hi[DH * IMGD],       g_WalT_lo[DH * IMGD];
__device__ bf16 g_Wq_hi[DH * HH * DH],      g_Wq_lo[DH * HH * DH];
__device__ bf16 g_Wk_hi[DH * HH * DH],      g_Wk_lo[DH * HH * DH];
__device__ bf16 g_Wv_hi[DH * HH * DH],      g_Wv_lo[DH * HH * DH];
__device__ bf16 g_WfcT_hi[DH * HH * DH],    g_WfcT_lo[DH * HH * DH];
__device__ bf16 g_C1_hi[NR * DH],           g_C1_lo[NR * DH];
__device__ bf16 g_Bqk_hi[HH * DH * DH],     g_Bqk_lo[HH * DH * DH];
__device__ bf16 g_WvfT_hi[HH * DH * DH],    g_WvfT_lo[HH * DH * DH];
__device__ float g_KC[HH * NR * DH];
__device__ float g_VC[HH * NR * DH];
__device__ float g_P[NB * HH * LSEQ * RR];
__device__ bf16 g_cat_hi[UU * 2 * DH],      g_cat_lo[UU * 2 * DH];
__device__ bf16 g_Wa1T_hi[2*DH * 2*DH],     g_Wa1T_lo[2*DH * 2*DH];
__device__ bf16 g_f1_hi[UU * 2 * DH],       g_f1_lo[UU * 2 * DH];
__device__ bf16 g_Wa2T_hi[DH * 2*DH],       g_Wa2T_lo[DH * 2*DH];
__device__ float g_fused[UU * DH];
__device__ float g_pool[NM * DH];
__device__ float g_hid[NM * DH];

// ---------------- helpers ----------------
__device__ __forceinline__ uint32_t smem_u32(const void* p) {
    uint32_t a;
    asm("{ .reg .u64 t; cvta.to.shared.u64 t, %1; cvt.u32.u64 %0, t; }" : "=r"(a) : "l"(p));
    return a;
}

__device__ __forceinline__ void ldm_x4(uint32_t* r, uint32_t addr) {
    asm volatile("ldmatrix.sync.aligned.m8n8.x4.shared.b16 {%0,%1,%2,%3}, [%4];"
                 : "=r"(r[0]), "=r"(r[1]), "=r"(r[2]), "=r"(r[3]) : "r"(addr));
}

__device__ __forceinline__ void mma16816(float* c, const uint32_t* a, uint32_t b0, uint32_t b1) {
    asm volatile(
        "mma.sync.aligned.m16n8k16.row.col.f32.bf16.bf16.f32 "
        "{%0,%1,%2,%3}, {%4,%5,%6,%7}, {%8,%9}, {%0,%1,%2,%3};"
        : "+f"(c[0]), "+f"(c[1]), "+f"(c[2]), "+f"(c[3])
        : "r"(a[0]), "r"(a[1]), "r"(a[2]), "r"(a[3]), "r"(b0), "r"(b1));
}

__device__ __forceinline__ void cpa16(uint32_t dst, const void* src) {
    asm volatile("cp.async.ca.shared.global [%0], [%1], 16;" :: "r"(dst), "l"(src));
}
__device__ __forceinline__ void cpa_commit() {
    asm volatile("cp.async.commit_group;" ::: "memory");
}
template<int N_>
__device__ __forceinline__ void cpa_wait() {
    asm volatile("cp.async.wait_group %0;" :: "n"(N_) : "memory");
}

// ---------------- split-bf16 tensor-core GEMM core v2 ----------------
// Block 128x128, BK=32, 4 warps (2x2), warp tile 64x64.
// 3-stage cp.async pipeline, XOR-swizzled smem (no padding), ONE sync per chunk.
// Swizzle: 16B-slot position = g ^ ((row>>1)&3), rows are 64B (32 bf16).
#define BM 128
#define BN 128
#define BK 32
#define T_AL 8192
#define T_BH 16384
#define T_BL 24576
#define STAGE_B 32768
#define MM_SMEM (3 * STAGE_B)                 // 98304

template<bool OUT_BF16, bool TANH_ACT>
__device__ __forceinline__ void mm_body(
    const bf16* __restrict__ Ahi, const bf16* __restrict__ Alo, int lda,
    const bf16* __restrict__ Bhi, const bf16* __restrict__ Blo, int ldb,
    float* __restrict__ Cf, bf16* __restrict__ Chi, bf16* __restrict__ Clo, int ldc,
    const float* __restrict__ bias, int M, int N, int K)
{
    extern __shared__ char dsm[];
    const uint32_t u_sm = smem_u32(dsm);

    const int tid = threadIdx.x, lane = tid & 31, wid = tid >> 5;
    const int wr = wid >> 1, wc = wid & 1;
    const int m0 = blockIdx.y * BM, n0 = blockIdx.x * BN;

    float acc[4][8][4];
#pragma unroll
    for (int i = 0; i < 4; i++)
#pragma unroll
        for (int j = 0; j < 8; j++)
#pragma unroll
            for (int e = 0; e < 4; e++) acc[i][j][e] = 0.f;

    const int lrow = lane & 15;
    const int khalf = lane >> 4;
    const int p = (lrow >> 1) & 3;
    const uint32_t sw0 = (uint32_t)((khalf ^ p) << 4);
    const uint32_t sw1 = (uint32_t)(((2 | khalf) ^ p) << 4);
    const uint32_t rA = (uint32_t)((wr * 64 + lrow) * 64);
    const uint32_t rB = (uint32_t)((wc * 64 + lrow) * 64);

    auto load_stage = [&](int st, int k0) {
        const uint32_t sbase = u_sm + (uint32_t)(st * STAGE_B);
#pragma unroll
        for (int i = 0; i < 16; i++) {
            int u = tid + i * 128;
            int r = (u & 511) >> 2;
            int g = u & 3;
            int sg = g << 3;
            const bf16* src;
            uint32_t toff;
            if (u < 512)       { int ga = m0 + r; if (ga > M - 1) ga = M - 1;
                                 src = Ahi + (long)ga * lda + k0 + sg; toff = 0; }
            else if (u < 1024) { int ga = m0 + r; if (ga > M - 1) ga = M - 1;
                                 src = Alo + (long)ga * lda + k0 + sg; toff = T_AL; }
            else if (u < 1536) { int gb = n0 + r; if (gb > N - 1) gb = N - 1;
                                 src = Bhi + (long)gb * ldb + k0 + sg; toff = T_BH; }
            else               { int gb = n0 + r; if (gb > N - 1) gb = N - 1;
                                 src = Blo + (long)gb * ldb + k0 + sg; toff = T_BL; }
            uint32_t doff = toff + (uint32_t)(r * 64) + (uint32_t)(((g ^ ((r >> 1) & 3)) << 4));
            cpa16(sbase + doff, src);
        }
    };

    const int nch = K / BK;
    load_stage(0, 0);  cpa_commit();
    load_stage(1, BK); cpa_commit();

    int st = 0;                     // stage holding chunk ch
    for (int ch = 0; ch < nch; ch++) {
        if (ch == nch - 1) cpa_wait<0>(); else cpa_wait<1>();
        __syncthreads();
        if (ch + 2 < nch) {
            int st2 = st + 2; if (st2 >= 3) st2 -= 3;
            load_stage(st2, (ch + 2) * BK);
            cpa_commit();
        }

        const uint32_t so = u_sm + (uint32_t)(st * STAGE_B);
#pragma unroll
        for (int ks = 0; ks < 2; ks++) {
            const uint32_t sw = ks ? sw1 : sw0;
            uint32_t bh[4][4], bl[4][4];
#pragma unroll
            for (int nt = 0; nt < 4; nt++) {
                ldm_x4(bh[nt], so + T_BH + rB + (uint32_t)(nt * 1024) + sw);
                ldm_x4(bl[nt], so + T_BL + rB + (uint32_t)(nt * 1024) + sw);
            }
#pragma unroll
            for (int mi = 0; mi < 4; mi++) {
                uint32_t ah[4], al[4];
                ldm_x4(ah, so + rA + (uint32_t)(mi * 1024) + sw);
                ldm_x4(al, so + T_AL + rA + (uint32_t)(mi * 1024) + sw);
#pragma unroll
                for (int nt = 0; nt < 4; nt++) {
#pragma unroll
                    for (int j = 0; j < 2; j++) {
                        const int nj = nt * 2 + j;
                        mma16816(acc[mi][nj], ah, bh[nt][j], bh[nt][j + 2]);
                        mma16816(acc[mi][nj], ah, bl[nt][j], bl[nt][j + 2]);
                        mma16816(acc[mi][nj], al, bh[nt][j], bh[nt][j + 2]);
                    }
                }
            }
        }
        if (++st == 3) st = 0;
    }

    const int er = m0 + wr * 64 + (lane >> 2);
    const int ec = n0 + wc * 64 + (lane & 3) * 2;
#pragma unroll
    for (int mi = 0; mi < 4; mi++) {
#pragma unroll
        for (int nj = 0; nj < 8; nj++) {
            const int col = ec + nj * 8;
            float bv0 = 0.f, bv1 = 0.f;
            if (bias) { bv0 = bias[col]; bv1 = bias[col + 1]; }
#pragma unroll
            for (int half = 0; half < 2; half++) {
                const int row = er + mi * 16 + half * 8;
                if (row >= M) continue;
                float v0 = acc[mi][nj][half * 2 + 0] + bv0;
                float v1 = acc[mi][nj][half * 2 + 1] + bv1;
                if (TANH_ACT) { v0 = tanhf(v0); v1 = tanhf(v1); }
                const long base = (long)row * ldc + col;
                if (OUT_BF16) {
                    __nv_bfloat162 h = __floats2bfloat162_rn(v0, v1);
                    __nv_bfloat162 l = __floats2bfloat162_rn(
                        v0 - __bfloat162float(h.x), v1 - __bfloat162float(h.y));
                    *reinterpret_cast<uint32_t*>(Chi + base) = reinterpret_cast<uint32_t&>(h);
                    *reinterpret_cast<uint32_t*>(Clo + base) = reinterpret_cast<uint32_t&>(l);
                } else {
                    *reinterpret_cast<float2*>(Cf + base) = make_float2(v0, v1);
                }
            }
        }
    }
}

// generic batched wrapper
template<bool OUT_BF16, bool TANH_ACT>
__global__ __launch_bounds__(128, 2)
void mmgemm(const bf16* __restrict__ Ahi, const bf16* __restrict__ Alo, int lda, long sA,
            const bf16* __restrict__ Bhi, const bf16* __restrict__ Blo, int ldb, long sB,
            float* __restrict__ Cf, bf16* __restrict__ Chi, bf16* __restrict__ Clo,
            int ldc, long sC, const float* __restrict__ bias,
            int M, int N, int K)
{
    const long za = (long)blockIdx.z * sA, zb = (long)blockIdx.z * sB, zc = (long)blockIdx.z * sC;
    mm_body<OUT_BF16, TANH_ACT>(
        Ahi + za, Alo + za, lda, Bhi + zb, Blo + zb, ldb,
        Cf ? Cf + zc : nullptr, Chi ? Chi + zc : nullptr, Clo ? Clo + zc : nullptr,
        ldc, bias, M, N, K);
}

// fused G1 + G2 + G3 launch: z=0 -> G1; z=1..8 -> G2 head; z=9..16 -> G3 head
__global__ __launch_bounds__(128, 2)
void mm_g123(const bf16* __restrict__ eh,  const bf16* __restrict__ el,
             const bf16* __restrict__ wath, const bf16* __restrict__ watl,
             bf16* __restrict__ c1h, bf16* __restrict__ c1l, const float* __restrict__ b_align,
             const bf16* __restrict__ wqh, const bf16* __restrict__ wql,
             const bf16* __restrict__ wkh, const bf16* __restrict__ wkl,
             bf16* __restrict__ bqh, bf16* __restrict__ bql,
             const bf16* __restrict__ wfh, const bf16* __restrict__ wfl,
             const bf16* __restrict__ wvh, const bf16* __restrict__ wvl,
             bf16* __restrict__ wvfh, bf16* __restrict__ wvfl)
{
    int z = blockIdx.z;
    if (z == 0) {
        mm_body<true, false>(eh, el, IMGD, wath, watl, IMGD,
                             nullptr, c1h, c1l, DH, b_align, NR, DH, IMGD);
    } else {
        if (blockIdx.y * BM >= DH) return;       // M=768 uses y=0..5 only
        z -= 1;
        const int set = z >> 3, h = z & 7;
        const long co = (long)h * DH;
        const long cc = (long)h * DH * DH;
        if (set == 0) {
            mm_body<true, false>(wqh + co, wql + co, HH * DH, wkh + co, wkl + co, HH * DH,
                                 nullptr, bqh + cc, bql + cc, DH, nullptr, DH, DH, DH);
        } else {
            mm_body<true, false>(wfh + co, wfl + co, HH * DH, wvh + co, wvl + co, HH * DH,
                                 nullptr, wvfh + cc, wvfl + cc, DH, nullptr, DH, DH, DH);
        }
    }
}

// fused G4 + G5: z=0..7 -> KC head, z=8..15 -> VC head
__global__ __launch_bounds__(128, 2)
void mm_g45(const bf16* __restrict__ c1h, const bf16* __restrict__ c1l,
            const bf16* __restrict__ bqh, const bf16* __restrict__ bql,
            const bf16* __restrict__ wvfh, const bf16* __restrict__ wvfl,
            float* __restrict__ pKC, float* __restrict__ pVC)
{
    int z = blockIdx.z;
    const long NRD = (long)NR * DH;
    const long HD2 = (long)DH * DH;
    if (z < HH) {
        mm_body<false, false>(c1h, c1l, DH, bqh + (long)z * HD2, bql + (long)z * HD2, DH,
                              pKC + (long)z * NRD, nullptr, nullptr, DH, nullptr, NR, DH, DH);
    } else {
        z -= HH;
        mm_body<false, false>(c1h, c1l, DH, wvfh + (long)z * HD2, wvfl + (long)z * HD2, DH,
                              pVC + (long)z * NRD, nullptr, nullptr, DH, nullptr, NR, DH, DH);
    }
}

// ---------------- fp32 -> bf16 hi/lo split (vectorized) ----------------
__global__ void split_kernel(const float* __restrict__ in, bf16* __restrict__ hi,
                             bf16* __restrict__ lo, long n)
{
    long i0 = ((long)blockIdx.x * blockDim.x + threadIdx.x) * 4;
    long stride = (long)gridDim.x * blockDim.x * 4;
    for (long i = i0; i < n; i += stride) {
        float4 v = *reinterpret_cast<const float4*>(in + i);
        __nv_bfloat162 h0 = __floats2bfloat162_rn(v.x, v.y);
        __nv_bfloat162 h1 = __floats2bfloat162_rn(v.z, v.w);
        __nv_bfloat162 l0 = __floats2bfloat162_rn(v.x - __bfloat162float(h0.x),
                                                  v.y - __bfloat162float(h0.y));
        __nv_bfloat162 l1 = __floats2bfloat162_rn(v.z - __bfloat162float(h1.x),
                                                  v.w - __bfloat162float(h1.y));
        *reinterpret_cast<uint2*>(hi + i) =
            make_uint2(reinterpret_cast<uint32_t&>(h0), reinterpret_cast<uint32_t&>(h1));
        *reinterpret_cast<uint2*>(lo + i) =
            make_uint2(reinterpret_cast<uint32_t&>(l0), reinterpret_cast<uint32_t&>(l1));
    }
}

// ---------------- fp32 [R,C] -> transposed bf16 hi/lo [C,R] (packed stores) ----------------
__global__ void splitT_kernel(const float* __restrict__ in, bf16* __restrict__ hi,
                              bf16* __restrict__ lo, int R, int C)
{
    __shared__ float t[32][33];
    int c0 = blockIdx.x * 32, r0 = blockIdx.y * 32;
    for (int i = threadIdx.y; i < 32; i += 8)
        t[i][threadIdx.x] = in[(long)(r0 + i) * C + c0 + threadIdx.x];
    __syncthreads();
    if (threadIdx.x < 16) {
        for (int i = threadIdx.y; i < 32; i += 8) {
            float va = t[2 * threadIdx.x][i];
            float vb = t[2 * threadIdx.x + 1][i];
            __nv_bfloat162 h = __floats2bfloat162_rn(va, vb);
            __nv_bfloat162 l = __floats2bfloat162_rn(va - __bfloat162float(h.x),
                                                     vb - __bfloat162float(h.y));
            long o = (long)(c0 + i) * R + r0 + 2 * threadIdx.x;
            *reinterpret_cast<uint32_t*>(hi + o) = reinterpret_cast<uint32_t&>(h);
            *reinterpret_cast<uint32_t*>(lo + o) = reinterpret_cast<uint32_t&>(l);
        }
    }
}

// ---------------- seq -> cat[:, 0:768] hi/lo (vectorized) ----------------
__global__ void seq_split_kernel(const float* __restrict__ seq)
{
    int row = blockIdx.x, t = threadIdx.x;
    for (int idx = t * 4; idx < DH; idx += 256 * 4) {
        float4 v = *reinterpret_cast<const float4*>(seq + (long)row * DH + idx);
        __nv_bfloat162 h0 = __floats2bfloat162_rn(v.x, v.y);
        __nv_bfloat162 h1 = __floats2bfloat162_rn(v.z, v.w);
        __nv_bfloat162 l0 = __floats2bfloat162_rn(v.x - __bfloat162float(h0.x),
                                                  v.y - __bfloat162float(h0.y));
        __nv_bfloat162 l1 = __floats2bfloat162_rn(v.z - __bfloat162float(h1.x),
                                                  v.w - __bfloat162float(h1.y));
        long o = (long)row * 2 * DH + idx;
        *reinterpret_cast<uint2*>(g_cat_hi + o) =
            make_uint2(reinterpret_cast<uint32_t&>(h0), reinterpret_cast<uint32_t&>(h1));
        *reinterpret_cast<uint2*>(g_cat_lo + o) =
            make_uint2(reinterpret_cast<uint32_t&>(l0), reinterpret_cast<uint32_t&>(l1));
    }
}

// ---------------- attention scores + softmax per token (dedup) ----------------
__global__ __launch_bounds__(256) void att_scores_u(const float* __restrict__ seq)
{
    const int h = blockIdx.x, n = blockIdx.y;
    __shared__ float buf[128 * 65 + 49 * 65];
    float (*sQ)[65] = reinterpret_cast<float(*)[65]>(buf);
    float (*sK)[65] = reinterpret_cast<float(*)[65]>(buf + 128 * 65);
    float* sS = buf;
    const int t = threadIdx.x;
    const int qg = t & 31, rg = t >> 5;

    float acc[4][7];
#pragma unroll
    for (int a = 0; a < 4; a++)
#pragma unroll
        for (int b = 0; b < 7; b++) acc[a][b] = 0.f;

    const float* Qp = seq + (long)n * LSEQ * DH;
    const float* Kp = g_KC + ((long)h * NR + (long)n * RR) * DH;

    for (int kc = 0; kc < DH / 64; kc++) {
        const int k0 = kc * 64;
        for (int e = t; e < 128 * 64; e += 256)
            sQ[e >> 6][e & 63] = Qp[(long)(e >> 6) * DH + k0 + (e & 63)];
        for (int e = t; e < 49 * 64; e += 256)
            sK[e / 64][e % 64] = Kp[(long)(e / 64) * DH + k0 + (e % 64)];
        __syncthreads();
        if (rg < 7) {
            for (int kk = 0; kk < 64; kk++) {
                float kv[7];
#pragma unroll
                for (int i = 0; i < 7; i++) kv[i] = sK[rg * 7 + i][kk];
#pragma unroll
                for (int qi = 0; qi < 4; qi++) {
                    float qv = sQ[qg + 32 * qi][kk];
#pragma unroll
                    for (int i = 0; i < 7; i++) acc[qi][i] += qv * kv[i];
                }
            }
        }
        __syncthreads();
    }

    const float scale = 1.0f / sqrtf((float)DH);
    if (rg < 7) {
#pragma unroll
        for (int qi = 0; qi < 4; qi++)
#pragma unroll
            for (int i = 0; i < 7; i++)
                sS[(qg + 32 * qi) * 49 + rg * 7 + i] = acc[qi][i] * scale;
    }
    __syncthreads();

    if (t < 128) {
        float* row = sS + t * 49;
        float mx = row[0];
        for (int r = 1; r < RR; r++) mx = fmaxf(mx, row[r]);
        float sum = 0.f;
        float ex[49];
        for (int r = 0; r < RR; r++) { ex[r] = expf(row[r] - mx); sum += ex[r]; }
        float inv = 1.f / sum;
        float* out = g_P + (((long)(n * HH + h)) * LSEQ + t) * RR;
        for (int r = 0; r < RR; r++) out[r] = ex[r] * inv;
    }
}

// ---------------- out = LN(sum_h P_h @ VC_h + seq) -> cat[:, 768:1536] hi/lo ----------------
#define AOL_SMEM ((8 * 16 * 49 + 16 * 768) * 4)
__global__ __launch_bounds__(256) void att_out_ln_u(const float* __restrict__ seq,
                                                    const float* __restrict__ gam,
                                                    const float* __restrict__ bet)
{
    extern __shared__ float ds[];
    float* sP = ds;
    float* sX = ds + 8 * 16 * 49;
    const int qg = blockIdx.x, n = blockIdx.y;
    const int t = threadIdx.x;

    for (int e = t; e < 8 * 16 * 49; e += 256) {
        int h = e / (16 * 49), rem = e % (16 * 49);
        int q = rem / 49, r = rem % 49;
        sP[e] = g_P[(((long)(n * HH + h)) * LSEQ + qg * 16 + q) * RR + r];
    }
    __syncthreads();

    float acc[16][3];
#pragma unroll
    for (int q = 0; q < 16; q++) { acc[q][0] = 0.f; acc[q][1] = 0.f; acc[q][2] = 0.f; }

    for (int h = 0; h < HH; h++) {
        const float* Vb = g_VC + ((long)h * NR + (long)n * RR) * DH;
        const float* Ph = sP + h * 16 * 49;
        for (int r = 0; r < RR; r++) {
            float v0 = Vb[(long)r * DH + t];
            float v1 = Vb[(long)r * DH + 256 + t];
            float v2 = Vb[(long)r * DH + 512 + t];
            const float* Pr = Ph + r;
#pragma unroll
            for (int q = 0; q < 16; q++) {
                float p = Pr[q * 49];
                acc[q][0] += p * v0; acc[q][1] += p * v1; acc[q][2] += p * v2;
            }
        }
    }

#pragma unroll
    for (int q = 0; q < 16; q++) {
        long srow = ((long)n * LSEQ + qg * 16 + q) * DH;
        sX[q * 768 + t]       = acc[q][0] + seq[srow + t];
        sX[q * 768 + 256 + t] = acc[q][1] + seq[srow + 256 + t];
        sX[q * 768 + 512 + t] = acc[q][2] + seq[srow + 512 + t];
    }
    __syncthreads();

    const int wid = t >> 5, lane = t & 31;
    for (int qq = wid * 2; qq < wid * 2 + 2; qq++) {
        float* row = sX + qq * 768;
        float s = 0.f;
        for (int k = lane; k < DH; k += 32) s += row[k];
        for (int o = 16; o; o >>= 1) s += __shfl_xor_sync(0xffffffffu, s, o);
        float mu = s * (1.f / DH);
        float v = 0.f;
        for (int k = lane; k < DH; k += 32) { float d = row[k] - mu; v += d * d; }
        for (int o = 16; o; o >>= 1) v += __shfl_xor_sync(0xffffffffu, v, o);
        float rstd = rsqrtf(v * (1.f / DH) + 1e-5f);
        long orow = ((long)n * LSEQ + qg * 16 + qq) * 2 * DH + DH;
        for (int k = lane * 2; k < DH; k += 64) {
            float a = (row[k]     - mu) * rstd * gam[k]     + bet[k];
            float b = (row[k + 1] - mu) * rstd * gam[k + 1] + bet[k + 1];
            __nv_bfloat162 h = __floats2bfloat162_rn(a, b);
            __nv_bfloat162 l = __floats2bfloat162_rn(a - __bfloat162float(h.x),
                                                     b - __bfloat162float(h.y));
            *reinterpret_cast<uint32_t*>(g_cat_hi + orow + k) = reinterpret_cast<uint32_t&>(h);
            *reinterpret_cast<uint32_t*>(g_cat_lo + orow + k) = reinterpret_cast<uint32_t&>(l);
        }
    }
}

// ---------------- unary score + masked softmax pooling (token-indexed) ----------------
__global__ void pool_kernel(const float* __restrict__ W_un, const float* __restrict__ b_un,
                            const int* __restrict__ starts, const int* __restrict__ ends)
{
    int sp = blockIdx.x, t = threadIdx.x;
    int lane = t & 31, w = t >> 5;
    int n = sp >> 3;
    int base = n * LSEQ + starts[sp];
    __shared__ float sS[JR];
    __shared__ float sProb[JR];

    for (int j = w; j < JR; j += 8) {
        int u = base + j; if (u > UU - 1) u = UU - 1;
        const float* fr = g_fused + (long)u * DH;
        float acc = 0.f;
        for (int k = lane; k < DH; k += 32) acc += fr[k] * W_un[k];
        for (int o = 16; o; o >>= 1) acc += __shfl_xor_sync(0xffffffffu, acc, o);
        if (lane == 0) sS[j] = acc + b_un[0];
    }
    __syncthreads();
    if (t == 0) {
        int width = ends[sp] - starts[sp] + 1;
        float mx = -1e30f;
        for (int j = 0; j < JR; j++) {
            float v = sS[j] + ((j < width) ? 0.f : -10000.f);
            sS[j] = v; mx = fmaxf(mx, v);
        }
        float sum = 0.f;
        for (int j = 0; j < JR; j++) { float e = expf(sS[j] - mx); sProb[j] = e; sum += e; }
        float inv = 1.f / sum;
        for (int j = 0; j < JR; j++) sProb[j] *= inv;
    }
    __syncthreads();
    for (int d = t; d < DH; d += 256) {
        float acc = 0.f;
        for (int j = 0; j < JR; j++) {
            int u = base + j; if (u > UU - 1) u = UU - 1;
            acc += sProb[j] * g_fused[(long)u * DH + d];
        }
        g_pool[(long)sp * DH + d] = acc;
    }
}

// ---------------- small fp32 sgemm (tiny dense layer only) ----------------
template<bool TRANSB, bool BIAS, bool TANH_ACT>
__global__ void sgemm(const float* __restrict__ A, int lda, long sA,
                      const float* __restrict__ B, int ldb, long sB,
                      float* __restrict__ C, int ldc, long sC,
                      const float* __restrict__ bias,
                      int M, int N, int K)
{
    A += (long)blockIdx.z * sA;
    B += (long)blockIdx.z * sB;
    C += (long)blockIdx.z * sC;
    __shared__ float As[16][128];
    __shared__ float Bs[16][128];
    const int tid = threadIdx.x;
    const int m0 = blockIdx.y * 128;
    const int n0 = blockIdx.x * 128;
    const int tx = tid & 15;
    const int ty = tid >> 4;
    float acc[8][8];
#pragma unroll
    for (int i = 0; i < 8; i++)
#pragma unroll
        for (int j = 0; j < 8; j++) acc[i][j] = 0.f;

    for (int k0 = 0; k0 < K; k0 += 16) {
#pragma unroll
        for (int i = 0; i < 2; i++) {
            int li = tid + i * 256;
            int row = li >> 2;
            int kk  = (li & 3) << 2;
            float4 v = make_float4(0.f, 0.f, 0.f, 0.f);
            if (m0 + row < M)
                v = *reinterpret_cast<const float4*>(&A[(long)(m0 + row) * lda + k0 + kk]);
            As[kk + 0][row] = v.x; As[kk + 1][row] = v.y;
            As[kk + 2][row] = v.z; As[kk + 3][row] = v.w;
        }
        if (!TRANSB) {
#pragma unroll
            for (int i = 0; i < 2; i++) {
                int li = tid + i * 256;
                int kr = li >> 5;
                int nn = (li & 31) << 2;
                float4 v = *reinterpret_cast<const float4*>(&B[(long)(k0 + kr) * ldb + n0 + nn]);
                *reinterpret_cast<float4*>(&Bs[kr][nn]) = v;
            }
        } else {
#pragma unroll
            for (int i = 0; i < 2; i++) {
                int li = tid + i * 256;
                int nr = li >> 2;
                int kk = (li & 3) << 2;
                float4 v = make_float4(0.f, 0.f, 0.f, 0.f);
                if (n0 + nr < N)
                    v = *reinterpret_cast<const float4*>(&B[(long)(n0 + nr) * ldb + k0 + kk]);
                Bs[kk + 0][nr] = v.x; Bs[kk + 1][nr] = v.y;
                Bs[kk + 2][nr] = v.z; Bs[kk + 3][nr] = v.w;
            }
        }
        __syncthreads();
#pragma unroll
        for (int k = 0; k < 16; k++) {
            float a[8], b[8];
#pragma unroll
            for (int i = 0; i < 8; i++) a[i] = As[k][ty * 8 + i];
#pragma unroll
            for (int j = 0; j < 8; j++) b[j] = Bs[k][tx * 8 + j];
#pragma unroll
            for (int i = 0; i < 8; i++)
#pragma unroll
                for (int j = 0; j < 8; j++) acc[i][j] += a[i] * b[j];
        }
        __syncthreads();
    }
#pragma unroll
    for (int i = 0; i < 8; i++) {
        int m = m0 + ty * 8 + i;
        if (m >= M) continue;
#pragma unroll
        for (int j = 0; j < 8; j++) {
            int n = n0 + tx * 8 + j;
            float v = acc[i][j];
            if (BIAS) v += bias[n];
            if (TANH_ACT) v = tanhf(v);
            C[(long)m * ldc + n] = v;
        }
    }
}

// ---------------- classifier ----------------
__global__ void cls_kernel(const float* __restrict__ W_cls, const float* __restrict__ b_cls,
                           float* __restrict__ out)
{
    int row = blockIdx.x, t = threadIdx.x;
    int lane = t & 31, c = t >> 5;
    const float* hr = g_hid + (long)row * DH;
    float acc = 0.f;
    for (int k = lane; k < DH; k += 32) acc += hr[k] * W_cls[k * 4 + c];
    for (int o = 16; o; o >>= 1) acc += __shfl_xor_sync(0xffffffffu, acc, o);
    if (lane == 0) out[row * 4 + c] = acc + b_cls[c];
}

// ---------------- launcher ----------------
extern "C" void kernel_launch(void* const* d_in, const int* in_sizes, int n_in,
                              void* d_out, int out_size)
{
    const float* enc_img  = (const float*)d_in[0];
    const float* seq      = (const float*)d_in[1];
    const int*   starts   = (const int*)d_in[3];
    const int*   ends     = (const int*)d_in[4];
    const float* W_align  = (const float*)d_in[5];
    const float* b_align  = (const float*)d_in[6];
    const float* Wq       = (const float*)d_in[7];
    const float* Wk       = (const float*)d_in[8];
    const float* Wv       = (const float*)d_in[9];
    const float* Wfc      = (const float*)d_in[10];
    const float* ln_g     = (const float*)d_in[11];
    const float* ln_b     = (const float*)d_in[12];
    const float* W_a1     = (const float*)d_in[13];
    const float* b_a1     = (const float*)d_in[14];
    const float* W_a2     = (const float*)d_in[15];
    const float* b_a2     = (const float*)d_in[16];
    const float* W_un     = (const float*)d_in[17];
    const float* b_un     = (const float*)d_in[18];
    const float* W_dense  = (const float*)d_in[19];
    const float* b_dense  = (const float*)d_in[20];
    const float* W_cls    = (const float*)d_in[21];
    const float* b_cls    = (const float*)d_in[22];

    bf16 *eh, *el, *wath, *watl, *wqh, *wql, *wkh, *wkl, *wvh, *wvl, *wfh, *wfl;
    bf16 *c1h, *c1l, *bqh, *bql, *wvfh, *wvfl;
    bf16 *cth, *ctl, *wa1h, *wa1l, *f1h, *f1l, *wa2h, *wa2l;
    float *pKC, *pVC, *pFused, *pPool, *pHid;
    cudaGetSymbolAddress((void**)&eh,   g_enc_hi);  cudaGetSymbolAddress((void**)&el,   g_enc_lo);
    cudaGetSymbolAddress((void**)&wath, g_WalT_hi); cudaGetSymbolAddress((void**)&watl, g_WalT_lo);
    cudaGetSymbolAddress((void**)&wqh,  g_Wq_hi);   cudaGetSymbolAddress((void**)&wql,  g_Wq_lo);
    cudaGetSymbolAddress((void**)&wkh,  g_Wk_hi);   cudaGetSymbolAddress((void**)&wkl,  g_Wk_lo);
    cudaGetSymbolAddress((void**)&wvh,  g_Wv_hi);   cudaGetSymbolAddress((void**)&wvl,  g_Wv_lo);
    cudaGetSymbolAddress((void**)&wfh,  g_WfcT_hi); cudaGetSymbolAddress((void**)&wfl,  g_WfcT_lo);
    cudaGetSymbolAddress((void**)&c1h,  g_C1_hi);   cudaGetSymbolAddress((void**)&c1l,  g_C1_lo);
    cudaGetSymbolAddress((void**)&bqh,  g_Bqk_hi);  cudaGetSymbolAddress((void**)&bql,  g_Bqk_lo);
    cudaGetSymbolAddress((void**)&wvfh, g_WvfT_hi); cudaGetSymbolAddress((void**)&wvfl, g_WvfT_lo);
    cudaGetSymbolAddress((void**)&cth,  g_cat_hi);  cudaGetSymbolAddress((void**)&ctl,  g_cat_lo);
    cudaGetSymbolAddress((void**)&wa1h, g_Wa1T_hi); cudaGetSymbolAddress((void**)&wa1l, g_Wa1T_lo);
    cudaGetSymbolAddress((void**)&f1h,  g_f1_hi);   cudaGetSymbolAddress((void**)&f1l,  g_f1_lo);
    cudaGetSymbolAddress((void**)&wa2h, g_Wa2T_hi); cudaGetSymbolAddress((void**)&wa2l, g_Wa2T_lo);
    cudaGetSymbolAddress((void**)&pKC, g_KC);       cudaGetSymbolAddress((void**)&pVC, g_VC);
    cudaGetSymbolAddress((void**)&pFused, g_fused);
    cudaGetSymbolAddress((void**)&pPool, g_pool);   cudaGetSymbolAddress((void**)&pHid, g_hid);

    cudaFuncSetAttribute(mm_g123, cudaFuncAttributeMaxDynamicSharedMemorySize, MM_SMEM);
    cudaFuncSetAttribute(mm_g45,  cudaFuncAttributeMaxDynamicSharedMemorySize, MM_SMEM);
    cudaFuncSetAttribute(mmgemm<true,  true >, cudaFuncAttributeMaxDynamicSharedMemorySize, MM_SMEM);
    cudaFuncSetAttribute(mmgemm<false, false>, cudaFuncAttributeMaxDynamicSharedMemorySize, MM_SMEM);
    cudaFuncSetAttribute(att_out_ln_u, cudaFuncAttributeMaxDynamicSharedMemorySize, AOL_SMEM);

    const dim3 blk(128);

    // ---- operand conversions ----
    split_kernel<<<1024, 256>>>(enc_img, eh, el, (long)NR * IMGD);
    splitT_kernel<<<dim3(DH / 32, IMGD / 32), dim3(32, 8)>>>(W_align, wath, watl, IMGD, DH);
    split_kernel<<<1024, 256>>>(Wq, wqh, wql, (long)DH * HH * DH);
    split_kernel<<<1024, 256>>>(Wk, wkh, wkl, (long)DH * HH * DH);
    split_kernel<<<1024, 256>>>(Wv, wvh, wvl, (long)DH * HH * DH);
    splitT_kernel<<<dim3(DH / 32, (HH * DH) / 32), dim3(32, 8)>>>(Wfc, wfh, wfl, HH * DH, DH);
    splitT_kernel<<<dim3((2*DH) / 32, (2*DH) / 32), dim3(32, 8)>>>(W_a1, wa1h, wa1l, 2*DH, 2*DH);
    splitT_kernel<<<dim3(DH / 32, (2*DH) / 32), dim3(32, 8)>>>(W_a2, wa2h, wa2l, 2*DH, DH);
    seq_split_kernel<<<UU, 256>>>(seq);

    // ---- G1 + G2 + G3 fused launch ----
    mm_g123<<<dim3(6, 7, 17), blk, MM_SMEM>>>(
        eh, el, wath, watl, c1h, c1l, b_align,
        wqh, wql, wkh, wkl, bqh, bql,
        wfh, wfl, wvh, wvl, wvfh, wvfl);

    // ---- G4 + G5 fused launch ----
    mm_g45<<<dim3(6, 7, 16), blk, MM_SMEM>>>(c1h, c1l, bqh, bql, wvfh, wvfl, pKC, pVC);

    // ---- attention on 2048 distinct tokens ----
    att_scores_u<<<dim3(HH, NB), 256>>>(seq);
    att_out_ln_u<<<dim3(8, NB), 256, AOL_SMEM>>>(seq, ln_g, ln_b);

    // ---- fusion MLP on 2048 tokens ----
    mmgemm<true, true><<<dim3(12, 16, 1), blk, MM_SMEM>>>(
        cth, ctl, 2 * DH, 0, wa1h, wa1l, 2 * DH, 0,
        nullptr, f1h, f1l, 2 * DH, 0, b_a1, UU, 2 * DH, 2 * DH);
    mmgemm<false, false><<<dim3(6, 16, 1), blk, MM_SMEM>>>(
        f1h, f1l, 2 * DH, 0, wa2h, wa2l, 2 * DH, 0,
        pFused, nullptr, nullptr, DH, 0, b_a2, UU, DH, 2 * DH);

    // ---- pooling + head ----
    pool_kernel<<<NM, 256>>>(W_un, b_un, starts, ends);
    sgemm<false, true, true><<<dim3(6, 1, 1), dim3(256)>>>(
        pPool, DH, 0, W_dense, DH, 0, pHid, DH, 0, b_dense, NM, DH, DH);
    cls_kernel<<<NM, 128>>>(W_cls, b_cls, (float*)d_out);
}

// round 9
// speedup vs baseline: 3.1085x; 1.6064x over previous
#include <cuda_runtime.h>
#include <cuda_fp16.h>
#include <math.h>
#include <stdint.h>

// ---------------- problem constants ----------------
#define NB    16
#define LSEQ  128
#define DH    768
#define MSP   8
#define HH    8
#define JR    30
#define RR    49
#define IMGD  2048
#define NM    128            // NB*MSP
#define UU    2048           // NB*LSEQ distinct tokens
#define NR    784            // NB*RR

typedef __half h16;

// ---------------- scratch (device globals; no cudaMalloc allowed) ----------------
__device__ h16 g_enc[NR * IMGD];
__device__ h16 g_WalT[DH * IMGD];
__device__ h16 g_Wq[DH * HH * DH];
__device__ h16 g_Wk[DH * HH * DH];
__device__ h16 g_Wv[DH * HH * DH];
__device__ h16 g_WfcT[DH * HH * DH];
__device__ h16 g_C1[NR * DH];
__device__ h16 g_Bqk[HH * DH * DH];
__device__ h16 g_WvfT[HH * DH * DH];
__device__ float g_KC[HH * NR * DH];
__device__ float g_VC[HH * NR * DH];
__device__ float g_P[NB * HH * LSEQ * RR];
__device__ h16 g_cat[UU * 2 * DH];
__device__ h16 g_Wa1T[2*DH * 2*DH];
__device__ h16 g_f1[UU * 2 * DH];
__device__ h16 g_Wa2T[DH * 2*DH];
__device__ float g_fused[UU * DH];
__device__ float g_pool[NM * DH];
__device__ float g_hid[NM * DH];

// ---------------- helpers ----------------
__device__ __forceinline__ uint32_t smem_u32(const void* p) {
    uint32_t a;
    asm("{ .reg .u64 t; cvta.to.shared.u64 t, %1; cvt.u32.u64 %0, t; }" : "=r"(a) : "l"(p));
    return a;
}

__device__ __forceinline__ void ldm_x4(uint32_t* r, uint32_t addr) {
    asm volatile("ldmatrix.sync.aligned.m8n8.x4.shared.b16 {%0,%1,%2,%3}, [%4];"
                 : "=r"(r[0]), "=r"(r[1]), "=r"(r[2]), "=r"(r[3]) : "r"(addr));
}

__device__ __forceinline__ void mma16816(float* c, const uint32_t* a, uint32_t b0, uint32_t b1) {
    asm volatile(
        "mma.sync.aligned.m16n8k16.row.col.f32.f16.f16.f32 "
        "{%0,%1,%2,%3}, {%4,%5,%6,%7}, {%8,%9}, {%0,%1,%2,%3};"
        : "+f"(c[0]), "+f"(c[1]), "+f"(c[2]), "+f"(c[3])
        : "r"(a[0]), "r"(a[1]), "r"(a[2]), "r"(a[3]), "r"(b0), "r"(b1));
}

__device__ __forceinline__ void cpa16(uint32_t dst, const void* src) {
    asm volatile("cp.async.ca.shared.global [%0], [%1], 16;" :: "r"(dst), "l"(src));
}
__device__ __forceinline__ void cpa_commit() {
    asm volatile("cp.async.commit_group;" ::: "memory");
}
template<int N_>
__device__ __forceinline__ void cpa_wait() {
    asm volatile("cp.async.wait_group %0;" :: "n"(N_) : "memory");
}

// ---------------- fp16 tensor-core GEMM core v3 ----------------
// Block 128x128, BK=64, 4 warps (2x2), warp tile 64x64.
// 3-stage cp.async pipeline, XOR-swizzled (128B rows: slot' = g ^ (row&7)).
#define BM 128
#define BN 128
#define BK 64
#define T_B 16384
#define STAGE_B 32768
#define MM_SMEM (3 * STAGE_B)                 // 98304

template<bool OUT_F16, bool TANH_ACT>
__device__ __forceinline__ void mm_body(
    const h16* __restrict__ A, int lda,
    const h16* __restrict__ B, int ldb,
    float* __restrict__ Cf, h16* __restrict__ Ch, int ldc,
    const float* __restrict__ bias, int M, int N, int K)
{
    extern __shared__ char dsm[];
    const uint32_t u_sm = smem_u32(dsm);

    const int tid = threadIdx.x, lane = tid & 31, wid = tid >> 5;
    const int wr = wid >> 1, wc = wid & 1;
    const int m0 = blockIdx.y * BM, n0 = blockIdx.x * BN;

    float acc[4][8][4];
#pragma unroll
    for (int i = 0; i < 4; i++)
#pragma unroll
        for (int j = 0; j < 8; j++)
#pragma unroll
            for (int e = 0; e < 4; e++) acc[i][j][e] = 0.f;

    const int lrow = lane & 15;
    const int khalf = lane >> 4;
    const int xk = lrow & 7;
    const uint32_t rA = (uint32_t)((wr * 64 + lrow) * 128);
    const uint32_t rB = (uint32_t)(T_B) + (uint32_t)((wc * 64 + lrow) * 128);

    // stage loader: 16 x 16B per thread (2048 ops = 32KB)
    auto load_stage = [&](int st, int k0) {
        const uint32_t sbase = u_sm + (uint32_t)(st * STAGE_B);
#pragma unroll
        for (int i = 0; i < 16; i++) {
            int u = tid + i * 128;            // 0..2047
            int v = u & 1023;
            int r = v >> 3;
            int g = v & 7;
            const h16* src;
            uint32_t toff;
            if (u < 1024) { int ga = m0 + r; if (ga > M - 1) ga = M - 1;
                            src = A + (long)ga * lda + k0 + g * 8; toff = 0; }
            else          { int gb = n0 + r; if (gb > N - 1) gb = N - 1;
                            src = B + (long)gb * ldb + k0 + g * 8; toff = T_B; }
            uint32_t doff = toff + (uint32_t)(r * 128) + (uint32_t)(((g ^ (r & 7)) << 4));
            cpa16(sbase + doff, src);
        }
    };

    const int nch = K / BK;
    load_stage(0, 0);  cpa_commit();
    load_stage(1, BK); cpa_commit();

    int st = 0;
    for (int ch = 0; ch < nch; ch++) {
        if (ch == nch - 1) cpa_wait<0>(); else cpa_wait<1>();
        __syncthreads();
        if (ch + 2 < nch) {
            int st2 = st + 2; if (st2 >= 3) st2 -= 3;
            load_stage(st2, (ch + 2) * BK);
            cpa_commit();
        }

        const uint32_t so = u_sm + (uint32_t)(st * STAGE_B);
#pragma unroll
        for (int ks = 0; ks < 4; ks++) {
            const uint32_t sw = (uint32_t)((((ks * 2) | khalf) ^ xk) << 4);
            uint32_t bh[4][4];
#pragma unroll
            for (int nt = 0; nt < 4; nt++)
                ldm_x4(bh[nt], so + rB + (uint32_t)(nt * 2048) + sw);
#pragma unroll
            for (int mi = 0; mi < 4; mi++) {
                uint32_t ah[4];
                ldm_x4(ah, so + rA + (uint32_t)(mi * 2048) + sw);
#pragma unroll
                for (int nt = 0; nt < 4; nt++) {
#pragma unroll
                    for (int j = 0; j < 2; j++)
                        mma16816(acc[mi][nt * 2 + j], ah, bh[nt][j], bh[nt][j + 2]);
                }
            }
        }
        if (++st == 3) st = 0;
    }

    const int er = m0 + wr * 64 + (lane >> 2);
    const int ec = n0 + wc * 64 + (lane & 3) * 2;
#pragma unroll
    for (int mi = 0; mi < 4; mi++) {
#pragma unroll
        for (int nj = 0; nj < 8; nj++) {
            const int col = ec + nj * 8;
            float bv0 = 0.f, bv1 = 0.f;
            if (bias) { bv0 = bias[col]; bv1 = bias[col + 1]; }
#pragma unroll
            for (int half = 0; half < 2; half++) {
                const int row = er + mi * 16 + half * 8;
                if (row >= M) continue;
                float v0 = acc[mi][nj][half * 2 + 0] + bv0;
                float v1 = acc[mi][nj][half * 2 + 1] + bv1;
                if (TANH_ACT) { v0 = tanhf(v0); v1 = tanhf(v1); }
                const long base = (long)row * ldc + col;
                if (OUT_F16) {
                    __half2 h = __floats2half2_rn(v0, v1);
                    *reinterpret_cast<uint32_t*>(Ch + base) = reinterpret_cast<uint32_t&>(h);
                } else {
                    *reinterpret_cast<float2*>(Cf + base) = make_float2(v0, v1);
                }
            }
        }
    }
}

// generic batched wrapper
template<bool OUT_F16, bool TANH_ACT>
__global__ __launch_bounds__(128, 2)
void mmgemm(const h16* __restrict__ A, int lda, long sA,
            const h16* __restrict__ B, int ldb, long sB,
            float* __restrict__ Cf, h16* __restrict__ Ch,
            int ldc, long sC, const float* __restrict__ bias,
            int M, int N, int K)
{
    const long za = (long)blockIdx.z * sA, zb = (long)blockIdx.z * sB, zc = (long)blockIdx.z * sC;
    mm_body<OUT_F16, TANH_ACT>(
        A + za, lda, B + zb, ldb,
        Cf ? Cf + zc : nullptr, Ch ? Ch + zc : nullptr, ldc, bias, M, N, K);
}

// fused G1 + G2 + G3: z=0 -> G1; z=1..8 -> G2 head; z=9..16 -> G3 head
__global__ __launch_bounds__(128, 2)
void mm_g123(const h16* __restrict__ enc, const h16* __restrict__ walT,
             h16* __restrict__ c1, const float* __restrict__ b_align,
             const h16* __restrict__ wq, const h16* __restrict__ wk, h16* __restrict__ bqk,
             const h16* __restrict__ wfT, const h16* __restrict__ wv, h16* __restrict__ wvfT)
{
    int z = blockIdx.z;
    if (z == 0) {
        mm_body<true, false>(enc, IMGD, walT, IMGD, nullptr, c1, DH, b_align, NR, DH, IMGD);
    } else {
        if (blockIdx.y * BM >= DH) return;
        z -= 1;
        const int set = z >> 3, h = z & 7;
        const long co = (long)h * DH;
        const long cc = (long)h * DH * DH;
        if (set == 0)
            mm_body<true, false>(wq + co, HH * DH, wk + co, HH * DH,
                                 nullptr, bqk + cc, DH, nullptr, DH, DH, DH);
        else
            mm_body<true, false>(wfT + co, HH * DH, wv + co, HH * DH,
                                 nullptr, wvfT + cc, DH, nullptr, DH, DH, DH);
    }
}

// fused G4 + G5: z=0..7 -> KC head, z=8..15 -> VC head
__global__ __launch_bounds__(128, 2)
void mm_g45(const h16* __restrict__ c1, const h16* __restrict__ bqk,
            const h16* __restrict__ wvfT, float* __restrict__ pKC, float* __restrict__ pVC)
{
    int z = blockIdx.z;
    const long NRD = (long)NR * DH;
    const long HD2 = (long)DH * DH;
    if (z < HH)
        mm_body<false, false>(c1, DH, bqk + (long)z * HD2, DH,
                              pKC + (long)z * NRD, nullptr, DH, nullptr, NR, DH, DH);
    else {
        z -= HH;
        mm_body<false, false>(c1, DH, wvfT + (long)z * HD2, DH,
                              pVC + (long)z * NRD, nullptr, DH, nullptr, NR, DH, DH);
    }
}

// ---------------- fp32 -> fp16 convert (vectorized) ----------------
__global__ void cvt_kernel(const float* __restrict__ in, h16* __restrict__ out, long n)
{
    long i0 = ((long)blockIdx.x * blockDim.x + threadIdx.x) * 4;
    long stride = (long)gridDim.x * blockDim.x * 4;
    for (long i = i0; i < n; i += stride) {
        float4 v = *reinterpret_cast<const float4*>(in + i);
        __half2 h0 = __floats2half2_rn(v.x, v.y);
        __half2 h1 = __floats2half2_rn(v.z, v.w);
        *reinterpret_cast<uint2*>(out + i) =
            make_uint2(reinterpret_cast<uint32_t&>(h0), reinterpret_cast<uint32_t&>(h1));
    }
}

// ---------------- fp32 [R,C] -> transposed fp16 [C,R] ----------------
__global__ void cvtT_kernel(const float* __restrict__ in, h16* __restrict__ out, int R, int C)
{
    __shared__ float t[32][33];
    int c0 = blockIdx.x * 32, r0 = blockIdx.y * 32;
    for (int i = threadIdx.y; i < 32; i += 8)
        t[i][threadIdx.x] = in[(long)(r0 + i) * C + c0 + threadIdx.x];
    __syncthreads();
    if (threadIdx.x < 16) {
        for (int i = threadIdx.y; i < 32; i += 8) {
            __half2 h = __floats2half2_rn(t[2 * threadIdx.x][i], t[2 * threadIdx.x + 1][i]);
            long o = (long)(c0 + i) * R + r0 + 2 * threadIdx.x;
            *reinterpret_cast<uint32_t*>(out + o) = reinterpret_cast<uint32_t&>(h);
        }
    }
}

// ---------------- seq -> cat[:, 0:768] fp16 ----------------
__global__ void seq_cvt_kernel(const float* __restrict__ seq)
{
    int row = blockIdx.x, t = threadIdx.x;
    for (int idx = t * 4; idx < DH; idx += 256 * 4) {
        float4 v = *reinterpret_cast<const float4*>(seq + (long)row * DH + idx);
        __half2 h0 = __floats2half2_rn(v.x, v.y);
        __half2 h1 = __floats2half2_rn(v.z, v.w);
        *reinterpret_cast<uint2*>(g_cat + (long)row * 2 * DH + idx) =
            make_uint2(reinterpret_cast<uint32_t&>(h0), reinterpret_cast<uint32_t&>(h1));
    }
}

// ---------------- attention scores + softmax per token (dedup) ----------------
__global__ __launch_bounds__(256) void att_scores_u(const float* __restrict__ seq)
{
    const int h = blockIdx.x, n = blockIdx.y;
    __shared__ float buf[128 * 65 + 49 * 65];
    float (*sQ)[65] = reinterpret_cast<float(*)[65]>(buf);
    float (*sK)[65] = reinterpret_cast<float(*)[65]>(buf + 128 * 65);
    float* sS = buf;
    const int t = threadIdx.x;
    const int qg = t & 31, rg = t >> 5;

    float acc[4][7];
#pragma unroll
    for (int a = 0; a < 4; a++)
#pragma unroll
        for (int b = 0; b < 7; b++) acc[a][b] = 0.f;

    const float* Qp = seq + (long)n * LSEQ * DH;
    const float* Kp = g_KC + ((long)h * NR + (long)n * RR) * DH;

    for (int kc = 0; kc < DH / 64; kc++) {
        const int k0 = kc * 64;
        for (int e = t; e < 128 * 64; e += 256)
            sQ[e >> 6][e & 63] = Qp[(long)(e >> 6) * DH + k0 + (e & 63)];
        for (int e = t; e < 49 * 64; e += 256)
            sK[e / 64][e % 64] = Kp[(long)(e / 64) * DH + k0 + (e % 64)];
        __syncthreads();
        if (rg < 7) {
            for (int kk = 0; kk < 64; kk++) {
                float kv[7];
#pragma unroll
                for (int i = 0; i < 7; i++) kv[i] = sK[rg * 7 + i][kk];
#pragma unroll
                for (int qi = 0; qi < 4; qi++) {
                    float qv = sQ[qg + 32 * qi][kk];
#pragma unroll
                    for (int i = 0; i < 7; i++) acc[qi][i] += qv * kv[i];
                }
            }
        }
        __syncthreads();
    }

    const float scale = 1.0f / sqrtf((float)DH);
    if (rg < 7) {
#pragma unroll
        for (int qi = 0; qi < 4; qi++)
#pragma unroll
            for (int i = 0; i < 7; i++)
                sS[(qg + 32 * qi) * 49 + rg * 7 + i] = acc[qi][i] * scale;
    }
    __syncthreads();

    if (t < 128) {
        float* row = sS + t * 49;
        float mx = row[0];
        for (int r = 1; r < RR; r++) mx = fmaxf(mx, row[r]);
        float sum = 0.f;
        float ex[49];
        for (int r = 0; r < RR; r++) { ex[r] = expf(row[r] - mx); sum += ex[r]; }
        float inv = 1.f / sum;
        float* out = g_P + (((long)(n * HH + h)) * LSEQ + t) * RR;
        for (int r = 0; r < RR; r++) out[r] = ex[r] * inv;
    }
}

// ---------------- out = LN(sum_h P_h @ VC_h + seq) -> cat[:, 768:1536] fp16 ----------------
#define AOL_SMEM ((8 * 16 * 49 + 16 * 768) * 4)
__global__ __launch_bounds__(256) void att_out_ln_u(const float* __restrict__ seq,
                                                    const float* __restrict__ gam,
                                                    const float* __restrict__ bet)
{
    extern __shared__ float ds[];
    float* sP = ds;
    float* sX = ds + 8 * 16 * 49;
    const int qg = blockIdx.x, n = blockIdx.y;
    const int t = threadIdx.x;

    for (int e = t; e < 8 * 16 * 49; e += 256) {
        int h = e / (16 * 49), rem = e % (16 * 49);
        int q = rem / 49, r = rem % 49;
        sP[e] = g_P[(((long)(n * HH + h)) * LSEQ + qg * 16 + q) * RR + r];
    }
    __syncthreads();

    float acc[16][3];
#pragma unroll
    for (int q = 0; q < 16; q++) { acc[q][0] = 0.f; acc[q][1] = 0.f; acc[q][2] = 0.f; }

    for (int h = 0; h < HH; h++) {
        const float* Vb = g_VC + ((long)h * NR + (long)n * RR) * DH;
        const float* Ph = sP + h * 16 * 49;
        for (int r = 0; r < RR; r++) {
            float v0 = Vb[(long)r * DH + t];
            float v1 = Vb[(long)r * DH + 256 + t];
            float v2 = Vb[(long)r * DH + 512 + t];
            const float* Pr = Ph + r;
#pragma unroll
            for (int q = 0; q < 16; q++) {
                float p = Pr[q * 49];
                acc[q][0] += p * v0; acc[q][1] += p * v1; acc[q][2] += p * v2;
            }
        }
    }

#pragma unroll
    for (int q = 0; q < 16; q++) {
        long srow = ((long)n * LSEQ + qg * 16 + q) * DH;
        sX[q * 768 + t]       = acc[q][0] + seq[srow + t];
        sX[q * 768 + 256 + t] = acc[q][1] + seq[srow + 256 + t];
        sX[q * 768 + 512 + t] = acc[q][2] + seq[srow + 512 + t];
    }
    __syncthreads();

    const int wid = t >> 5, lane = t & 31;
    for (int qq = wid * 2; qq < wid * 2 + 2; qq++) {
        float* row = sX + qq * 768;
        float s = 0.f;
        for (int k = lane; k < DH; k += 32) s += row[k];
        for (int o = 16; o; o >>= 1) s += __shfl_xor_sync(0xffffffffu, s, o);
        float mu = s * (1.f / DH);
        float v = 0.f;
        for (int k = lane; k < DH; k += 32) { float d = row[k] - mu; v += d * d; }
        for (int o = 16; o; o >>= 1) v += __shfl_xor_sync(0xffffffffu, v, o);
        float rstd = rsqrtf(v * (1.f / DH) + 1e-5f);
        long orow = ((long)n * LSEQ + qg * 16 + qq) * 2 * DH + DH;
        for (int k = lane * 2; k < DH; k += 64) {
            float a = (row[k]     - mu) * rstd * gam[k]     + bet[k];
            float b = (row[k + 1] - mu) * rstd * gam[k + 1] + bet[k + 1];
            __half2 h = __floats2half2_rn(a, b);
            *reinterpret_cast<uint32_t*>(g_cat + orow + k) = reinterpret_cast<uint32_t&>(h);
        }
    }
}

// ---------------- unary score + masked softmax pooling (token-indexed) ----------------
__global__ void pool_kernel(const float* __restrict__ W_un, const float* __restrict__ b_un,
                            const int* __restrict__ starts, const int* __restrict__ ends)
{
    int sp = blockIdx.x, t = threadIdx.x;
    int lane = t & 31, w = t >> 5;
    int n = sp >> 3;
    int base = n * LSEQ + starts[sp];
    __shared__ float sS[JR];
    __shared__ float sProb[JR];

    for (int j = w; j < JR; j += 8) {
        int u = base + j; if (u > UU - 1) u = UU - 1;
        const float* fr = g_fused + (long)u * DH;
        float acc = 0.f;
        for (int k = lane; k < DH; k += 32) acc += fr[k] * W_un[k];
        for (int o = 16; o; o >>= 1) acc += __shfl_xor_sync(0xffffffffu, acc, o);
        if (lane == 0) sS[j] = acc + b_un[0];
    }
    __syncthreads();
    if (t == 0) {
        int width = ends[sp] - starts[sp] + 1;
        float mx = -1e30f;
        for (int j = 0; j < JR; j++) {
            float v = sS[j] + ((j < width) ? 0.f : -10000.f);
            sS[j] = v; mx = fmaxf(mx, v);
        }
        float sum = 0.f;
        for (int j = 0; j < JR; j++) { float e = expf(sS[j] - mx); sProb[j] = e; sum += e; }
        float inv = 1.f / sum;
        for (int j = 0; j < JR; j++) sProb[j] *= inv;
    }
    __syncthreads();
    for (int d = t; d < DH; d += 256) {
        float acc = 0.f;
        for (int j = 0; j < JR; j++) {
            int u = base + j; if (u > UU - 1) u = UU - 1;
            acc += sProb[j] * g_fused[(long)u * DH + d];
        }
        g_pool[(long)sp * DH + d] = acc;
    }
}

// ---------------- small fp32 sgemm (tiny dense layer only) ----------------
template<bool TRANSB, bool BIAS, bool TANH_ACT>
__global__ void sgemm(const float* __restrict__ A, int lda, long sA,
                      const float* __restrict__ B, int ldb, long sB,
                      float* __restrict__ C, int ldc, long sC,
                      const float* __restrict__ bias,
                      int M, int N, int K)
{
    A += (long)blockIdx.z * sA;
    B += (long)blockIdx.z * sB;
    C += (long)blockIdx.z * sC;
    __shared__ float As[16][128];
    __shared__ float Bs[16][128];
    const int tid = threadIdx.x;
    const int m0 = blockIdx.y * 128;
    const int n0 = blockIdx.x * 128;
    const int tx = tid & 15;
    const int ty = tid >> 4;
    float acc[8][8];
#pragma unroll
    for (int i = 0; i < 8; i++)
#pragma unroll
        for (int j = 0; j < 8; j++) acc[i][j] = 0.f;

    for (int k0 = 0; k0 < K; k0 += 16) {
#pragma unroll
        for (int i = 0; i < 2; i++) {
            int li = tid + i * 256;
            int row = li >> 2;
            int kk  = (li & 3) << 2;
            float4 v = make_float4(0.f, 0.f, 0.f, 0.f);
            if (m0 + row < M)
                v = *reinterpret_cast<const float4*>(&A[(long)(m0 + row) * lda + k0 + kk]);
            As[kk + 0][row] = v.x; As[kk + 1][row] = v.y;
            As[kk + 2][row] = v.z; As[kk + 3][row] = v.w;
        }
        if (!TRANSB) {
#pragma unroll
            for (int i = 0; i < 2; i++) {
                int li = tid + i * 256;
                int kr = li >> 5;
                int nn = (li & 31) << 2;
                float4 v = *reinterpret_cast<const float4*>(&B[(long)(k0 + kr) * ldb + n0 + nn]);
                *reinterpret_cast<float4*>(&Bs[kr][nn]) = v;
            }
        } else {
#pragma unroll
            for (int i = 0; i < 2; i++) {
                int li = tid + i * 256;
                int nr = li >> 2;
                int kk = (li & 3) << 2;
                float4 v = make_float4(0.f, 0.f, 0.f, 0.f);
                if (n0 + nr < N)
                    v = *reinterpret_cast<const float4*>(&B[(long)(n0 + nr) * ldb + k0 + kk]);
                Bs[kk + 0][nr] = v.x; Bs[kk + 1][nr] = v.y;
                Bs[kk + 2][nr] = v.z; Bs[kk + 3][nr] = v.w;
            }
        }
        __syncthreads();
#pragma unroll
        for (int k = 0; k < 16; k++) {
            float a[8], b[8];
#pragma unroll
            for (int i = 0; i < 8; i++) a[i] = As[k][ty * 8 + i];
#pragma unroll
            for (int j = 0; j < 8; j++) b[j] = Bs[k][tx * 8 + j];
#pragma unroll
            for (int i = 0; i < 8; i++)
#pragma unroll
                for (int j = 0; j < 8; j++) acc[i][j] += a[i] * b[j];
        }
        __syncthreads();
    }
#pragma unroll
    for (int i = 0; i < 8; i++) {
        int m = m0 + ty * 8 + i;
        if (m >= M) continue;
#pragma unroll
        for (int j = 0; j < 8; j++) {
            int n = n0 + tx * 8 + j;
            float v = acc[i][j];
            if (BIAS) v += bias[n];
            if (TANH_ACT) v = tanhf(v);
            C[(long)m * ldc + n] = v;
        }
    }
}

// ---------------- classifier ----------------
__global__ void cls_kernel(const float* __restrict__ W_cls, const float* __restrict__ b_cls,
                           float* __restrict__ out)
{
    int row = blockIdx.x, t = threadIdx.x;
    int lane = t & 31, c = t >> 5;
    const float* hr = g_hid + (long)row * DH;
    float acc = 0.f;
    for (int k = lane; k < DH; k += 32) acc += hr[k] * W_cls[k * 4 + c];
    for (int o = 16; o; o >>= 1) acc += __shfl_xor_sync(0xffffffffu, acc, o);
    if (lane == 0) out[row * 4 + c] = acc + b_cls[c];
}

// ---------------- launcher ----------------
extern "C" void kernel_launch(void* const* d_in, const int* in_sizes, int n_in,
                              void* d_out, int out_size)
{
    const float* enc_img  = (const float*)d_in[0];
    const float* seq      = (const float*)d_in[1];
    const int*   starts   = (const int*)d_in[3];
    const int*   ends     = (const int*)d_in[4];
    const float* W_align  = (const float*)d_in[5];
    const float* b_align  = (const float*)d_in[6];
    const float* Wq       = (const float*)d_in[7];
    const float* Wk       = (const float*)d_in[8];
    const float* Wv       = (const float*)d_in[9];
    const float* Wfc      = (const float*)d_in[10];
    const float* ln_g     = (const float*)d_in[11];
    const float* ln_b     = (const float*)d_in[12];
    const float* W_a1     = (const float*)d_in[13];
    const float* b_a1     = (const float*)d_in[14];
    const float* W_a2     = (const float*)d_in[15];
    const float* b_a2     = (const float*)d_in[16];
    const float* W_un     = (const float*)d_in[17];
    const float* b_un     = (const float*)d_in[18];
    const float* W_dense  = (const float*)d_in[19];
    const float* b_dense  = (const float*)d_in[20];
    const float* W_cls    = (const float*)d_in[21];
    const float* b_cls    = (const float*)d_in[22];

    h16 *enc, *walT, *wq, *wk, *wv, *wfT, *c1, *bqk, *wvfT, *cat, *wa1T, *f1, *wa2T;
    float *pKC, *pVC, *pFused, *pPool, *pHid;
    cudaGetSymbolAddress((void**)&enc,  g_enc);
    cudaGetSymbolAddress((void**)&walT, g_WalT);
    cudaGetSymbolAddress((void**)&wq,   g_Wq);
    cudaGetSymbolAddress((void**)&wk,   g_Wk);
    cudaGetSymbolAddress((void**)&wv,   g_Wv);
    cudaGetSymbolAddress((void**)&wfT,  g_WfcT);
    cudaGetSymbolAddress((void**)&c1,   g_C1);
    cudaGetSymbolAddress((void**)&bqk,  g_Bqk);
    cudaGetSymbolAddress((void**)&wvfT, g_WvfT);
    cudaGetSymbolAddress((void**)&cat,  g_cat);
    cudaGetSymbolAddress((void**)&wa1T, g_Wa1T);
    cudaGetSymbolAddress((void**)&f1,   g_f1);
    cudaGetSymbolAddress((void**)&wa2T, g_Wa2T);
    cudaGetSymbolAddress((void**)&pKC, g_KC);
    cudaGetSymbolAddress((void**)&pVC, g_VC);
    cudaGetSymbolAddress((void**)&pFused, g_fused);
    cudaGetSymbolAddress((void**)&pPool, g_pool);
    cudaGetSymbolAddress((void**)&pHid, g_hid);

    cudaFuncSetAttribute(mm_g123, cudaFuncAttributeMaxDynamicSharedMemorySize, MM_SMEM);
    cudaFuncSetAttribute(mm_g45,  cudaFuncAttributeMaxDynamicSharedMemorySize, MM_SMEM);
    cudaFuncSetAttribute(mmgemm<true,  true >, cudaFuncAttributeMaxDynamicSharedMemorySize, MM_SMEM);
    cudaFuncSetAttribute(mmgemm<false, false>, cudaFuncAttributeMaxDynamicSharedMemorySize, MM_SMEM);
    cudaFuncSetAttribute(att_out_ln_u, cudaFuncAttributeMaxDynamicSharedMemorySize, AOL_SMEM);

    const dim3 blk(128);

    // ---- operand conversions (fp32 -> fp16) ----
    cvt_kernel<<<1024, 256>>>(enc_img, enc, (long)NR * IMGD);
    cvtT_kernel<<<dim3(DH / 32, IMGD / 32), dim3(32, 8)>>>(W_align, walT, IMGD, DH);
    cvt_kernel<<<1024, 256>>>(Wq, wq, (long)DH * HH * DH);
    cvt_kernel<<<1024, 256>>>(Wk, wk, (long)DH * HH * DH);
    cvt_kernel<<<1024, 256>>>(Wv, wv, (long)DH * HH * DH);
    cvtT_kernel<<<dim3(DH / 32, (HH * DH) / 32), dim3(32, 8)>>>(Wfc, wfT, HH * DH, DH);
    cvtT_kernel<<<dim3((2*DH) / 32, (2*DH) / 32), dim3(32, 8)>>>(W_a1, wa1T, 2*DH, 2*DH);
    cvtT_kernel<<<dim3(DH / 32, (2*DH) / 32), dim3(32, 8)>>>(W_a2, wa2T, 2*DH, DH);
    seq_cvt_kernel<<<UU, 256>>>(seq);

    // ---- G1 + G2 + G3 fused ----
    mm_g123<<<dim3(6, 7, 17), blk, MM_SMEM>>>(
        enc, walT, c1, b_align, wq, wk, bqk, wfT, wv, wvfT);

    // ---- G4 + G5 fused ----
    mm_g45<<<dim3(6, 7, 16), blk, MM_SMEM>>>(c1, bqk, wvfT, pKC, pVC);

    // ---- attention on 2048 distinct tokens ----
    att_scores_u<<<dim3(HH, NB), 256>>>(seq);
    att_out_ln_u<<<dim3(8, NB), 256, AOL_SMEM>>>(seq, ln_g, ln_b);

    // ---- fusion MLP on 2048 tokens ----
    mmgemm<true, true><<<dim3(12, 16, 1), blk, MM_SMEM>>>(
        cat, 2 * DH, 0, wa1T, 2 * DH, 0,
        nullptr, f1, 2 * DH, 0, b_a1, UU, 2 * DH, 2 * DH);
    mmgemm<false, false><<<dim3(6, 16, 1), blk, MM_SMEM>>>(
        f1, 2 * DH, 0, wa2T, 2 * DH, 0,
        pFused, nullptr, DH, 0, b_a2, UU, DH, 2 * DH);

    // ---- pooling + head ----
    pool_kernel<<<NM, 256>>>(W_un, b_un, starts, ends);
    sgemm<false, true, true><<<dim3(6, 1, 1), dim3(256)>>>(
        pPool, DH, 0, W_dense, DH, 0, pHid, DH, 0, b_dense, NM, DH, DH);
    cls_kernel<<<NM, 128>>>(W_cls, b_cls, (float*)d_out);
}

// round 10
// speedup vs baseline: 4.2130x; 1.3553x over previous
#include <cuda_runtime.h>
#include <cuda_fp16.h>
#include <math.h>
#include <stdint.h>

// ---------------- problem constants ----------------
#define NB    16
#define LSEQ  128
#define DH    768
#define MSP   8
#define HH    8
#define JR    30
#define RR    49
#define IMGD  2048
#define NM    128            // NB*MSP
#define UU    2048           // NB*LSEQ distinct tokens
#define NR    784            // NB*RR
#define KP    448            // padded concat-head K (8*49=392 -> 448)

typedef __half h16;

// ---------------- scratch (device globals; no cudaMalloc allowed) ----------------
__device__ h16 g_enc[NR * IMGD];
__device__ h16 g_WalT[DH * IMGD];
__device__ h16 g_Wq[DH * HH * DH];
__device__ h16 g_Wk[DH * HH * DH];
__device__ h16 g_Wv[DH * HH * DH];
__device__ h16 g_WfcT[DH * HH * DH];
__device__ h16 g_C1[NR * DH];
__device__ h16 g_Bqk[HH * DH * DH];
__device__ h16 g_WvfT[HH * DH * DH];
__device__ h16 g_KC16[HH * NR * DH];
__device__ h16 g_VC16[HH * NR * DH];
__device__ float g_S[NB * HH * LSEQ * 64];     // raw scores, padded 49->64
__device__ h16 g_Pp[NB * LSEQ * KP];           // probs, [n][tok][h*49+r], zero-padded
__device__ h16 g_Vt[NB * DH * KP];             // [n][d][h*49+r]
__device__ float g_attout[UU * DH];
__device__ h16 g_cat[UU * 2 * DH];
__device__ h16 g_Wa1T[2*DH * 2*DH];
__device__ h16 g_f1[UU * 2 * DH];
__device__ h16 g_Wa2T[DH * 2*DH];
__device__ float g_fused[UU * DH];
__device__ float g_pool[NM * DH];
__device__ float g_hid[NM * DH];

// ---------------- helpers ----------------
__device__ __forceinline__ uint32_t smem_u32(const void* p) {
    uint32_t a;
    asm("{ .reg .u64 t; cvta.to.shared.u64 t, %1; cvt.u32.u64 %0, t; }" : "=r"(a) : "l"(p));
    return a;
}

__device__ __forceinline__ void ldm_x4(uint32_t* r, uint32_t addr) {
    asm volatile("ldmatrix.sync.aligned.m8n8.x4.shared.b16 {%0,%1,%2,%3}, [%4];"
                 : "=r"(r[0]), "=r"(r[1]), "=r"(r[2]), "=r"(r[3]) : "r"(addr));
}

__device__ __forceinline__ void mma16816(float* c, const uint32_t* a, uint32_t b0, uint32_t b1) {
    asm volatile(
        "mma.sync.aligned.m16n8k16.row.col.f32.f16.f16.f32 "
        "{%0,%1,%2,%3}, {%4,%5,%6,%7}, {%8,%9}, {%0,%1,%2,%3};"
        : "+f"(c[0]), "+f"(c[1]), "+f"(c[2]), "+f"(c[3])
        : "r"(a[0]), "r"(a[1]), "r"(a[2]), "r"(a[3]), "r"(b0), "r"(b1));
}

__device__ __forceinline__ void cpa16(uint32_t dst, const void* src) {
    asm volatile("cp.async.ca.shared.global [%0], [%1], 16;" :: "r"(dst), "l"(src));
}
__device__ __forceinline__ void cpa_commit() {
    asm volatile("cp.async.commit_group;" ::: "memory");
}
template<int N_>
__device__ __forceinline__ void cpa_wait() {
    asm volatile("cp.async.wait_group %0;" :: "n"(N_) : "memory");
}

// ---------------- fp16 tensor-core GEMM core v3 ----------------
// Block 128x128, BK=64, 4 warps (2x2), warp tile 64x64.
// 3-stage cp.async pipeline, XOR swizzle (slot' = g ^ (row&7)).
// nst: columns >= nst are not stored (must be even).
#define BM 128
#define BN 128
#define BK 64
#define T_B 16384
#define STAGE_B 32768
#define MM_SMEM (3 * STAGE_B)

template<bool OUT_F16, bool TANH_ACT>
__device__ __forceinline__ void mm_body(
    const h16* __restrict__ A, int lda,
    const h16* __restrict__ B, int ldb,
    float* __restrict__ Cf, h16* __restrict__ Ch, int ldc,
    const float* __restrict__ bias, int M, int N, int K, int nst)
{
    extern __shared__ char dsm[];
    const uint32_t u_sm = smem_u32(dsm);

    const int tid = threadIdx.x, lane = tid & 31, wid = tid >> 5;
    const int wr = wid >> 1, wc = wid & 1;
    const int m0 = blockIdx.y * BM, n0 = blockIdx.x * BN;

    float acc[4][8][4];
#pragma unroll
    for (int i = 0; i < 4; i++)
#pragma unroll
        for (int j = 0; j < 8; j++)
#pragma unroll
            for (int e = 0; e < 4; e++) acc[i][j][e] = 0.f;

    const int lrow = lane & 15;
    const int khalf = lane >> 4;
    const int xk = lrow & 7;
    const uint32_t rA = (uint32_t)((wr * 64 + lrow) * 128);
    const uint32_t rB = (uint32_t)(T_B) + (uint32_t)((wc * 64 + lrow) * 128);

    auto load_stage = [&](int st, int k0) {
        const uint32_t sbase = u_sm + (uint32_t)(st * STAGE_B);
#pragma unroll
        for (int i = 0; i < 16; i++) {
            int u = tid + i * 128;
            int v = u & 1023;
            int r = v >> 3;
            int g = v & 7;
            const h16* src;
            uint32_t toff;
            if (u < 1024) { int ga = m0 + r; if (ga > M - 1) ga = M - 1;
                            src = A + (long)ga * lda + k0 + g * 8; toff = 0; }
            else          { int gb = n0 + r; if (gb > N - 1) gb = N - 1;
                            src = B + (long)gb * ldb + k0 + g * 8; toff = T_B; }
            uint32_t doff = toff + (uint32_t)(r * 128) + (uint32_t)(((g ^ (r & 7)) << 4));
            cpa16(sbase + doff, src);
        }
    };

    const int nch = K / BK;
    load_stage(0, 0);  cpa_commit();
    load_stage(1, BK); cpa_commit();

    int st = 0;
    for (int ch = 0; ch < nch; ch++) {
        if (ch == nch - 1) cpa_wait<0>(); else cpa_wait<1>();
        __syncthreads();
        if (ch + 2 < nch) {
            int st2 = st + 2; if (st2 >= 3) st2 -= 3;
            load_stage(st2, (ch + 2) * BK);
            cpa_commit();
        }

        const uint32_t so = u_sm + (uint32_t)(st * STAGE_B);
#pragma unroll
        for (int ks = 0; ks < 4; ks++) {
            const uint32_t sw = (uint32_t)((((ks * 2) | khalf) ^ xk) << 4);
            uint32_t bh[4][4];
#pragma unroll
            for (int nt = 0; nt < 4; nt++)
                ldm_x4(bh[nt], so + rB + (uint32_t)(nt * 2048) + sw);
#pragma unroll
            for (int mi = 0; mi < 4; mi++) {
                uint32_t ah[4];
                ldm_x4(ah, so + rA + (uint32_t)(mi * 2048) + sw);
#pragma unroll
                for (int nt = 0; nt < 4; nt++) {
#pragma unroll
                    for (int j = 0; j < 2; j++)
                        mma16816(acc[mi][nt * 2 + j], ah, bh[nt][j], bh[nt][j + 2]);
                }
            }
        }
        if (++st == 3) st = 0;
    }

    const int er = m0 + wr * 64 + (lane >> 2);
    const int ec = n0 + wc * 64 + (lane & 3) * 2;
#pragma unroll
    for (int mi = 0; mi < 4; mi++) {
#pragma unroll
        for (int nj = 0; nj < 8; nj++) {
            const int col = ec + nj * 8;
            if (col >= nst) continue;
            float bv0 = 0.f, bv1 = 0.f;
            if (bias) { bv0 = bias[col]; bv1 = bias[col + 1]; }
#pragma unroll
            for (int half = 0; half < 2; half++) {
                const int row = er + mi * 16 + half * 8;
                if (row >= M) continue;
                float v0 = acc[mi][nj][half * 2 + 0] + bv0;
                float v1 = acc[mi][nj][half * 2 + 1] + bv1;
                if (TANH_ACT) { v0 = tanhf(v0); v1 = tanhf(v1); }
                const long base = (long)row * ldc + col;
                if (OUT_F16) {
                    __half2 h = __floats2half2_rn(v0, v1);
                    *reinterpret_cast<uint32_t*>(Ch + base) = reinterpret_cast<uint32_t&>(h);
                } else {
                    *reinterpret_cast<float2*>(Cf + base) = make_float2(v0, v1);
                }
            }
        }
    }
}

// generic batched wrapper
template<bool OUT_F16, bool TANH_ACT>
__global__ __launch_bounds__(128, 2)
void mmgemm(const h16* __restrict__ A, int lda, long sA,
            const h16* __restrict__ B, int ldb, long sB,
            float* __restrict__ Cf, h16* __restrict__ Ch,
            int ldc, long sC, const float* __restrict__ bias,
            int M, int N, int K, int nst)
{
    const long za = (long)blockIdx.z * sA, zb = (long)blockIdx.z * sB, zc = (long)blockIdx.z * sC;
    mm_body<OUT_F16, TANH_ACT>(
        A + za, lda, B + zb, ldb,
        Cf ? Cf + zc : nullptr, Ch ? Ch + zc : nullptr, ldc, bias, M, N, K, nst);
}

// fused G1 + G2 + G3: z=0 -> G1; z=1..8 -> G2 head; z=9..16 -> G3 head
__global__ __launch_bounds__(128, 2)
void mm_g123(const h16* __restrict__ enc, const h16* __restrict__ walT,
             h16* __restrict__ c1, const float* __restrict__ b_align,
             const h16* __restrict__ wq, const h16* __restrict__ wk, h16* __restrict__ bqk,
             const h16* __restrict__ wfT, const h16* __restrict__ wv, h16* __restrict__ wvfT)
{
    int z = blockIdx.z;
    if (z == 0) {
        mm_body<true, false>(enc, IMGD, walT, IMGD, nullptr, c1, DH, b_align, NR, DH, IMGD, DH);
    } else {
        if (blockIdx.y * BM >= DH) return;
        z -= 1;
        const int set = z >> 3, h = z & 7;
        const long co = (long)h * DH;
        const long cc = (long)h * DH * DH;
        if (set == 0)
            mm_body<true, false>(wq + co, HH * DH, wk + co, HH * DH,
                                 nullptr, bqk + cc, DH, nullptr, DH, DH, DH, DH);
        else
            mm_body<true, false>(wfT + co, HH * DH, wv + co, HH * DH,
                                 nullptr, wvfT + cc, DH, nullptr, DH, DH, DH, DH);
    }
}

// fused G4 + G5 -> fp16 KC / VC
__global__ __launch_bounds__(128, 2)
void mm_g45(const h16* __restrict__ c1, const h16* __restrict__ bqk,
            const h16* __restrict__ wvfT, h16* __restrict__ kc, h16* __restrict__ vc)
{
    int z = blockIdx.z;
    const long NRD = (long)NR * DH;
    const long HD2 = (long)DH * DH;
    if (z < HH)
        mm_body<true, false>(c1, DH, bqk + (long)z * HD2, DH,
                             nullptr, kc + (long)z * NRD, DH, nullptr, NR, DH, DH, DH);
    else {
        z -= HH;
        mm_body<true, false>(c1, DH, wvfT + (long)z * HD2, DH,
                             nullptr, vc + (long)z * NRD, DH, nullptr, NR, DH, DH, DH);
    }
}

// attention scores GEMM: per (n,h): S[128tok,49] = seq16 . KC16^T (raw, unscaled)
__global__ __launch_bounds__(128, 2)
void mm_scores(const h16* __restrict__ cat, const h16* __restrict__ kc, float* __restrict__ S)
{
    const int z = blockIdx.z, n = z >> 3, h = z & 7;
    mm_body<false, false>(cat + (long)n * LSEQ * 2 * DH, 2 * DH,
                          kc + ((long)h * NR + (long)n * RR) * DH, DH,
                          S + (long)z * LSEQ * 64, nullptr, 64, nullptr,
                          LSEQ, RR, DH, 64);
}

// ---------------- softmax: S -> P fp16 packed [n][tok][h*49+r], zero pad ----------------
__global__ __launch_bounds__(128) void softmax_p()
{
    const int z = blockIdx.x, n = z >> 3, h = z & 7;
    const int t = threadIdx.x;            // token
    const float* row = g_S + ((long)z * LSEQ + t) * 64;
    const float scale = rsqrtf((float)DH);
    float ex[RR];
    float mx = -1e30f;
#pragma unroll
    for (int r = 0; r < RR; r++) { float v = row[r] * scale; ex[r] = v; mx = fmaxf(mx, v); }
    float sum = 0.f;
#pragma unroll
    for (int r = 0; r < RR; r++) { float e = expf(ex[r] - mx); ex[r] = e; sum += e; }
    const float inv = 1.f / sum;
    h16* out = g_Pp + ((long)n * LSEQ + t) * KP + h * RR;
#pragma unroll
    for (int r = 0; r < RR; r++) out[r] = __float2half(ex[r] * inv);
    if (h == 0) {
        h16* pad = g_Pp + ((long)n * LSEQ + t) * KP + HH * RR;
        for (int i = 0; i < KP - HH * RR; i++) pad[i] = (h16)0.f;
    }
}

// ---------------- VC fp16 -> Vt [n][d][h*49+r] ----------------
__global__ void transpose_v()
{
    __shared__ h16 tile[32][33];
    const int z = blockIdx.z, n = z >> 3, h = z & 7;
    const int d0 = blockIdx.x * 32, r0 = blockIdx.y * 32;
    const int tx = threadIdx.x, ty = threadIdx.y;
    for (int i = ty; i < 32; i += 8) {
        int r = r0 + i;
        h16 v = (h16)0.f;
        if (r < RR) v = g_VC16[((long)h * NR + (long)n * RR + r) * DH + d0 + tx];
        tile[i][tx] = v;
    }
    __syncthreads();
    for (int i = ty; i < 32; i += 8) {
        int r = r0 + tx;
        if (r < RR)
            g_Vt[((long)n * DH + d0 + i) * KP + h * RR + r] = tile[tx][i];
    }
}

// ---------------- residual + LN -> cat[:, 768:1536] fp16 ----------------
__global__ __launch_bounds__(256) void ln_cat(const float* __restrict__ seq,
                                              const float* __restrict__ gam,
                                              const float* __restrict__ bet)
{
    const int wid = threadIdx.x >> 5, lane = threadIdx.x & 31;
    for (int rr = 0; rr < 2; rr++) {
        const long u = (long)blockIdx.x * 16 + wid * 2 + rr;
        const float* ao = g_attout + u * DH;
        const float* sq = seq + u * DH;
        float s = 0.f;
        for (int k = lane; k < DH; k += 32) s += ao[k] + sq[k];
        for (int o = 16; o; o >>= 1) s += __shfl_xor_sync(0xffffffffu, s, o);
        float mu = s * (1.f / DH);
        float v = 0.f;
        for (int k = lane; k < DH; k += 32) { float d = ao[k] + sq[k] - mu; v += d * d; }
        for (int o = 16; o; o >>= 1) v += __shfl_xor_sync(0xffffffffu, v, o);
        float rstd = rsqrtf(v * (1.f / DH) + 1e-5f);
        h16* dst = g_cat + u * 2 * DH + DH;
        for (int k = lane * 2; k < DH; k += 64) {
            float a = (ao[k]     + sq[k]     - mu) * rstd * gam[k]     + bet[k];
            float b = (ao[k + 1] + sq[k + 1] - mu) * rstd * gam[k + 1] + bet[k + 1];
            __half2 h = __floats2half2_rn(a, b);
            *reinterpret_cast<uint32_t*>(dst + k) = reinterpret_cast<uint32_t&>(h);
        }
    }
}

// ---------------- fp32 -> fp16 convert (vectorized) ----------------
__global__ void cvt_kernel(const float* __restrict__ in, h16* __restrict__ out, long n)
{
    long i0 = ((long)blockIdx.x * blockDim.x + threadIdx.x) * 4;
    long stride = (long)gridDim.x * blockDim.x * 4;
    for (long i = i0; i < n; i += stride) {
        float4 v = *reinterpret_cast<const float4*>(in + i);
        __half2 h0 = __floats2half2_rn(v.x, v.y);
        __half2 h1 = __floats2half2_rn(v.z, v.w);
        *reinterpret_cast<uint2*>(out + i) =
            make_uint2(reinterpret_cast<uint32_t&>(h0), reinterpret_cast<uint32_t&>(h1));
    }
}

// ---------------- fp32 [R,C] -> transposed fp16 [C,R] ----------------
__global__ void cvtT_kernel(const float* __restrict__ in, h16* __restrict__ out, int R, int C)
{
    __shared__ float t[32][33];
    int c0 = blockIdx.x * 32, r0 = blockIdx.y * 32;
    for (int i = threadIdx.y; i < 32; i += 8)
        t[i][threadIdx.x] = in[(long)(r0 + i) * C + c0 + threadIdx.x];
    __syncthreads();
    if (threadIdx.x < 16) {
        for (int i = threadIdx.y; i < 32; i += 8) {
            __half2 h = __floats2half2_rn(t[2 * threadIdx.x][i], t[2 * threadIdx.x + 1][i]);
            long o = (long)(c0 + i) * R + r0 + 2 * threadIdx.x;
            *reinterpret_cast<uint32_t*>(out + o) = reinterpret_cast<uint32_t&>(h);
        }
    }
}

// ---------------- seq -> cat[:, 0:768] fp16 ----------------
__global__ void seq_cvt_kernel(const float* __restrict__ seq)
{
    int row = blockIdx.x, t = threadIdx.x;
    for (int idx = t * 4; idx < DH; idx += 256 * 4) {
        float4 v = *reinterpret_cast<const float4*>(seq + (long)row * DH + idx);
        __half2 h0 = __floats2half2_rn(v.x, v.y);
        __half2 h1 = __floats2half2_rn(v.z, v.w);
        *reinterpret_cast<uint2*>(g_cat + (long)row * 2 * DH + idx) =
            make_uint2(reinterpret_cast<uint32_t&>(h0), reinterpret_cast<uint32_t&>(h1));
    }
}

// ---------------- unary score + masked softmax pooling (token-indexed) ----------------
__global__ void pool_kernel(const float* __restrict__ W_un, const float* __restrict__ b_un,
                            const int* __restrict__ starts, const int* __restrict__ ends)
{
    int sp = blockIdx.x, t = threadIdx.x;
    int lane = t & 31, w = t >> 5;
    int n = sp >> 3;
    int base = n * LSEQ + starts[sp];
    __shared__ float sS[JR];
    __shared__ float sProb[JR];

    for (int j = w; j < JR; j += 8) {
        int u = base + j; if (u > UU - 1) u = UU - 1;
        const float* fr = g_fused + (long)u * DH;
        float acc = 0.f;
        for (int k = lane; k < DH; k += 32) acc += fr[k] * W_un[k];
        for (int o = 16; o; o >>= 1) acc += __shfl_xor_sync(0xffffffffu, acc, o);
        if (lane == 0) sS[j] = acc + b_un[0];
    }
    __syncthreads();
    if (t == 0) {
        int width = ends[sp] - starts[sp] + 1;
        float mx = -1e30f;
        for (int j = 0; j < JR; j++) {
            float v = sS[j] + ((j < width) ? 0.f : -10000.f);
            sS[j] = v; mx = fmaxf(mx, v);
        }
        float sum = 0.f;
        for (int j = 0; j < JR; j++) { float e = expf(sS[j] - mx); sProb[j] = e; sum += e; }
        float inv = 1.f / sum;
        for (int j = 0; j < JR; j++) sProb[j] *= inv;
    }
    __syncthreads();
    for (int d = t; d < DH; d += 256) {
        float acc = 0.f;
        for (int j = 0; j < JR; j++) {
            int u = base + j; if (u > UU - 1) u = UU - 1;
            acc += sProb[j] * g_fused[(long)u * DH + d];
        }
        g_pool[(long)sp * DH + d] = acc;
    }
}

// ---------------- small fp32 sgemm (tiny dense layer only) ----------------
template<bool TRANSB, bool BIAS, bool TANH_ACT>
__global__ void sgemm(const float* __restrict__ A, int lda, long sA,
                      const float* __restrict__ B, int ldb, long sB,
                      float* __restrict__ C, int ldc, long sC,
                      const float* __restrict__ bias,
                      int M, int N, int K)
{
    A += (long)blockIdx.z * sA;
    B += (long)blockIdx.z * sB;
    C += (long)blockIdx.z * sC;
    __shared__ float As[16][128];
    __shared__ float Bs[16][128];
    const int tid = threadIdx.x;
    const int m0 = blockIdx.y * 128;
    const int n0 = blockIdx.x * 128;
    const int tx = tid & 15;
    const int ty = tid >> 4;
    float acc[8][8];
#pragma unroll
    for (int i = 0; i < 8; i++)
#pragma unroll
        for (int j = 0; j < 8; j++) acc[i][j] = 0.f;

    for (int k0 = 0; k0 < K; k0 += 16) {
#pragma unroll
        for (int i = 0; i < 2; i++) {
            int li = tid + i * 256;
            int row = li >> 2;
            int kk  = (li & 3) << 2;
            float4 v = make_float4(0.f, 0.f, 0.f, 0.f);
            if (m0 + row < M)
                v = *reinterpret_cast<const float4*>(&A[(long)(m0 + row) * lda + k0 + kk]);
            As[kk + 0][row] = v.x; As[kk + 1][row] = v.y;
            As[kk + 2][row] = v.z; As[kk + 3][row] = v.w;
        }
        if (!TRANSB) {
#pragma unroll
            for (int i = 0; i < 2; i++) {
                int li = tid + i * 256;
                int kr = li >> 5;
                int nn = (li & 31) << 2;
                float4 v = *reinterpret_cast<const float4*>(&B[(long)(k0 + kr) * ldb + n0 + nn]);
                *reinterpret_cast<float4*>(&Bs[kr][nn]) = v;
            }
        } else {
#pragma unroll
            for (int i = 0; i < 2; i++) {
                int li = tid + i * 256;
                int nr = li >> 2;
                int kk = (li & 3) << 2;
                float4 v = make_float4(0.f, 0.f, 0.f, 0.f);
                if (n0 + nr < N)
                    v = *reinterpret_cast<const float4*>(&B[(long)(n0 + nr) * ldb + k0 + kk]);
                Bs[kk + 0][nr] = v.x; Bs[kk + 1][nr] = v.y;
                Bs[kk + 2][nr] = v.z; Bs[kk + 3][nr] = v.w;
            }
        }
        __syncthreads();
#pragma unroll
        for (int k = 0; k < 16; k++) {
            float a[8], b[8];
#pragma unroll
            for (int i = 0; i < 8; i++) a[i] = As[k][ty * 8 + i];
#pragma unroll
            for (int j = 0; j < 8; j++) b[j] = Bs[k][tx * 8 + j];
#pragma unroll
            for (int i = 0; i < 8; i++)
#pragma unroll
                for (int j = 0; j < 8; j++) acc[i][j] += a[i] * b[j];
        }
        __syncthreads();
    }
#pragma unroll
    for (int i = 0; i < 8; i++) {
        int m = m0 + ty * 8 + i;
        if (m >= M) continue;
#pragma unroll
        for (int j = 0; j < 8; j++) {
            int n = n0 + tx * 8 + j;
            float v = acc[i][j];
            if (BIAS) v += bias[n];
            if (TANH_ACT) v = tanhf(v);
            C[(long)m * ldc + n] = v;
        }
    }
}

// ---------------- classifier ----------------
__global__ void cls_kernel(const float* __restrict__ W_cls, const float* __restrict__ b_cls,
                           float* __restrict__ out)
{
    int row = blockIdx.x, t = threadIdx.x;
    int lane = t & 31, c = t >> 5;
    const float* hr = g_hid + (long)row * DH;
    float acc = 0.f;
    for (int k = lane; k < DH; k += 32) acc += hr[k] * W_cls[k * 4 + c];
    for (int o = 16; o; o >>= 1) acc += __shfl_xor_sync(0xffffffffu, acc, o);
    if (lane == 0) out[row * 4 + c] = acc + b_cls[c];
}

// ---------------- launcher ----------------
extern "C" void kernel_launch(void* const* d_in, const int* in_sizes, int n_in,
                              void* d_out, int out_size)
{
    const float* enc_img  = (const float*)d_in[0];
    const float* seq      = (const float*)d_in[1];
    const int*   starts   = (const int*)d_in[3];
    const int*   ends     = (const int*)d_in[4];
    const float* W_align  = (const float*)d_in[5];
    const float* b_align  = (const float*)d_in[6];
    const float* Wq       = (const float*)d_in[7];
    const float* Wk       = (const float*)d_in[8];
    const float* Wv       = (const float*)d_in[9];
    const float* Wfc      = (const float*)d_in[10];
    const float* ln_g     = (const float*)d_in[11];
    const float* ln_b     = (const float*)d_in[12];
    const float* W_a1     = (const float*)d_in[13];
    const float* b_a1     = (const float*)d_in[14];
    const float* W_a2     = (const float*)d_in[15];
    const float* b_a2     = (const float*)d_in[16];
    const float* W_un     = (const float*)d_in[17];
    const float* b_un     = (const float*)d_in[18];
    const float* W_dense  = (const float*)d_in[19];
    const float* b_dense  = (const float*)d_in[20];
    const float* W_cls    = (const float*)d_in[21];
    const float* b_cls    = (const float*)d_in[22];

    h16 *enc, *walT, *wq, *wk, *wv, *wfT, *c1, *bqk, *wvfT, *kc, *vc, *cat, *wa1T, *f1, *wa2T;
    h16 *pp, *vt;
    float *pS, *pAO, *pFused, *pPool, *pHid;
    cudaGetSymbolAddress((void**)&enc,  g_enc);
    cudaGetSymbolAddress((void**)&walT, g_WalT);
    cudaGetSymbolAddress((void**)&wq,   g_Wq);
    cudaGetSymbolAddress((void**)&wk,   g_Wk);
    cudaGetSymbolAddress((void**)&wv,   g_Wv);
    cudaGetSymbolAddress((void**)&wfT,  g_WfcT);
    cudaGetSymbolAddress((void**)&c1,   g_C1);
    cudaGetSymbolAddress((void**)&bqk,  g_Bqk);
    cudaGetSymbolAddress((void**)&wvfT, g_WvfT);
    cudaGetSymbolAddress((void**)&kc,   g_KC16);
    cudaGetSymbolAddress((void**)&vc,   g_VC16);
    cudaGetSymbolAddress((void**)&pp,   g_Pp);
    cudaGetSymbolAddress((void**)&vt,   g_Vt);
    cudaGetSymbolAddress((void**)&pS,   g_S);
    cudaGetSymbolAddress((void**)&pAO,  g_attout);
    cudaGetSymbolAddress((void**)&cat,  g_cat);
    cudaGetSymbolAddress((void**)&wa1T, g_Wa1T);
    cudaGetSymbolAddress((void**)&f1,   g_f1);
    cudaGetSymbolAddress((void**)&wa2T, g_Wa2T);
    cudaGetSymbolAddress((void**)&pFused, g_fused);
    cudaGetSymbolAddress((void**)&pPool, g_pool);
    cudaGetSymbolAddress((void**)&pHid, g_hid);

    cudaFuncSetAttribute(mm_g123,   cudaFuncAttributeMaxDynamicSharedMemorySize, MM_SMEM);
    cudaFuncSetAttribute(mm_g45,    cudaFuncAttributeMaxDynamicSharedMemorySize, MM_SMEM);
    cudaFuncSetAttribute(mm_scores, cudaFuncAttributeMaxDynamicSharedMemorySize, MM_SMEM);
    cudaFuncSetAttribute(mmgemm<true,  true >, cudaFuncAttributeMaxDynamicSharedMemorySize, MM_SMEM);
    cudaFuncSetAttribute(mmgemm<false, false>, cudaFuncAttributeMaxDynamicSharedMemorySize, MM_SMEM);

    const dim3 blk(128);

    // ---- operand conversions (fp32 -> fp16) ----
    cvt_kernel<<<1024, 256>>>(enc_img, enc, (long)NR * IMGD);
    cvtT_kernel<<<dim3(DH / 32, IMGD / 32), dim3(32, 8)>>>(W_align, walT, IMGD, DH);
    cvt_kernel<<<1024, 256>>>(Wq, wq, (long)DH * HH * DH);
    cvt_kernel<<<1024, 256>>>(Wk, wk, (long)DH * HH * DH);
    cvt_kernel<<<1024, 256>>>(Wv, wv, (long)DH * HH * DH);
    cvtT_kernel<<<dim3(DH / 32, (HH * DH) / 32), dim3(32, 8)>>>(Wfc, wfT, HH * DH, DH);
    cvtT_kernel<<<dim3((2*DH) / 32, (2*DH) / 32), dim3(32, 8)>>>(W_a1, wa1T, 2*DH, 2*DH);
    cvtT_kernel<<<dim3(DH / 32, (2*DH) / 32), dim3(32, 8)>>>(W_a2, wa2T, 2*DH, DH);
    seq_cvt_kernel<<<UU, 256>>>(seq);

    // ---- G1 + G2 + G3 fused ----
    mm_g123<<<dim3(6, 7, 17), blk, MM_SMEM>>>(
        enc, walT, c1, b_align, wq, wk, bqk, wfT, wv, wvfT);

    // ---- G4 + G5 fused -> fp16 KC / VC ----
    mm_g45<<<dim3(6, 7, 16), blk, MM_SMEM>>>(c1, bqk, wvfT, kc, vc);

    // ---- attention (tensorized) ----
    transpose_v<<<dim3(DH / 32, 2, NB * HH), dim3(32, 8)>>>();
    mm_scores<<<dim3(1, 1, NB * HH), blk, MM_SMEM>>>(cat, kc, pS);
    softmax_p<<<NB * HH, 128>>>();
    mmgemm<false, false><<<dim3(6, 1, NB), blk, MM_SMEM>>>(
        pp, KP, (long)LSEQ * KP, vt, KP, (long)DH * KP,
        pAO, nullptr, DH, (long)LSEQ * DH, nullptr, LSEQ, DH, KP, DH);
    ln_cat<<<UU / 16, 256>>>(seq, ln_g, ln_b);

    // ---- fusion MLP on 2048 tokens ----
    mmgemm<true, true><<<dim3(12, 16, 1), blk, MM_SMEM>>>(
        cat, 2 * DH, 0, wa1T, 2 * DH, 0,
        nullptr, f1, 2 * DH, 0, b_a1, UU, 2 * DH, 2 * DH, 2 * DH);
    mmgemm<false, false><<<dim3(6, 16, 1), blk, MM_SMEM>>>(
        f1, 2 * DH, 0, wa2T, 2 * DH, 0,
        pFused, nullptr, DH, 0, b_a2, UU, DH, 2 * DH, DH);

    // ---- pooling + head ----
    pool_kernel<<<NM, 256>>>(W_un, b_un, starts, ends);
    sgemm<false, true, true><<<dim3(6, 1, 1), dim3(256)>>>(
        pPool, DH, 0, W_dense, DH, 0, pHid, DH, 0, b_dense, NM, DH, DH);
    cls_kernel<<<NM, 128>>>(W_cls, b_cls, (float*)d_out);
}

// round 11
// speedup vs baseline: 5.3609x; 1.2725x over previous
#include <cuda_runtime.h>
#include <cuda_fp16.h>
#include <math.h>
#include <stdint.h>

// ---------------- problem constants ----------------
#define NB    16
#define LSEQ  128
#define DH    768
#define MSP   8
#define HH    8
#define JR    30
#define RR    49
#define IMGD  2048
#define NM    128            // NB*MSP
#define UU    2048           // NB*LSEQ distinct tokens
#define NR    784            // NB*RR
#define KP    448            // padded concat-head K (8*49=392 -> 448)

typedef __half h16;

// ---------------- scratch (device globals; no cudaMalloc allowed) ----------------
__device__ h16 g_enc[NR * IMGD];
__device__ h16 g_WalT[DH * IMGD];
__device__ h16 g_Wq[DH * HH * DH];
__device__ h16 g_Wk[DH * HH * DH];
__device__ h16 g_Wv[DH * HH * DH];
__device__ h16 g_WfcT[DH * HH * DH];
__device__ h16 g_C1[NR * DH];
__device__ h16 g_Bqk[HH * DH * DH];
__device__ h16 g_WvfT[HH * DH * DH];
__device__ h16 g_KC16[HH * NR * DH];
__device__ h16 g_VC16[HH * NR * DH];
__device__ h16 g_Pp[NB * LSEQ * KP];           // probs, [n][tok][h*49+r], zero-padded
__device__ h16 g_Vt[NB * DH * KP];             // [n][d][h*49+r]
__device__ float g_attout[UU * DH];
__device__ h16 g_cat[UU * 2 * DH];
__device__ h16 g_Wa1T[2*DH * 2*DH];
__device__ h16 g_f1[UU * 2 * DH];
__device__ h16 g_Wa2T[DH * 2*DH];
__device__ h16 g_WdT[DH * DH];
__device__ float g_fused[UU * DH];
__device__ h16 g_pool16[NM * DH];
__device__ float g_hid[NM * DH];

// ---------------- helpers ----------------
__device__ __forceinline__ uint32_t smem_u32(const void* p) {
    uint32_t a;
    asm("{ .reg .u64 t; cvta.to.shared.u64 t, %1; cvt.u32.u64 %0, t; }" : "=r"(a) : "l"(p));
    return a;
}

__device__ __forceinline__ void ldm_x4(uint32_t* r, uint32_t addr) {
    asm volatile("ldmatrix.sync.aligned.m8n8.x4.shared.b16 {%0,%1,%2,%3}, [%4];"
                 : "=r"(r[0]), "=r"(r[1]), "=r"(r[2]), "=r"(r[3]) : "r"(addr));
}

__device__ __forceinline__ void mma16816(float* c, const uint32_t* a, uint32_t b0, uint32_t b1) {
    asm volatile(
        "mma.sync.aligned.m16n8k16.row.col.f32.f16.f16.f32 "
        "{%0,%1,%2,%3}, {%4,%5,%6,%7}, {%8,%9}, {%0,%1,%2,%3};"
        : "+f"(c[0]), "+f"(c[1]), "+f"(c[2]), "+f"(c[3])
        : "r"(a[0]), "r"(a[1]), "r"(a[2]), "r"(a[3]), "r"(b0), "r"(b1));
}

__device__ __forceinline__ void cpa16(uint32_t dst, const void* src) {
    asm volatile("cp.async.ca.shared.global [%0], [%1], 16;" :: "r"(dst), "l"(src));
}
__device__ __forceinline__ void cpa_commit() {
    asm volatile("cp.async.commit_group;" ::: "memory");
}
template<int N_>
__device__ __forceinline__ void cpa_wait() {
    asm volatile("cp.async.wait_group %0;" :: "n"(N_) : "memory");
}

// ---------------- fp16 tensor-core GEMM core v3 ----------------
#define BM 128
#define BN 128
#define BK 64
#define T_B 16384
#define STAGE_B 32768
#define MM_SMEM (3 * STAGE_B)

template<bool OUT_F16, bool TANH_ACT>
__device__ __forceinline__ void mm_body(
    const h16* __restrict__ A, int lda,
    const h16* __restrict__ B, int ldb,
    float* __restrict__ Cf, h16* __restrict__ Ch, int ldc,
    const float* __restrict__ bias, int M, int N, int K, int nst)
{
    extern __shared__ char dsm[];
    const uint32_t u_sm = smem_u32(dsm);

    const int tid = threadIdx.x, lane = tid & 31, wid = tid >> 5;
    const int wr = wid >> 1, wc = wid & 1;
    const int m0 = blockIdx.y * BM, n0 = blockIdx.x * BN;

    float acc[4][8][4];
#pragma unroll
    for (int i = 0; i < 4; i++)
#pragma unroll
        for (int j = 0; j < 8; j++)
#pragma unroll
            for (int e = 0; e < 4; e++) acc[i][j][e] = 0.f;

    const int lrow = lane & 15;
    const int khalf = lane >> 4;
    const int xk = lrow & 7;
    const uint32_t rA = (uint32_t)((wr * 64 + lrow) * 128);
    const uint32_t rB = (uint32_t)(T_B) + (uint32_t)((wc * 64 + lrow) * 128);

    auto load_stage = [&](int st, int k0) {
        const uint32_t sbase = u_sm + (uint32_t)(st * STAGE_B);
#pragma unroll
        for (int i = 0; i < 16; i++) {
            int u = tid + i * 128;
            int v = u & 1023;
            int r = v >> 3;
            int g = v & 7;
            const h16* src;
            uint32_t toff;
            if (u < 1024) { int ga = m0 + r; if (ga > M - 1) ga = M - 1;
                            src = A + (long)ga * lda + k0 + g * 8; toff = 0; }
            else          { int gb = n0 + r; if (gb > N - 1) gb = N - 1;
                            src = B + (long)gb * ldb + k0 + g * 8; toff = T_B; }
            uint32_t doff = toff + (uint32_t)(r * 128) + (uint32_t)(((g ^ (r & 7)) << 4));
            cpa16(sbase + doff, src);
        }
    };

    const int nch = K / BK;
    load_stage(0, 0);  cpa_commit();
    load_stage(1, BK); cpa_commit();

    int st = 0;
    for (int ch = 0; ch < nch; ch++) {
        if (ch == nch - 1) cpa_wait<0>(); else cpa_wait<1>();
        __syncthreads();
        if (ch + 2 < nch) {
            int st2 = st + 2; if (st2 >= 3) st2 -= 3;
            load_stage(st2, (ch + 2) * BK);
            cpa_commit();
        }

        const uint32_t so = u_sm + (uint32_t)(st * STAGE_B);
#pragma unroll
        for (int ks = 0; ks < 4; ks++) {
            const uint32_t sw = (uint32_t)((((ks * 2) | khalf) ^ xk) << 4);
            uint32_t bh[4][4];
#pragma unroll
            for (int nt = 0; nt < 4; nt++)
                ldm_x4(bh[nt], so + rB + (uint32_t)(nt * 2048) + sw);
#pragma unroll
            for (int mi = 0; mi < 4; mi++) {
                uint32_t ah[4];
                ldm_x4(ah, so + rA + (uint32_t)(mi * 2048) + sw);
#pragma unroll
                for (int nt = 0; nt < 4; nt++) {
#pragma unroll
                    for (int j = 0; j < 2; j++)
                        mma16816(acc[mi][nt * 2 + j], ah, bh[nt][j], bh[nt][j + 2]);
                }
            }
        }
        if (++st == 3) st = 0;
    }

    const int er = m0 + wr * 64 + (lane >> 2);
    const int ec = n0 + wc * 64 + (lane & 3) * 2;
#pragma unroll
    for (int mi = 0; mi < 4; mi++) {
#pragma unroll
        for (int nj = 0; nj < 8; nj++) {
            const int col = ec + nj * 8;
            if (col >= nst) continue;
            float bv0 = 0.f, bv1 = 0.f;
            if (bias) { bv0 = bias[col]; bv1 = bias[col + 1]; }
#pragma unroll
            for (int half = 0; half < 2; half++) {
                const int row = er + mi * 16 + half * 8;
                if (row >= M) continue;
                float v0 = acc[mi][nj][half * 2 + 0] + bv0;
                float v1 = acc[mi][nj][half * 2 + 1] + bv1;
                if (TANH_ACT) { v0 = tanhf(v0); v1 = tanhf(v1); }
                const long base = (long)row * ldc + col;
                if (OUT_F16) {
                    __half2 h = __floats2half2_rn(v0, v1);
                    *reinterpret_cast<uint32_t*>(Ch + base) = reinterpret_cast<uint32_t&>(h);
                } else {
                    *reinterpret_cast<float2*>(Cf + base) = make_float2(v0, v1);
                }
            }
        }
    }
}

// generic batched wrapper
template<bool OUT_F16, bool TANH_ACT>
__global__ __launch_bounds__(128, 2)
void mmgemm(const h16* __restrict__ A, int lda, long sA,
            const h16* __restrict__ B, int ldb, long sB,
            float* __restrict__ Cf, h16* __restrict__ Ch,
            int ldc, long sC, const float* __restrict__ bias,
            int M, int N, int K, int nst)
{
    const long za = (long)blockIdx.z * sA, zb = (long)blockIdx.z * sB, zc = (long)blockIdx.z * sC;
    mm_body<OUT_F16, TANH_ACT>(
        A + za, lda, B + zb, ldb,
        Cf ? Cf + zc : nullptr, Ch ? Ch + zc : nullptr, ldc, bias, M, N, K, nst);
}

// fused G1 + G2 + G3: z=0 -> G1; z=1..8 -> G2 head; z=9..16 -> G3 head
__global__ __launch_bounds__(128, 2)
void mm_g123(const h16* __restrict__ enc, const h16* __restrict__ walT,
             h16* __restrict__ c1, const float* __restrict__ b_align,
             const h16* __restrict__ wq, const h16* __restrict__ wk, h16* __restrict__ bqk,
             const h16* __restrict__ wfT, const h16* __restrict__ wv, h16* __restrict__ wvfT)
{
    int z = blockIdx.z;
    if (z == 0) {
        mm_body<true, false>(enc, IMGD, walT, IMGD, nullptr, c1, DH, b_align, NR, DH, IMGD, DH);
    } else {
        if (blockIdx.y * BM >= DH) return;
        z -= 1;
        const int set = z >> 3, h = z & 7;
        const long co = (long)h * DH;
        const long cc = (long)h * DH * DH;
        if (set == 0)
            mm_body<true, false>(wq + co, HH * DH, wk + co, HH * DH,
                                 nullptr, bqk + cc, DH, nullptr, DH, DH, DH, DH);
        else
            mm_body<true, false>(wfT + co, HH * DH, wv + co, HH * DH,
                                 nullptr, wvfT + cc, DH, nullptr, DH, DH, DH, DH);
    }
}

// fused G4 + G5 -> fp16 KC / VC
__global__ __launch_bounds__(128, 2)
void mm_g45(const h16* __restrict__ c1, const h16* __restrict__ bqk,
            const h16* __restrict__ wvfT, h16* __restrict__ kc, h16* __restrict__ vc)
{
    int z = blockIdx.z;
    const long NRD = (long)NR * DH;
    const long HD2 = (long)DH * DH;
    if (z < HH)
        mm_body<true, false>(c1, DH, bqk + (long)z * HD2, DH,
                             nullptr, kc + (long)z * NRD, DH, nullptr, NR, DH, DH, DH);
    else {
        z -= HH;
        mm_body<true, false>(c1, DH, wvfT + (long)z * HD2, DH,
                             nullptr, vc + (long)z * NRD, DH, nullptr, NR, DH, DH, DH);
    }
}

// ---------------- scores GEMM + fused softmax -> packed fp16 P ----------------
// one CTA per (n,h): S[128,49] = seq16 . KC16^T, softmax rows, write g_Pp.
__global__ __launch_bounds__(128, 2)
void mm_scores_softmax(const h16* __restrict__ cat, const h16* __restrict__ kc)
{
    extern __shared__ char dsm[];
    const uint32_t u_sm = smem_u32(dsm);
    const int z = blockIdx.z, n = z >> 3, hh = z & 7;
    const h16* A = cat + (long)n * LSEQ * 2 * DH;
    const h16* B = kc + ((long)hh * NR + (long)n * RR) * DH;
    const int lda = 2 * DH, ldb = DH;
    const int M = LSEQ, N = RR, K = DH;

    const int tid = threadIdx.x, lane = tid & 31, wid = tid >> 5;
    const int wr = wid >> 1, wc = wid & 1;

    float acc[4][8][4];
#pragma unroll
    for (int i = 0; i < 4; i++)
#pragma unroll
        for (int j = 0; j < 8; j++)
#pragma unroll
            for (int e = 0; e < 4; e++) acc[i][j][e] = 0.f;

    const int lrow = lane & 15;
    const int khalf = lane >> 4;
    const int xk = lrow & 7;
    const uint32_t rA = (uint32_t)((wr * 64 + lrow) * 128);
    const uint32_t rB = (uint32_t)(T_B) + (uint32_t)((wc * 64 + lrow) * 128);

    auto load_stage = [&](int st, int k0) {
        const uint32_t sbase = u_sm + (uint32_t)(st * STAGE_B);
#pragma unroll
        for (int i = 0; i < 16; i++) {
            int u = tid + i * 128;
            int v = u & 1023;
            int r = v >> 3;
            int g = v & 7;
            const h16* src;
            uint32_t toff;
            if (u < 1024) { src = A + (long)r * lda + k0 + g * 8; toff = 0; }
            else          { int gb = r; if (gb > N - 1) gb = N - 1;
                            src = B + (long)gb * ldb + k0 + g * 8; toff = T_B; }
            uint32_t doff = toff + (uint32_t)(r * 128) + (uint32_t)(((g ^ (r & 7)) << 4));
            cpa16(sbase + doff, src);
        }
    };

    const int nch = K / BK;
    load_stage(0, 0);  cpa_commit();
    load_stage(1, BK); cpa_commit();

    int st = 0;
    for (int ch = 0; ch < nch; ch++) {
        if (ch == nch - 1) cpa_wait<0>(); else cpa_wait<1>();
        __syncthreads();
        if (ch + 2 < nch) {
            int st2 = st + 2; if (st2 >= 3) st2 -= 3;
            load_stage(st2, (ch + 2) * BK);
            cpa_commit();
        }
        const uint32_t so = u_sm + (uint32_t)(st * STAGE_B);
#pragma unroll
        for (int ks = 0; ks < 4; ks++) {
            const uint32_t sw = (uint32_t)((((ks * 2) | khalf) ^ xk) << 4);
            uint32_t bh[4][4];
#pragma unroll
            for (int nt = 0; nt < 4; nt++)
                ldm_x4(bh[nt], so + rB + (uint32_t)(nt * 2048) + sw);
#pragma unroll
            for (int mi = 0; mi < 4; mi++) {
                uint32_t ah[4];
                ldm_x4(ah, so + rA + (uint32_t)(mi * 2048) + sw);
#pragma unroll
                for (int nt = 0; nt < 4; nt++) {
#pragma unroll
                    for (int j = 0; j < 2; j++)
                        mma16816(acc[mi][nt * 2 + j], ah, bh[nt][j], bh[nt][j + 2]);
                }
            }
        }
        if (++st == 3) st = 0;
    }

    // epilogue -> smem S[128][65]
    float* S = reinterpret_cast<float*>(dsm);
    __syncthreads();          // all compute done before reusing smem
    if (wc == 0) {
        const int er0 = wr * 64 + (lane >> 2);
        const int ec0 = (lane & 3) * 2;
#pragma unroll
        for (int mi = 0; mi < 4; mi++) {
#pragma unroll
            for (int nj = 0; nj < 8; nj++) {
                const int col = ec0 + nj * 8;
#pragma unroll
                for (int half = 0; half < 2; half++) {
                    const int row = er0 + mi * 16 + half * 8;
                    S[row * 65 + col]     = acc[mi][nj][half * 2 + 0];
                    S[row * 65 + col + 1] = acc[mi][nj][half * 2 + 1];
                }
            }
        }
    }
    __syncthreads();

    // softmax per token row
    const int t = tid;        // 0..127 = token
    const float scale = rsqrtf((float)DH);
    float ex[RR];
    float mx = -1e30f;
#pragma unroll
    for (int r = 0; r < RR; r++) { float v = S[t * 65 + r] * scale; ex[r] = v; mx = fmaxf(mx, v); }
    float sum = 0.f;
#pragma unroll
    for (int r = 0; r < RR; r++) { float e = expf(ex[r] - mx); ex[r] = e; sum += e; }
    const float inv = 1.f / sum;
    h16* out = g_Pp + ((long)n * LSEQ + t) * KP + hh * RR;
#pragma unroll
    for (int r = 0; r < RR; r++) out[r] = __float2half(ex[r] * inv);
    if (hh == 0) {
        h16* pad = g_Pp + ((long)n * LSEQ + t) * KP + HH * RR;
        for (int i = 0; i < KP - HH * RR; i++) pad[i] = (h16)0.f;
    }
}

// ---------------- VC fp16 -> Vt [n][d][h*49+r] ----------------
__global__ void transpose_v()
{
    __shared__ h16 tile[32][33];
    const int z = blockIdx.z, n = z >> 3, h = z & 7;
    const int d0 = blockIdx.x * 32, r0 = blockIdx.y * 32;
    const int tx = threadIdx.x, ty = threadIdx.y;
    for (int i = ty; i < 32; i += 8) {
        int r = r0 + i;
        h16 v = (h16)0.f;
        if (r < RR) v = g_VC16[((long)h * NR + (long)n * RR + r) * DH + d0 + tx];
        tile[i][tx] = v;
    }
    __syncthreads();
    for (int i = ty; i < 32; i += 8) {
        int r = r0 + tx;
        if (r < RR)
            g_Vt[((long)n * DH + d0 + i) * KP + h * RR + r] = tile[tx][i];
    }
}

// ---------------- residual + LN -> cat[:, 768:1536] fp16 ----------------
__global__ __launch_bounds__(256) void ln_cat(const float* __restrict__ seq,
                                              const float* __restrict__ gam,
                                              const float* __restrict__ bet)
{
    const int wid = threadIdx.x >> 5, lane = threadIdx.x & 31;
    for (int rr = 0; rr < 2; rr++) {
        const long u = (long)blockIdx.x * 16 + wid * 2 + rr;
        const float* ao = g_attout + u * DH;
        const float* sq = seq + u * DH;
        float s = 0.f;
        for (int k = lane; k < DH; k += 32) s += ao[k] + sq[k];
        for (int o = 16; o; o >>= 1) s += __shfl_xor_sync(0xffffffffu, s, o);
        float mu = s * (1.f / DH);
        float v = 0.f;
        for (int k = lane; k < DH; k += 32) { float d = ao[k] + sq[k] - mu; v += d * d; }
        for (int o = 16; o; o >>= 1) v += __shfl_xor_sync(0xffffffffu, v, o);
        float rstd = rsqrtf(v * (1.f / DH) + 1e-5f);
        h16* dst = g_cat + u * 2 * DH + DH;
        for (int k = lane * 2; k < DH; k += 64) {
            float a = (ao[k]     + sq[k]     - mu) * rstd * gam[k]     + bet[k];
            float b = (ao[k + 1] + sq[k + 1] - mu) * rstd * gam[k + 1] + bet[k + 1];
            __half2 h = __floats2half2_rn(a, b);
            *reinterpret_cast<uint32_t*>(dst + k) = reinterpret_cast<uint32_t&>(h);
        }
    }
}

// ---------------- merged straight conversions (enc, Wq, Wk, Wv) ----------------
#define N_ENC (NR * IMGD)                   // 1605632
#define N_W   (DH * HH * DH)                // 4718592
__global__ void cvt_all(const float* __restrict__ enc_img, const float* __restrict__ Wq,
                        const float* __restrict__ Wk, const float* __restrict__ Wv)
{
    const long total = (long)N_ENC + 3L * N_W;
    long i0 = ((long)blockIdx.x * blockDim.x + threadIdx.x) * 4;
    long stride = (long)gridDim.x * blockDim.x * 4;
    for (long i = i0; i < total; i += stride) {
        const float* src; h16* dst; long off;
        if (i < N_ENC)                { src = enc_img; dst = g_enc; off = i; }
        else if (i < N_ENC + N_W)     { src = Wq; dst = g_Wq; off = i - N_ENC; }
        else if (i < N_ENC + 2L*N_W)  { src = Wk; dst = g_Wk; off = i - N_ENC - N_W; }
        else                          { src = Wv; dst = g_Wv; off = i - N_ENC - 2L*N_W; }
        float4 v = *reinterpret_cast<const float4*>(src + off);
        __half2 h0 = __floats2half2_rn(v.x, v.y);
        __half2 h1 = __floats2half2_rn(v.z, v.w);
        *reinterpret_cast<uint2*>(dst + off) =
            make_uint2(reinterpret_cast<uint32_t&>(h0), reinterpret_cast<uint32_t&>(h1));
    }
}

// ---------------- merged transposed conversions ----------------
// segments: 0 W_align(2048x768) 1 Wfc(6144x768) 2 W_a1(1536x1536) 3 W_a2(1536x768) 4 W_dense(768x768)
__global__ void cvtT_all(const float* __restrict__ W_align, const float* __restrict__ Wfc,
                         const float* __restrict__ W_a1, const float* __restrict__ W_a2,
                         const float* __restrict__ W_dense)
{
    __shared__ float t[32][33];
    int b = blockIdx.x;
    const float* in; h16* out; int R, C, local;
    if (b < 1536)       { in = W_align; out = g_WalT; R = 2048; C = 768;  local = b; }
    else if (b < 6144)  { in = Wfc;     out = g_WfcT; R = 6144; C = 768;  local = b - 1536; }
    else if (b < 8448)  { in = W_a1;    out = g_Wa1T; R = 1536; C = 1536; local = b - 6144; }
    else if (b < 9600)  { in = W_a2;    out = g_Wa2T; R = 1536; C = 768;  local = b - 8448; }
    else                { in = W_dense; out = g_WdT;  R = 768;  C = 768;  local = b - 9600; }
    const int tx = C / 32;
    const int cx = local % tx, ry = local / tx;
    const int c0 = cx * 32, r0 = ry * 32;
    for (int i = threadIdx.y; i < 32; i += 8)
        t[i][threadIdx.x] = in[(long)(r0 + i) * C + c0 + threadIdx.x];
    __syncthreads();
    if (threadIdx.x < 16) {
        for (int i = threadIdx.y; i < 32; i += 8) {
            __half2 h = __floats2half2_rn(t[2 * threadIdx.x][i], t[2 * threadIdx.x + 1][i]);
            long o = (long)(c0 + i) * R + r0 + 2 * threadIdx.x;
            *reinterpret_cast<uint32_t*>(out + o) = reinterpret_cast<uint32_t&>(h);
        }
    }
}

// ---------------- seq -> cat[:, 0:768] fp16 (grid-stride) ----------------
__global__ void seq_cvt_kernel(const float* __restrict__ seq)
{
    long i0 = ((long)blockIdx.x * blockDim.x + threadIdx.x) * 4;
    long stride = (long)gridDim.x * blockDim.x * 4;
    const long total = (long)UU * DH;
    for (long i = i0; i < total; i += stride) {
        long row = i / DH, col = i - row * DH;
        float4 v = *reinterpret_cast<const float4*>(seq + i);
        __half2 h0 = __floats2half2_rn(v.x, v.y);
        __half2 h1 = __floats2half2_rn(v.z, v.w);
        *reinterpret_cast<uint2*>(g_cat + row * 2 * DH + col) =
            make_uint2(reinterpret_cast<uint32_t&>(h0), reinterpret_cast<uint32_t&>(h1));
    }
}

// ---------------- unary score + masked softmax pooling -> fp16 pool ----------------
__global__ void pool_kernel(const float* __restrict__ W_un, const float* __restrict__ b_un,
                            const int* __restrict__ starts, const int* __restrict__ ends)
{
    int sp = blockIdx.x, t = threadIdx.x;
    int lane = t & 31, w = t >> 5;
    int n = sp >> 3;
    int base = n * LSEQ + starts[sp];
    __shared__ float sS[JR];
    __shared__ float sProb[JR];

    for (int j = w; j < JR; j += 8) {
        int u = base + j; if (u > UU - 1) u = UU - 1;
        const float* fr = g_fused + (long)u * DH;
        float acc = 0.f;
        for (int k = lane; k < DH; k += 32) acc += fr[k] * W_un[k];
        for (int o = 16; o; o >>= 1) acc += __shfl_xor_sync(0xffffffffu, acc, o);
        if (lane == 0) sS[j] = acc + b_un[0];
    }
    __syncthreads();
    if (t == 0) {
        int width = ends[sp] - starts[sp] + 1;
        float mx = -1e30f;
        for (int j = 0; j < JR; j++) {
            float v = sS[j] + ((j < width) ? 0.f : -10000.f);
            sS[j] = v; mx = fmaxf(mx, v);
        }
        float sum = 0.f;
        for (int j = 0; j < JR; j++) { float e = expf(sS[j] - mx); sProb[j] = e; sum += e; }
        float inv = 1.f / sum;
        for (int j = 0; j < JR; j++) sProb[j] *= inv;
    }
    __syncthreads();
    for (int d = t; d < DH; d += 256) {
        float acc = 0.f;
        for (int j = 0; j < JR; j++) {
            int u = base + j; if (u > UU - 1) u = UU - 1;
            acc += sProb[j] * g_fused[(long)u * DH + d];
        }
        g_pool16[(long)sp * DH + d] = __float2half(acc);
    }
}

// ---------------- classifier ----------------
__global__ void cls_kernel(const float* __restrict__ W_cls, const float* __restrict__ b_cls,
                           float* __restrict__ out)
{
    int row = blockIdx.x, t = threadIdx.x;
    int lane = t & 31, c = t >> 5;
    const float* hr = g_hid + (long)row * DH;
    float acc = 0.f;
    for (int k = lane; k < DH; k += 32) acc += hr[k] * W_cls[k * 4 + c];
    for (int o = 16; o; o >>= 1) acc += __shfl_xor_sync(0xffffffffu, acc, o);
    if (lane == 0) out[row * 4 + c] = acc + b_cls[c];
}

// ---------------- launcher ----------------
extern "C" void kernel_launch(void* const* d_in, const int* in_sizes, int n_in,
                              void* d_out, int out_size)
{
    const float* enc_img  = (const float*)d_in[0];
    const float* seq      = (const float*)d_in[1];
    const int*   starts   = (const int*)d_in[3];
    const int*   ends     = (const int*)d_in[4];
    const float* W_align  = (const float*)d_in[5];
    const float* b_align  = (const float*)d_in[6];
    const float* Wq       = (const float*)d_in[7];
    const float* Wk       = (const float*)d_in[8];
    const float* Wv       = (const float*)d_in[9];
    const float* Wfc      = (const float*)d_in[10];
    const float* ln_g     = (const float*)d_in[11];
    const float* ln_b     = (const float*)d_in[12];
    const float* W_a1     = (const float*)d_in[13];
    const float* b_a1     = (const float*)d_in[14];
    const float* W_a2     = (const float*)d_in[15];
    const float* b_a2     = (const float*)d_in[16];
    const float* W_un     = (const float*)d_in[17];
    const float* b_un     = (const float*)d_in[18];
    const float* W_dense  = (const float*)d_in[19];
    const float* b_dense  = (const float*)d_in[20];
    const float* W_cls    = (const float*)d_in[21];
    const float* b_cls    = (const float*)d_in[22];

    h16 *enc, *walT, *wq, *wk, *wv, *wfT, *c1, *bqk, *wvfT, *kc, *vc, *cat, *wa1T, *f1, *wa2T;
    h16 *pp, *vt, *wdT, *pool16;
    float *pAO, *pFused, *pHid;
    cudaGetSymbolAddress((void**)&enc,  g_enc);
    cudaGetSymbolAddress((void**)&walT, g_WalT);
    cudaGetSymbolAddress((void**)&wq,   g_Wq);
    cudaGetSymbolAddress((void**)&wk,   g_Wk);
    cudaGetSymbolAddress((void**)&wv,   g_Wv);
    cudaGetSymbolAddress((void**)&wfT,  g_WfcT);
    cudaGetSymbolAddress((void**)&c1,   g_C1);
    cudaGetSymbolAddress((void**)&bqk,  g_Bqk);
    cudaGetSymbolAddress((void**)&wvfT, g_WvfT);
    cudaGetSymbolAddress((void**)&kc,   g_KC16);
    cudaGetSymbolAddress((void**)&vc,   g_VC16);
    cudaGetSymbolAddress((void**)&pp,   g_Pp);
    cudaGetSymbolAddress((void**)&vt,   g_Vt);
    cudaGetSymbolAddress((void**)&pAO,  g_attout);
    cudaGetSymbolAddress((void**)&cat,  g_cat);
    cudaGetSymbolAddress((void**)&wa1T, g_Wa1T);
    cudaGetSymbolAddress((void**)&f1,   g_f1);
    cudaGetSymbolAddress((void**)&wa2T, g_Wa2T);
    cudaGetSymbolAddress((void**)&wdT,  g_WdT);
    cudaGetSymbolAddress((void**)&pool16, g_pool16);
    cudaGetSymbolAddress((void**)&pFused, g_fused);
    cudaGetSymbolAddress((void**)&pHid, g_hid);

    cudaFuncSetAttribute(mm_g123, cudaFuncAttributeMaxDynamicSharedMemorySize, MM_SMEM);
    cudaFuncSetAttribute(mm_g45,  cudaFuncAttributeMaxDynamicSharedMemorySize, MM_SMEM);
    cudaFuncSetAttribute(mm_scores_softmax, cudaFuncAttributeMaxDynamicSharedMemorySize, MM_SMEM);
    cudaFuncSetAttribute(mmgemm<true,  true >, cudaFuncAttributeMaxDynamicSharedMemorySize, MM_SMEM);
    cudaFuncSetAttribute(mmgemm<false, false>, cudaFuncAttributeMaxDynamicSharedMemorySize, MM_SMEM);
    cudaFuncSetAttribute(mmgemm<false, true >, cudaFuncAttributeMaxDynamicSharedMemorySize, MM_SMEM);

    const dim3 blk(128);

    // ---- operand conversions (merged) ----
    cvt_all<<<2048, 256>>>(enc_img, Wq, Wk, Wv);
    cvtT_all<<<10176, dim3(32, 8)>>>(W_align, Wfc, W_a1, W_a2, W_dense);
    seq_cvt_kernel<<<1536, 256>>>(seq);

    // ---- G1 + G2 + G3 fused ----
    mm_g123<<<dim3(6, 7, 17), blk, MM_SMEM>>>(
        enc, walT, c1, b_align, wq, wk, bqk, wfT, wv, wvfT);

    // ---- G4 + G5 fused -> fp16 KC / VC ----
    mm_g45<<<dim3(6, 7, 16), blk, MM_SMEM>>>(c1, bqk, wvfT, kc, vc);

    // ---- attention (tensorized, softmax fused into scores) ----
    transpose_v<<<dim3(DH / 32, 2, NB * HH), dim3(32, 8)>>>();
    mm_scores_softmax<<<dim3(1, 1, NB * HH), blk, MM_SMEM>>>(cat, kc);
    mmgemm<false, false><<<dim3(6, 1, NB), blk, MM_SMEM>>>(
        pp, KP, (long)LSEQ * KP, vt, KP, (long)DH * KP,
        pAO, nullptr, DH, (long)LSEQ * DH, nullptr, LSEQ, DH, KP, DH);
    ln_cat<<<UU / 16, 256>>>(seq, ln_g, ln_b);

    // ---- fusion MLP on 2048 tokens ----
    mmgemm<true, true><<<dim3(12, 16, 1), blk, MM_SMEM>>>(
        cat, 2 * DH, 0, wa1T, 2 * DH, 0,
        nullptr, f1, 2 * DH, 0, b_a1, UU, 2 * DH, 2 * DH, 2 * DH);
    mmgemm<false, false><<<dim3(6, 16, 1), blk, MM_SMEM>>>(
        f1, 2 * DH, 0, wa2T, 2 * DH, 0,
        pFused, nullptr, DH, 0, b_a2, UU, DH, 2 * DH, DH);

    // ---- pooling + head (dense on tensor cores) ----
    pool_kernel<<<NM, 256>>>(W_un, b_un, starts, ends);
    mmgemm<false, true><<<dim3(6, 1, 1), blk, MM_SMEM>>>(
        pool16, DH, 0, wdT, DH, 0,
        pHid, nullptr, DH, 0, b_dense, NM, DH, DH, DH);
    cls_kernel<<<NM, 128>>>(W_cls, b_cls, (float*)d_out);
}

// round 12
// speedup vs baseline: 5.6760x; 1.0588x over previous
#include <cuda_runtime.h>
#include <cuda_fp16.h>
#include <math.h>
#include <stdint.h>

// ---------------- problem constants ----------------
#define NB    16
#define LSEQ  128
#define DH    768
#define MSP   8
#define HH    8
#define JR    30
#define RR    49
#define IMGD  2048
#define NM    128            // NB*MSP
#define UU    2048           // NB*LSEQ distinct tokens
#define NR    784            // NB*RR
#define KP    448            // padded concat-head K (8*49=392 -> 448)

typedef __half h16;

// ---------------- scratch (device globals; no cudaMalloc allowed) ----------------
__device__ h16 g_enc[NR * IMGD];
__device__ h16 g_WalT[DH * IMGD];
__device__ h16 g_Wq[DH * HH * DH];
__device__ h16 g_Wk[DH * HH * DH];
__device__ h16 g_Wv[DH * HH * DH];
__device__ h16 g_WfcT[DH * HH * DH];
__device__ h16 g_C1[NR * DH];
__device__ h16 g_Bqk[HH * DH * DH];
__device__ h16 g_WvfT[HH * DH * DH];
__device__ h16 g_KC16[HH * NR * DH];
__device__ h16 g_VC16[HH * NR * DH];
__device__ h16 g_Pp[NB * LSEQ * KP];           // probs, [n][tok][h*49+r], zero-padded
__device__ h16 g_Vt[NB * DH * KP];             // [n][d][h*49+r]
__device__ float g_attout[UU * DH];
__device__ h16 g_cat[UU * 2 * DH];
__device__ h16 g_Wa1T[2*DH * 2*DH];
__device__ h16 g_f1[UU * 2 * DH];
__device__ h16 g_Wa2T[DH * 2*DH];
__device__ h16 g_WdT[DH * DH];
__device__ float g_fused[UU * DH];
__device__ h16 g_pool16[NM * DH];
__device__ float g_hid[NM * DH];

// ---------------- helpers ----------------
__device__ __forceinline__ uint32_t smem_u32(const void* p) {
    uint32_t a;
    asm("{ .reg .u64 t; cvta.to.shared.u64 t, %1; cvt.u32.u64 %0, t; }" : "=r"(a) : "l"(p));
    return a;
}

__device__ __forceinline__ void ldm_x4(uint32_t* r, uint32_t addr) {
    asm volatile("ldmatrix.sync.aligned.m8n8.x4.shared.b16 {%0,%1,%2,%3}, [%4];"
                 : "=r"(r[0]), "=r"(r[1]), "=r"(r[2]), "=r"(r[3]) : "r"(addr));
}

__device__ __forceinline__ void mma16816(float* c, const uint32_t* a, uint32_t b0, uint32_t b1) {
    asm volatile(
        "mma.sync.aligned.m16n8k16.row.col.f32.f16.f16.f32 "
        "{%0,%1,%2,%3}, {%4,%5,%6,%7}, {%8,%9}, {%0,%1,%2,%3};"
        : "+f"(c[0]), "+f"(c[1]), "+f"(c[2]), "+f"(c[3])
        : "r"(a[0]), "r"(a[1]), "r"(a[2]), "r"(a[3]), "r"(b0), "r"(b1));
}

__device__ __forceinline__ void cpa16(uint32_t dst, const void* src) {
    asm volatile("cp.async.ca.shared.global [%0], [%1], 16;" :: "r"(dst), "l"(src));
}
__device__ __forceinline__ void cpa_commit() {
    asm volatile("cp.async.commit_group;" ::: "memory");
}
template<int N_>
__device__ __forceinline__ void cpa_wait() {
    asm volatile("cp.async.wait_group %0;" :: "n"(N_) : "memory");
}

// ---------------- fp16 tensor-core GEMM core v4 ----------------
// Block 128x128, BK=64, 8 warps (4x2), warp tile 32x64, 256 threads.
// 2-stage cp.async pipeline (wait -> sync -> prefetch -> compute), XOR swizzle.
#define BM 128
#define BN 128
#define BK 64
#define T_B 16384
#define STAGE_B 32768
#define MM_SMEM (2 * STAGE_B)                  // 65536

template<bool OUT_F16, bool TANH_ACT>
__device__ __forceinline__ void mm_body(
    const h16* __restrict__ A, int lda,
    const h16* __restrict__ B, int ldb,
    float* __restrict__ Cf, h16* __restrict__ Ch, int ldc,
    const float* __restrict__ bias, int M, int N, int K, int nst)
{
    extern __shared__ char dsm[];
    const uint32_t u_sm = smem_u32(dsm);

    const int tid = threadIdx.x, lane = tid & 31, wid = tid >> 5;
    const int wr = wid >> 1, wc = wid & 1;           // 4x2 warps, 32x64 each
    const int m0 = blockIdx.y * BM, n0 = blockIdx.x * BN;

    float acc[2][8][4];
#pragma unroll
    for (int i = 0; i < 2; i++)
#pragma unroll
        for (int j = 0; j < 8; j++)
#pragma unroll
            for (int e = 0; e < 4; e++) acc[i][j][e] = 0.f;

    const int lrow = lane & 15;
    const int khalf = lane >> 4;
    const int xk = lrow & 7;
    const uint32_t rA = (uint32_t)((wr * 32 + lrow) * 128);
    const uint32_t rB = (uint32_t)(T_B) + (uint32_t)((wc * 64 + lrow) * 128);

    // stage loader: 8 x 16B per thread (2048 ops = 32KB)
    auto load_stage = [&](int st, int k0) {
        const uint32_t sbase = u_sm + (uint32_t)(st * STAGE_B);
#pragma unroll
        for (int i = 0; i < 8; i++) {
            int u = tid + i * 256;
            int v = u & 1023;
            int r = v >> 3;
            int g = v & 7;
            const h16* src;
            uint32_t toff;
            if (u < 1024) { int ga = m0 + r; if (ga > M - 1) ga = M - 1;
                            src = A + (long)ga * lda + k0 + g * 8; toff = 0; }
            else          { int gb = n0 + r; if (gb > N - 1) gb = N - 1;
                            src = B + (long)gb * ldb + k0 + g * 8; toff = T_B; }
            uint32_t doff = toff + (uint32_t)(r * 128) + (uint32_t)(((g ^ (r & 7)) << 4));
            cpa16(sbase + doff, src);
        }
    };

    const int nch = K / BK;
    load_stage(0, 0);  cpa_commit();

    for (int ch = 0; ch < nch; ch++) {
        cpa_wait<0>();
        __syncthreads();
        if (ch + 1 < nch) {
            load_stage((ch + 1) & 1, (ch + 1) * BK);
            cpa_commit();
        }

        const uint32_t so = u_sm + (uint32_t)((ch & 1) * STAGE_B);
#pragma unroll
        for (int ks = 0; ks < 4; ks++) {
            const uint32_t sw = (uint32_t)((((ks * 2) | khalf) ^ xk) << 4);
            uint32_t bh[4][4];
#pragma unroll
            for (int nt = 0; nt < 4; nt++)
                ldm_x4(bh[nt], so + rB + (uint32_t)(nt * 2048) + sw);
#pragma unroll
            for (int mi = 0; mi < 2; mi++) {
                uint32_t ah[4];
                ldm_x4(ah, so + rA + (uint32_t)(mi * 2048) + sw);
#pragma unroll
                for (int nt = 0; nt < 4; nt++) {
#pragma unroll
                    for (int j = 0; j < 2; j++)
                        mma16816(acc[mi][nt * 2 + j], ah, bh[nt][j], bh[nt][j + 2]);
                }
            }
        }
    }

    const int er = m0 + wr * 32 + (lane >> 2);
    const int ec = n0 + wc * 64 + (lane & 3) * 2;
#pragma unroll
    for (int mi = 0; mi < 2; mi++) {
#pragma unroll
        for (int nj = 0; nj < 8; nj++) {
            const int col = ec + nj * 8;
            if (col >= nst) continue;
            float bv0 = 0.f, bv1 = 0.f;
            if (bias) { bv0 = bias[col]; bv1 = bias[col + 1]; }
#pragma unroll
            for (int half = 0; half < 2; half++) {
                const int row = er + mi * 16 + half * 8;
                if (row >= M) continue;
                float v0 = acc[mi][nj][half * 2 + 0] + bv0;
                float v1 = acc[mi][nj][half * 2 + 1] + bv1;
                if (TANH_ACT) { v0 = tanhf(v0); v1 = tanhf(v1); }
                const long base = (long)row * ldc + col;
                if (OUT_F16) {
                    __half2 h = __floats2half2_rn(v0, v1);
                    *reinterpret_cast<uint32_t*>(Ch + base) = reinterpret_cast<uint32_t&>(h);
                } else {
                    *reinterpret_cast<float2*>(Cf + base) = make_float2(v0, v1);
                }
            }
        }
    }
}

// generic batched wrapper
template<bool OUT_F16, bool TANH_ACT>
__global__ __launch_bounds__(256, 2)
void mmgemm(const h16* __restrict__ A, int lda, long sA,
            const h16* __restrict__ B, int ldb, long sB,
            float* __restrict__ Cf, h16* __restrict__ Ch,
            int ldc, long sC, const float* __restrict__ bias,
            int M, int N, int K, int nst)
{
    const long za = (long)blockIdx.z * sA, zb = (long)blockIdx.z * sB, zc = (long)blockIdx.z * sC;
    mm_body<OUT_F16, TANH_ACT>(
        A + za, lda, B + zb, ldb,
        Cf ? Cf + zc : nullptr, Ch ? Ch + zc : nullptr, ldc, bias, M, N, K, nst);
}

// fused G1 + G2 + G3: z=0 -> G1; z=1..8 -> G2 head; z=9..16 -> G3 head
__global__ __launch_bounds__(256, 2)
void mm_g123(const h16* __restrict__ enc, const h16* __restrict__ walT,
             h16* __restrict__ c1, const float* __restrict__ b_align,
             const h16* __restrict__ wq, const h16* __restrict__ wk, h16* __restrict__ bqk,
             const h16* __restrict__ wfT, const h16* __restrict__ wv, h16* __restrict__ wvfT)
{
    int z = blockIdx.z;
    if (z == 0) {
        mm_body<true, false>(enc, IMGD, walT, IMGD, nullptr, c1, DH, b_align, NR, DH, IMGD, DH);
    } else {
        if (blockIdx.y * BM >= DH) return;
        z -= 1;
        const int set = z >> 3, h = z & 7;
        const long co = (long)h * DH;
        const long cc = (long)h * DH * DH;
        if (set == 0)
            mm_body<true, false>(wq + co, HH * DH, wk + co, HH * DH,
                                 nullptr, bqk + cc, DH, nullptr, DH, DH, DH, DH);
        else
            mm_body<true, false>(wfT + co, HH * DH, wv + co, HH * DH,
                                 nullptr, wvfT + cc, DH, nullptr, DH, DH, DH, DH);
    }
}

// fused G4 + G5 -> fp16 KC / VC
__global__ __launch_bounds__(256, 2)
void mm_g45(const h16* __restrict__ c1, const h16* __restrict__ bqk,
            const h16* __restrict__ wvfT, h16* __restrict__ kc, h16* __restrict__ vc)
{
    int z = blockIdx.z;
    const long NRD = (long)NR * DH;
    const long HD2 = (long)DH * DH;
    if (z < HH)
        mm_body<true, false>(c1, DH, bqk + (long)z * HD2, DH,
                             nullptr, kc + (long)z * NRD, DH, nullptr, NR, DH, DH, DH);
    else {
        z -= HH;
        mm_body<true, false>(c1, DH, wvfT + (long)z * HD2, DH,
                             nullptr, vc + (long)z * NRD, DH, nullptr, NR, DH, DH, DH);
    }
}

// ---------------- scores GEMM + fused softmax -> packed fp16 P ----------------
// one CTA per (n,h): S[128,49] = seq16 . KC16^T, softmax rows, write g_Pp.
__global__ __launch_bounds__(256, 2)
void mm_scores_softmax(const h16* __restrict__ cat, const h16* __restrict__ kc)
{
    extern __shared__ char dsm[];
    const uint32_t u_sm = smem_u32(dsm);
    const int z = blockIdx.z, n = z >> 3, hh = z & 7;
    const h16* A = cat + (long)n * LSEQ * 2 * DH;
    const h16* B = kc + ((long)hh * NR + (long)n * RR) * DH;
    const int lda = 2 * DH, ldb = DH;
    const int N = RR, K = DH;

    const int tid = threadIdx.x, lane = tid & 31, wid = tid >> 5;
    const int wr = wid >> 1, wc = wid & 1;

    float acc[2][8][4];
#pragma unroll
    for (int i = 0; i < 2; i++)
#pragma unroll
        for (int j = 0; j < 8; j++)
#pragma unroll
            for (int e = 0; e < 4; e++) acc[i][j][e] = 0.f;

    const int lrow = lane & 15;
    const int khalf = lane >> 4;
    const int xk = lrow & 7;
    const uint32_t rA = (uint32_t)((wr * 32 + lrow) * 128);
    const uint32_t rB = (uint32_t)(T_B) + (uint32_t)((wc * 64 + lrow) * 128);

    auto load_stage = [&](int st, int k0) {
        const uint32_t sbase = u_sm + (uint32_t)(st * STAGE_B);
#pragma unroll
        for (int i = 0; i < 8; i++) {
            int u = tid + i * 256;
            int v = u & 1023;
            int r = v >> 3;
            int g = v & 7;
            const h16* src;
            uint32_t toff;
            if (u < 1024) { src = A + (long)r * lda + k0 + g * 8; toff = 0; }
            else          { int gb = r; if (gb > N - 1) gb = N - 1;
                            src = B + (long)gb * ldb + k0 + g * 8; toff = T_B; }
            uint32_t doff = toff + (uint32_t)(r * 128) + (uint32_t)(((g ^ (r & 7)) << 4));
            cpa16(sbase + doff, src);
        }
    };

    const int nch = K / BK;
    load_stage(0, 0);  cpa_commit();

    for (int ch = 0; ch < nch; ch++) {
        cpa_wait<0>();
        __syncthreads();
        if (ch + 1 < nch) {
            load_stage((ch + 1) & 1, (ch + 1) * BK);
            cpa_commit();
        }
        const uint32_t so = u_sm + (uint32_t)((ch & 1) * STAGE_B);
#pragma unroll
        for (int ks = 0; ks < 4; ks++) {
            const uint32_t sw = (uint32_t)((((ks * 2) | khalf) ^ xk) << 4);
            uint32_t bh[4][4];
#pragma unroll
            for (int nt = 0; nt < 4; nt++)
                ldm_x4(bh[nt], so + rB + (uint32_t)(nt * 2048) + sw);
#pragma unroll
            for (int mi = 0; mi < 2; mi++) {
                uint32_t ah[4];
                ldm_x4(ah, so + rA + (uint32_t)(mi * 2048) + sw);
#pragma unroll
                for (int nt = 0; nt < 4; nt++) {
#pragma unroll
                    for (int j = 0; j < 2; j++)
                        mma16816(acc[mi][nt * 2 + j], ah, bh[nt][j], bh[nt][j + 2]);
                }
            }
        }
    }

    // epilogue -> smem S[128][65] (only wc==0 warps hold cols 0..63)
    float* S = reinterpret_cast<float*>(dsm);
    __syncthreads();
    if (wc == 0) {
        const int er0 = wr * 32 + (lane >> 2);
        const int ec0 = (lane & 3) * 2;
#pragma unroll
        for (int mi = 0; mi < 2; mi++) {
#pragma unroll
            for (int nj = 0; nj < 8; nj++) {
                const int col = ec0 + nj * 8;
#pragma unroll
                for (int half = 0; half < 2; half++) {
                    const int row = er0 + mi * 16 + half * 8;
                    S[row * 65 + col]     = acc[mi][nj][half * 2 + 0];
                    S[row * 65 + col + 1] = acc[mi][nj][half * 2 + 1];
                }
            }
        }
    }
    __syncthreads();

    // softmax per token row (threads 0..127)
    if (tid < 128) {
        const int t = tid;
        const float scale = rsqrtf((float)DH);
        float ex[RR];
        float mx = -1e30f;
#pragma unroll
        for (int r = 0; r < RR; r++) { float v = S[t * 65 + r] * scale; ex[r] = v; mx = fmaxf(mx, v); }
        float sum = 0.f;
#pragma unroll
        for (int r = 0; r < RR; r++) { float e = expf(ex[r] - mx); ex[r] = e; sum += e; }
        const float inv = 1.f / sum;
        h16* out = g_Pp + ((long)n * LSEQ + t) * KP + hh * RR;
#pragma unroll
        for (int r = 0; r < RR; r++) out[r] = __float2half(ex[r] * inv);
        if (hh == 0) {
            h16* pad = g_Pp + ((long)n * LSEQ + t) * KP + HH * RR;
            for (int i = 0; i < KP - HH * RR; i++) pad[i] = (h16)0.f;
        }
    }
}

// ---------------- VC fp16 -> Vt [n][d][h*49+r] ----------------
__global__ void transpose_v()
{
    __shared__ h16 tile[32][33];
    const int z = blockIdx.z, n = z >> 3, h = z & 7;
    const int d0 = blockIdx.x * 32, r0 = blockIdx.y * 32;
    const int tx = threadIdx.x, ty = threadIdx.y;
    for (int i = ty; i < 32; i += 8) {
        int r = r0 + i;
        h16 v = (h16)0.f;
        if (r < RR) v = g_VC16[((long)h * NR + (long)n * RR + r) * DH + d0 + tx];
        tile[i][tx] = v;
    }
    __syncthreads();
    for (int i = ty; i < 32; i += 8) {
        int r = r0 + tx;
        if (r < RR)
            g_Vt[((long)n * DH + d0 + i) * KP + h * RR + r] = tile[tx][i];
    }
}

// ---------------- residual + LN -> cat[:, 768:1536] fp16 ----------------
__global__ __launch_bounds__(256) void ln_cat(const float* __restrict__ seq,
                                              const float* __restrict__ gam,
                                              const float* __restrict__ bet)
{
    const int wid = threadIdx.x >> 5, lane = threadIdx.x & 31;
    for (int rr = 0; rr < 2; rr++) {
        const long u = (long)blockIdx.x * 16 + wid * 2 + rr;
        const float* ao = g_attout + u * DH;
        const float* sq = seq + u * DH;
        float s = 0.f;
        for (int k = lane; k < DH; k += 32) s += ao[k] + sq[k];
        for (int o = 16; o; o >>= 1) s += __shfl_xor_sync(0xffffffffu, s, o);
        float mu = s * (1.f / DH);
        float v = 0.f;
        for (int k = lane; k < DH; k += 32) { float d = ao[k] + sq[k] - mu; v += d * d; }
        for (int o = 16; o; o >>= 1) v += __shfl_xor_sync(0xffffffffu, v, o);
        float rstd = rsqrtf(v * (1.f / DH) + 1e-5f);
        h16* dst = g_cat + u * 2 * DH + DH;
        for (int k = lane * 2; k < DH; k += 64) {
            float a = (ao[k]     + sq[k]     - mu) * rstd * gam[k]     + bet[k];
            float b = (ao[k + 1] + sq[k + 1] - mu) * rstd * gam[k + 1] + bet[k + 1];
            __half2 h = __floats2half2_rn(a, b);
            *reinterpret_cast<uint32_t*>(dst + k) = reinterpret_cast<uint32_t&>(h);
        }
    }
}

// ---------------- merged straight conversions (enc, Wq, Wk, Wv) ----------------
#define N_ENC (NR * IMGD)                   // 1605632
#define N_W   (DH * HH * DH)                // 4718592
__global__ void cvt_all(const float* __restrict__ enc_img, const float* __restrict__ Wq,
                        const float* __restrict__ Wk, const float* __restrict__ Wv)
{
    const long total = (long)N_ENC + 3L * N_W;
    long i0 = ((long)blockIdx.x * blockDim.x + threadIdx.x) * 4;
    long stride = (long)gridDim.x * blockDim.x * 4;
    for (long i = i0; i < total; i += stride) {
        const float* src; h16* dst; long off;
        if (i < N_ENC)                { src = enc_img; dst = g_enc; off = i; }
        else if (i < N_ENC + N_W)     { src = Wq; dst = g_Wq; off = i - N_ENC; }
        else if (i < N_ENC + 2L*N_W)  { src = Wk; dst = g_Wk; off = i - N_ENC - N_W; }
        else                          { src = Wv; dst = g_Wv; off = i - N_ENC - 2L*N_W; }
        float4 v = *reinterpret_cast<const float4*>(src + off);
        __half2 h0 = __floats2half2_rn(v.x, v.y);
        __half2 h1 = __floats2half2_rn(v.z, v.w);
        *reinterpret_cast<uint2*>(dst + off) =
            make_uint2(reinterpret_cast<uint32_t&>(h0), reinterpret_cast<uint32_t&>(h1));
    }
}

// ---------------- merged transposed conversions ----------------
__global__ void cvtT_all(const float* __restrict__ W_align, const float* __restrict__ Wfc,
                         const float* __restrict__ W_a1, const float* __restrict__ W_a2,
                         const float* __restrict__ W_dense)
{
    __shared__ float t[32][33];
    int b = blockIdx.x;
    const float* in; h16* out; int R, C, local;
    if (b < 1536)       { in = W_align; out = g_WalT; R = 2048; C = 768;  local = b; }
    else if (b < 6144)  { in = Wfc;     out = g_WfcT; R = 6144; C = 768;  local = b - 1536; }
    else if (b < 8448)  { in = W_a1;    out = g_Wa1T; R = 1536; C = 1536; local = b - 6144; }
    else if (b < 9600)  { in = W_a2;    out = g_Wa2T; R = 1536; C = 768;  local = b - 8448; }
    else                { in = W_dense; out = g_WdT;  R = 768;  C = 768;  local = b - 9600; }
    const int tx = C / 32;
    const int cx = local % tx, ry = local / tx;
    const int c0 = cx * 32, r0 = ry * 32;
    for (int i = threadIdx.y; i < 32; i += 8)
        t[i][threadIdx.x] = in[(long)(r0 + i) * C + c0 + threadIdx.x];
    __syncthreads();
    if (threadIdx.x < 16) {
        for (int i = threadIdx.y; i < 32; i += 8) {
            __half2 h = __floats2half2_rn(t[2 * threadIdx.x][i], t[2 * threadIdx.x + 1][i]);
            long o = (long)(c0 + i) * R + r0 + 2 * threadIdx.x;
            *reinterpret_cast<uint32_t*>(out + o) = reinterpret_cast<uint32_t&>(h);
        }
    }
}

// ---------------- seq -> cat[:, 0:768] fp16 (grid-stride) ----------------
__global__ void seq_cvt_kernel(const float* __restrict__ seq)
{
    long i0 = ((long)blockIdx.x * blockDim.x + threadIdx.x) * 4;
    long stride = (long)gridDim.x * blockDim.x * 4;
    const long total = (long)UU * DH;
    for (long i = i0; i < total; i += stride) {
        long row = i / DH, col = i - row * DH;
        float4 v = *reinterpret_cast<const float4*>(seq + i);
        __half2 h0 = __floats2half2_rn(v.x, v.y);
        __half2 h1 = __floats2half2_rn(v.z, v.w);
        *reinterpret_cast<uint2*>(g_cat + row * 2 * DH + col) =
            make_uint2(reinterpret_cast<uint32_t&>(h0), reinterpret_cast<uint32_t&>(h1));
    }
}

// ---------------- unary score + masked softmax pooling -> fp16 pool ----------------
__global__ void pool_kernel(const float* __restrict__ W_un, const float* __restrict__ b_un,
                            const int* __restrict__ starts, const int* __restrict__ ends)
{
    int sp = blockIdx.x, t = threadIdx.x;
    int lane = t & 31, w = t >> 5;
    int n = sp >> 3;
    int base = n * LSEQ + starts[sp];
    __shared__ float sS[JR];
    __shared__ float sProb[JR];

    for (int j = w; j < JR; j += 8) {
        int u = base + j; if (u > UU - 1) u = UU - 1;
        const float* fr = g_fused + (long)u * DH;
        float acc = 0.f;
        for (int k = lane; k < DH; k += 32) acc += fr[k] * W_un[k];
        for (int o = 16; o; o >>= 1) acc += __shfl_xor_sync(0xffffffffu, acc, o);
        if (lane == 0) sS[j] = acc + b_un[0];
    }
    __syncthreads();
    if (t == 0) {
        int width = ends[sp] - starts[sp] + 1;
        float mx = -1e30f;
        for (int j = 0; j < JR; j++) {
            float v = sS[j] + ((j < width) ? 0.f : -10000.f);
            sS[j] = v; mx = fmaxf(mx, v);
        }
        float sum = 0.f;
        for (int j = 0; j < JR; j++) { float e = expf(sS[j] - mx); sProb[j] = e; sum += e; }
        float inv = 1.f / sum;
        for (int j = 0; j < JR; j++) sProb[j] *= inv;
    }
    __syncthreads();
    for (int d = t; d < DH; d += 256) {
        float acc = 0.f;
        for (int j = 0; j < JR; j++) {
            int u = base + j; if (u > UU - 1) u = UU - 1;
            acc += sProb[j] * g_fused[(long)u * DH + d];
        }
        g_pool16[(long)sp * DH + d] = __float2half(acc);
    }
}

// ---------------- classifier ----------------
__global__ void cls_kernel(const float* __restrict__ W_cls, const float* __restrict__ b_cls,
                           float* __restrict__ out)
{
    int row = blockIdx.x, t = threadIdx.x;
    int lane = t & 31, c = t >> 5;
    const float* hr = g_hid + (long)row * DH;
    float acc = 0.f;
    for (int k = lane; k < DH; k += 32) acc += hr[k] * W_cls[k * 4 + c];
    for (int o = 16; o; o >>= 1) acc += __shfl_xor_sync(0xffffffffu, acc, o);
    if (lane == 0) out[row * 4 + c] = acc + b_cls[c];
}

// ---------------- launcher ----------------
extern "C" void kernel_launch(void* const* d_in, const int* in_sizes, int n_in,
                              void* d_out, int out_size)
{
    const float* enc_img  = (const float*)d_in[0];
    const float* seq      = (const float*)d_in[1];
    const int*   starts   = (const int*)d_in[3];
    const int*   ends     = (const int*)d_in[4];
    const float* W_align  = (const float*)d_in[5];
    const float* b_align  = (const float*)d_in[6];
    const float* Wq       = (const float*)d_in[7];
    const float* Wk       = (const float*)d_in[8];
    const float* Wv       = (const float*)d_in[9];
    const float* Wfc      = (const float*)d_in[10];
    const float* ln_g     = (const float*)d_in[11];
    const float* ln_b     = (const float*)d_in[12];
    const float* W_a1     = (const float*)d_in[13];
    const float* b_a1     = (const float*)d_in[14];
    const float* W_a2     = (const float*)d_in[15];
    const float* b_a2     = (const float*)d_in[16];
    const float* W_un     = (const float*)d_in[17];
    const float* b_un     = (const float*)d_in[18];
    const float* W_dense  = (const float*)d_in[19];
    const float* b_dense  = (const float*)d_in[20];
    const float* W_cls    = (const float*)d_in[21];
    const float* b_cls    = (const float*)d_in[22];

    h16 *enc, *walT, *wq, *wk, *wv, *wfT, *c1, *bqk, *wvfT, *kc, *vc, *cat, *wa1T, *f1, *wa2T;
    h16 *pp, *vt, *wdT, *pool16;
    float *pAO, *pFused, *pHid;
    cudaGetSymbolAddress((void**)&enc,  g_enc);
    cudaGetSymbolAddress((void**)&walT, g_WalT);
    cudaGetSymbolAddress((void**)&wq,   g_Wq);
    cudaGetSymbolAddress((void**)&wk,   g_Wk);
    cudaGetSymbolAddress((void**)&wv,   g_Wv);
    cudaGetSymbolAddress((void**)&wfT,  g_WfcT);
    cudaGetSymbolAddress((void**)&c1,   g_C1);
    cudaGetSymbolAddress((void**)&bqk,  g_Bqk);
    cudaGetSymbolAddress((void**)&wvfT, g_WvfT);
    cudaGetSymbolAddress((void**)&kc,   g_KC16);
    cudaGetSymbolAddress((void**)&vc,   g_VC16);
    cudaGetSymbolAddress((void**)&pp,   g_Pp);
    cudaGetSymbolAddress((void**)&vt,   g_Vt);
    cudaGetSymbolAddress((void**)&pAO,  g_attout);
    cudaGetSymbolAddress((void**)&cat,  g_cat);
    cudaGetSymbolAddress((void**)&wa1T, g_Wa1T);
    cudaGetSymbolAddress((void**)&f1,   g_f1);
    cudaGetSymbolAddress((void**)&wa2T, g_Wa2T);
    cudaGetSymbolAddress((void**)&wdT,  g_WdT);
    cudaGetSymbolAddress((void**)&pool16, g_pool16);
    cudaGetSymbolAddress((void**)&pFused, g_fused);
    cudaGetSymbolAddress((void**)&pHid, g_hid);

    cudaFuncSetAttribute(mm_g123, cudaFuncAttributeMaxDynamicSharedMemorySize, MM_SMEM);
    cudaFuncSetAttribute(mm_g45,  cudaFuncAttributeMaxDynamicSharedMemorySize, MM_SMEM);
    cudaFuncSetAttribute(mm_scores_softmax, cudaFuncAttributeMaxDynamicSharedMemorySize, MM_SMEM);
    cudaFuncSetAttribute(mmgemm<true,  true >, cudaFuncAttributeMaxDynamicSharedMemorySize, MM_SMEM);
    cudaFuncSetAttribute(mmgemm<false, false>, cudaFuncAttributeMaxDynamicSharedMemorySize, MM_SMEM);
    cudaFuncSetAttribute(mmgemm<false, true >, cudaFuncAttributeMaxDynamicSharedMemorySize, MM_SMEM);

    const dim3 blk(256);

    // ---- operand conversions (merged) ----
    cvt_all<<<2048, 256>>>(enc_img, Wq, Wk, Wv);
    cvtT_all<<<10176, dim3(32, 8)>>>(W_align, Wfc, W_a1, W_a2, W_dense);
    seq_cvt_kernel<<<1536, 256>>>(seq);

    // ---- G1 + G2 + G3 fused ----
    mm_g123<<<dim3(6, 7, 17), blk, MM_SMEM>>>(
        enc, walT, c1, b_align, wq, wk, bqk, wfT, wv, wvfT);

    // ---- G4 + G5 fused -> fp16 KC / VC ----
    mm_g45<<<dim3(6, 7, 16), blk, MM_SMEM>>>(c1, bqk, wvfT, kc, vc);

    // ---- attention (tensorized, softmax fused into scores) ----
    transpose_v<<<dim3(DH / 32, 2, NB * HH), dim3(32, 8)>>>();
    mm_scores_softmax<<<dim3(1, 1, NB * HH), blk, MM_SMEM>>>(cat, kc);
    mmgemm<false, false><<<dim3(6, 1, NB), blk, MM_SMEM>>>(
        pp, KP, (long)LSEQ * KP, vt, KP, (long)DH * KP,
        pAO, nullptr, DH, (long)LSEQ * DH, nullptr, LSEQ, DH, KP, DH);
    ln_cat<<<UU / 16, 256>>>(seq, ln_g, ln_b);

    // ---- fusion MLP on 2048 tokens ----
    mmgemm<true, true><<<dim3(12, 16, 1), blk, MM_SMEM>>>(
        cat, 2 * DH, 0, wa1T, 2 * DH, 0,
        nullptr, f1, 2 * DH, 0, b_a1, UU, 2 * DH, 2 * DH, 2 * DH);
    mmgemm<false, false><<<dim3(6, 16, 1), blk, MM_SMEM>>>(
        f1, 2 * DH, 0, wa2T, 2 * DH, 0,
        pFused, nullptr, DH, 0, b_a2, UU, DH, 2 * DH, DH);

    // ---- pooling + head (dense on tensor cores) ----
    pool_kernel<<<NM, 256>>>(W_un, b_un, starts, ends);
    mmgemm<false, true><<<dim3(6, 1, 1), blk, MM_SMEM>>>(
        pool16, DH, 0, wdT, DH, 0,
        pHid, nullptr, DH, 0, b_dense, NM, DH, DH, DH);
    cls_kernel<<<NM, 128>>>(W_cls, b_cls, (float*)d_out);
}

// round 13
// speedup vs baseline: 5.7793x; 1.0182x over previous
#include <cuda_runtime.h>
#include <cuda_fp16.h>
#include <math.h>
#include <stdint.h>

// ---------------- problem constants ----------------
#define NB    16
#define LSEQ  128
#define DH    768
#define MSP   8
#define HH    8
#define JR    30
#define RR    49
#define IMGD  2048
#define NM    128
#define UU    2048
#define NR    784
#define KP    448

typedef __half h16;

// ---------------- scratch ----------------
__device__ h16 g_enc[NR * IMGD];
__device__ h16 g_WalT[DH * IMGD];
__device__ h16 g_Wq[DH * HH * DH];
__device__ h16 g_Wk[DH * HH * DH];
__device__ h16 g_Wv[DH * HH * DH];
__device__ h16 g_WfcT[DH * HH * DH];
__device__ h16 g_C1[NR * DH];
__device__ h16 g_Bqk[HH * DH * DH];
__device__ h16 g_WvfT[HH * DH * DH];
__device__ h16 g_KC16[HH * NR * DH];
__device__ h16 g_VC16[HH * NR * DH];
__device__ h16 g_Pp[NB * LSEQ * KP];
__device__ h16 g_Vt[NB * DH * KP];
__device__ float g_attout[UU * DH];
__device__ h16 g_cat[UU * 2 * DH];
__device__ h16 g_Wa1T[2*DH * 2*DH];
__device__ h16 g_f1[UU * 2 * DH];
__device__ h16 g_Wa2T[DH * 2*DH];
__device__ h16 g_WdT[DH * DH];
__device__ float g_fused[UU * DH];
__device__ h16 g_pool16[NM * DH];
__device__ float g_hid[NM * DH];

// ---------------- helpers ----------------
__device__ __forceinline__ uint32_t smem_u32(const void* p) {
    uint32_t a;
    asm("{ .reg .u64 t; cvta.to.shared.u64 t, %1; cvt.u32.u64 %0, t; }" : "=r"(a) : "l"(p));
    return a;
}

__device__ __forceinline__ void ldm_x4(uint32_t* r, uint32_t addr) {
    asm volatile("ldmatrix.sync.aligned.m8n8.x4.shared.b16 {%0,%1,%2,%3}, [%4];"
                 : "=r"(r[0]), "=r"(r[1]), "=r"(r[2]), "=r"(r[3]) : "r"(addr));
}

__device__ __forceinline__ void mma16816(float* c, const uint32_t* a, uint32_t b0, uint32_t b1) {
    asm volatile(
        "mma.sync.aligned.m16n8k16.row.col.f32.f16.f16.f32 "
        "{%0,%1,%2,%3}, {%4,%5,%6,%7}, {%8,%9}, {%0,%1,%2,%3};"
        : "+f"(c[0]), "+f"(c[1]), "+f"(c[2]), "+f"(c[3])
        : "r"(a[0]), "r"(a[1]), "r"(a[2]), "r"(a[3]), "r"(b0), "r"(b1));
}

__device__ __forceinline__ void cpa16(uint32_t dst, const void* src) {
    asm volatile("cp.async.ca.shared.global [%0], [%1], 16;" :: "r"(dst), "l"(src));
}
__device__ __forceinline__ void cpa_commit() {
    asm volatile("cp.async.commit_group;" ::: "memory");
}
template<int N_>
__device__ __forceinline__ void cpa_wait() {
    asm volatile("cp.async.wait_group %0;" :: "n"(N_) : "memory");
}

// ---------------- fp16 tensor-core GEMM core v4 ----------------
#define BM 128
#define BN 128
#define BK 64
#define T_B 16384
#define STAGE_B 32768
#define MM_SMEM (2 * STAGE_B)

template<bool OUT_F16, bool TANH_ACT>
__device__ __forceinline__ void mm_body(
    const h16* __restrict__ A, int lda,
    const h16* __restrict__ B, int ldb,
    float* __restrict__ Cf, h16* __restrict__ Ch, int ldc,
    const float* __restrict__ bias, int M, int N, int K, int nst)
{
    extern __shared__ char dsm[];
    const uint32_t u_sm = smem_u32(dsm);

    const int tid = threadIdx.x, lane = tid & 31, wid = tid >> 5;
    const int wr = wid >> 1, wc = wid & 1;
    const int m0 = blockIdx.y * BM, n0 = blockIdx.x * BN;

    float acc[2][8][4];
#pragma unroll
    for (int i = 0; i < 2; i++)
#pragma unroll
        for (int j = 0; j < 8; j++)
#pragma unroll
            for (int e = 0; e < 4; e++) acc[i][j][e] = 0.f;

    const int lrow = lane & 15;
    const int khalf = lane >> 4;
    const int xk = lrow & 7;
    const uint32_t rA = (uint32_t)((wr * 32 + lrow) * 128);
    const uint32_t rB = (uint32_t)(T_B) + (uint32_t)((wc * 64 + lrow) * 128);

    auto load_stage = [&](int st, int k0) {
        const uint32_t sbase = u_sm + (uint32_t)(st * STAGE_B);
#pragma unroll
        for (int i = 0; i < 8; i++) {
            int u = tid + i * 256;
            int v = u & 1023;
            int r = v >> 3;
            int g = v & 7;
            const h16* src;
            uint32_t toff;
            if (u < 1024) { int ga = m0 + r; if (ga > M - 1) ga = M - 1;
                            src = A + (long)ga * lda + k0 + g * 8; toff = 0; }
            else          { int gb = n0 + r; if (gb > N - 1) gb = N - 1;
                            src = B + (long)gb * ldb + k0 + g * 8; toff = T_B; }
            uint32_t doff = toff + (uint32_t)(r * 128) + (uint32_t)(((g ^ (r & 7)) << 4));
            cpa16(sbase + doff, src);
        }
    };

    const int nch = K / BK;
    load_stage(0, 0);  cpa_commit();

    for (int ch = 0; ch < nch; ch++) {
        cpa_wait<0>();
        __syncthreads();
        if (ch + 1 < nch) {
            load_stage((ch + 1) & 1, (ch + 1) * BK);
            cpa_commit();
        }

        const uint32_t so = u_sm + (uint32_t)((ch & 1) * STAGE_B);
#pragma unroll
        for (int ks = 0; ks < 4; ks++) {
            const uint32_t sw = (uint32_t)((((ks * 2) | khalf) ^ xk) << 4);
            uint32_t bh[4][4];
#pragma unroll
            for (int nt = 0; nt < 4; nt++)
                ldm_x4(bh[nt], so + rB + (uint32_t)(nt * 2048) + sw);
#pragma unroll
            for (int mi = 0; mi < 2; mi++) {
                uint32_t ah[4];
                ldm_x4(ah, so + rA + (uint32_t)(mi * 2048) + sw);
#pragma unroll
                for (int nt = 0; nt < 4; nt++) {
#pragma unroll
                    for (int j = 0; j < 2; j++)
                        mma16816(acc[mi][nt * 2 + j], ah, bh[nt][j], bh[nt][j + 2]);
                }
            }
        }
    }

    const int er = m0 + wr * 32 + (lane >> 2);
    const int ec = n0 + wc * 64 + (lane & 3) * 2;
#pragma unroll
    for (int mi = 0; mi < 2; mi++) {
#pragma unroll
        for (int nj = 0; nj < 8; nj++) {
            const int col = ec + nj * 8;
            if (col >= nst) continue;
            float bv0 = 0.f, bv1 = 0.f;
            if (bias) { bv0 = bias[col]; bv1 = bias[col + 1]; }
#pragma unroll
            for (int half = 0; half < 2; half++) {
                const int row = er + mi * 16 + half * 8;
                if (row >= M) continue;
                float v0 = acc[mi][nj][half * 2 + 0] + bv0;
                float v1 = acc[mi][nj][half * 2 + 1] + bv1;
                if (TANH_ACT) { v0 = tanhf(v0); v1 = tanhf(v1); }
                const long base = (long)row * ldc + col;
                if (OUT_F16) {
                    __half2 h = __floats2half2_rn(v0, v1);
                    *reinterpret_cast<uint32_t*>(Ch + base) = reinterpret_cast<uint32_t&>(h);
                } else {
                    *reinterpret_cast<float2*>(Cf + base) = make_float2(v0, v1);
                }
            }
        }
    }
}

template<bool OUT_F16, bool TANH_ACT>
__global__ __launch_bounds__(256, 2)
void mmgemm(const h16* __restrict__ A, int lda, long sA,
            const h16* __restrict__ B, int ldb, long sB,
            float* __restrict__ Cf, h16* __restrict__ Ch,
            int ldc, long sC, const float* __restrict__ bias,
            int M, int N, int K, int nst)
{
    const long za = (long)blockIdx.z * sA, zb = (long)blockIdx.z * sB, zc = (long)blockIdx.z * sC;
    mm_body<OUT_F16, TANH_ACT>(
        A + za, lda, B + zb, ldb,
        Cf ? Cf + zc : nullptr, Ch ? Ch + zc : nullptr, ldc, bias, M, N, K, nst);
}

__global__ __launch_bounds__(256, 2)
void mm_g123(const h16* __restrict__ enc, const h16* __restrict__ walT,
             h16* __restrict__ c1, const float* __restrict__ b_align,
             const h16* __restrict__ wq, const h16* __restrict__ wk, h16* __restrict__ bqk,
             const h16* __restrict__ wfT, const h16* __restrict__ wv, h16* __restrict__ wvfT)
{
    int z = blockIdx.z;
    if (z == 0) {
        mm_body<true, false>(enc, IMGD, walT, IMGD, nullptr, c1, DH, b_align, NR, DH, IMGD, DH);
    } else {
        if (blockIdx.y * BM >= DH) return;
        z -= 1;
        const int set = z >> 3, h = z & 7;
        const long co = (long)h * DH;
        const long cc = (long)h * DH * DH;
        if (set == 0)
            mm_body<true, false>(wq + co, HH * DH, wk + co, HH * DH,
                                 nullptr, bqk + cc, DH, nullptr, DH, DH, DH, DH);
        else
            mm_body<true, false>(wfT + co, HH * DH, wv + co, HH * DH,
                                 nullptr, wvfT + cc, DH, nullptr, DH, DH, DH, DH);
    }
}

__global__ __launch_bounds__(256, 2)
void mm_g45(const h16* __restrict__ c1, const h16* __restrict__ bqk,
            const h16* __restrict__ wvfT, h16* __restrict__ kc, h16* __restrict__ vc)
{
    int z = blockIdx.z;
    const long NRD = (long)NR * DH;
    const long HD2 = (long)DH * DH;
    if (z < HH)
        mm_body<true, false>(c1, DH, bqk + (long)z * HD2, DH,
                             nullptr, kc + (long)z * NRD, DH, nullptr, NR, DH, DH, DH);
    else {
        z -= HH;
        mm_body<true, false>(c1, DH, wvfT + (long)z * HD2, DH,
                             nullptr, vc + (long)z * NRD, DH, nullptr, NR, DH, DH, DH);
    }
}

// ---------------- scores GEMM + fused softmax -> packed fp16 P ----------------
__global__ __launch_bounds__(256, 2)
void mm_scores_softmax(const h16* __restrict__ cat, const h16* __restrict__ kc)
{
    extern __shared__ char dsm[];
    const uint32_t u_sm = smem_u32(dsm);
    const int z = blockIdx.z, n = z >> 3, hh = z & 7;
    const h16* A = cat + (long)n * LSEQ * 2 * DH;
    const h16* B = kc + ((long)hh * NR + (long)n * RR) * DH;
    const int lda = 2 * DH, ldb = DH;
    const int N = RR, K = DH;

    const int tid = threadIdx.x, lane = tid & 31, wid = tid >> 5;
    const int wr = wid >> 1, wc = wid & 1;

    float acc[2][8][4];
#pragma unroll
    for (int i = 0; i < 2; i++)
#pragma unroll
        for (int j = 0; j < 8; j++)
#pragma unroll
            for (int e = 0; e < 4; e++) acc[i][j][e] = 0.f;

    const int lrow = lane & 15;
    const int khalf = lane >> 4;
    const int xk = lrow & 7;
    const uint32_t rA = (uint32_t)((wr * 32 + lrow) * 128);
    const uint32_t rB = (uint32_t)(T_B) + (uint32_t)((wc * 64 + lrow) * 128);

    auto load_stage = [&](int st, int k0) {
        const uint32_t sbase = u_sm + (uint32_t)(st * STAGE_B);
#pragma unroll
        for (int i = 0; i < 8; i++) {
            int u = tid + i * 256;
            int v = u & 1023;
            int r = v >> 3;
            int g = v & 7;
            const h16* src;
            uint32_t toff;
            if (u < 1024) { src = A + (long)r * lda + k0 + g * 8; toff = 0; }
            else          { int gb = r; if (gb > N - 1) gb = N - 1;
                            src = B + (long)gb * ldb + k0 + g * 8; toff = T_B; }
            uint32_t doff = toff + (uint32_t)(r * 128) + (uint32_t)(((g ^ (r & 7)) << 4));
            cpa16(sbase + doff, src);
        }
    };

    const int nch = K / BK;
    load_stage(0, 0);  cpa_commit();

    for (int ch = 0; ch < nch; ch++) {
        cpa_wait<0>();
        __syncthreads();
        if (ch + 1 < nch) {
            load_stage((ch + 1) & 1, (ch + 1) * BK);
            cpa_commit();
        }
        const uint32_t so = u_sm + (uint32_t)((ch & 1) * STAGE_B);
#pragma unroll
        for (int ks = 0; ks < 4; ks++) {
            const uint32_t sw = (uint32_t)((((ks * 2) | khalf) ^ xk) << 4);
            uint32_t bh[4][4];
#pragma unroll
            for (int nt = 0; nt < 4; nt++)
                ldm_x4(bh[nt], so + rB + (uint32_t)(nt * 2048) + sw);
#pragma unroll
            for (int mi = 0; mi < 2; mi++) {
                uint32_t ah[4];
                ldm_x4(ah, so + rA + (uint32_t)(mi * 2048) + sw);
#pragma unroll
                for (int nt = 0; nt < 4; nt++) {
#pragma unroll
                    for (int j = 0; j < 2; j++)
                        mma16816(acc[mi][nt * 2 + j], ah, bh[nt][j], bh[nt][j + 2]);
                }
            }
        }
    }

    float* S = reinterpret_cast<float*>(dsm);
    __syncthreads();
    if (wc == 0) {
        const int er0 = wr * 32 + (lane >> 2);
        const int ec0 = (lane & 3) * 2;
#pragma unroll
        for (int mi = 0; mi < 2; mi++) {
#pragma unroll
            for (int nj = 0; nj < 8; nj++) {
                const int col = ec0 + nj * 8;
#pragma unroll
                for (int half = 0; half < 2; half++) {
                    const int row = er0 + mi * 16 + half * 8;
                    S[row * 65 + col]     = acc[mi][nj][half * 2 + 0];
                    S[row * 65 + col + 1] = acc[mi][nj][half * 2 + 1];
                }
            }
        }
    }
    __syncthreads();

    if (tid < 128) {
        const int t = tid;
        const float scale = rsqrtf((float)DH);
        float ex[RR];
        float mx = -1e30f;
#pragma unroll
        for (int r = 0; r < RR; r++) { float v = S[t * 65 + r] * scale; ex[r] = v; mx = fmaxf(mx, v); }
        float sum = 0.f;
#pragma unroll
        for (int r = 0; r < RR; r++) { float e = expf(ex[r] - mx); ex[r] = e; sum += e; }
        const float inv = 1.f / sum;
        h16* out = g_Pp + ((long)n * LSEQ + t) * KP + hh * RR;
#pragma unroll
        for (int r = 0; r < RR; r++) out[r] = __float2half(ex[r] * inv);
        if (hh == 0) {
            h16* pad = g_Pp + ((long)n * LSEQ + t) * KP + HH * RR;
            for (int i = 0; i < KP - HH * RR; i++) pad[i] = (h16)0.f;
        }
    }
}

// ---------------- VC fp16 -> Vt [n][d][h*49+r] ----------------
__global__ void transpose_v()
{
    __shared__ h16 tile[32][33];
    const int z = blockIdx.z, n = z >> 3, h = z & 7;
    const int d0 = blockIdx.x * 32, r0 = blockIdx.y * 32;
    const int tx = threadIdx.x, ty = threadIdx.y;
    for (int i = ty; i < 32; i += 8) {
        int r = r0 + i;
        h16 v = (h16)0.f;
        if (r < RR) v = g_VC16[((long)h * NR + (long)n * RR + r) * DH + d0 + tx];
        tile[i][tx] = v;
    }
    __syncthreads();
    for (int i = ty; i < 32; i += 8) {
        int r = r0 + tx;
        if (r < RR)
            g_Vt[((long)n * DH + d0 + i) * KP + h * RR + r] = tile[tx][i];
    }
}

// ---------------- residual + LN -> cat[:, 768:1536] fp16 ----------------
__global__ __launch_bounds__(256) void ln_cat(const float* __restrict__ seq,
                                              const float* __restrict__ gam,
                                              const float* __restrict__ bet)
{
    const int wid = threadIdx.x >> 5, lane = threadIdx.x & 31;
    for (int rr = 0; rr < 2; rr++) {
        const long u = (long)blockIdx.x * 16 + wid * 2 + rr;
        const float* ao = g_attout + u * DH;
        const float* sq = seq + u * DH;
        float s = 0.f;
        for (int k = lane; k < DH; k += 32) s += ao[k] + sq[k];
        for (int o = 16; o; o >>= 1) s += __shfl_xor_sync(0xffffffffu, s, o);
        float mu = s * (1.f / DH);
        float v = 0.f;
        for (int k = lane; k < DH; k += 32) { float d = ao[k] + sq[k] - mu; v += d * d; }
        for (int o = 16; o; o >>= 1) v += __shfl_xor_sync(0xffffffffu, v, o);
        float rstd = rsqrtf(v * (1.f / DH) + 1e-5f);
        h16* dst = g_cat + u * 2 * DH + DH;
        for (int k = lane * 2; k < DH; k += 64) {
            float a = (ao[k]     + sq[k]     - mu) * rstd * gam[k]     + bet[k];
            float b = (ao[k + 1] + sq[k + 1] - mu) * rstd * gam[k + 1] + bet[k + 1];
            __half2 h = __floats2half2_rn(a, b);
            *reinterpret_cast<uint32_t*>(dst + k) = reinterpret_cast<uint32_t&>(h);
        }
    }
}

// ---------------- merged straight conversions (enc, Wq, Wk, Wv) ----------------
#define N_ENC (NR * IMGD)
#define N_W   (DH * HH * DH)
__global__ void cvt_all(const float* __restrict__ enc_img, const float* __restrict__ Wq,
                        const float* __restrict__ Wk, const float* __restrict__ Wv)
{
    const long total = (long)N_ENC + 3L * N_W;
    long i0 = ((long)blockIdx.x * blockDim.x + threadIdx.x) * 4;
    long stride = (long)gridDim.x * blockDim.x * 4;
    for (long i = i0; i < total; i += stride) {
        const float* src; h16* dst; long off;
        if (i < N_ENC)                { src = enc_img; dst = g_enc; off = i; }
        else if (i < N_ENC + N_W)     { src = Wq; dst = g_Wq; off = i - N_ENC; }
        else if (i < N_ENC + 2L*N_W)  { src = Wk; dst = g_Wk; off = i - N_ENC - N_W; }
        else                          { src = Wv; dst = g_Wv; off = i - N_ENC - 2L*N_W; }
        float4 v = *reinterpret_cast<const float4*>(src + off);
        __half2 h0 = __floats2half2_rn(v.x, v.y);
        __half2 h1 = __floats2half2_rn(v.z, v.w);
        *reinterpret_cast<uint2*>(dst + off) =
            make_uint2(reinterpret_cast<uint32_t&>(h0), reinterpret_cast<uint32_t&>(h1));
    }
}

// ---------------- transposed conversions, early set (W_align, Wfc) ----------------
__global__ void cvtT_early(const float* __restrict__ W_align, const float* __restrict__ Wfc)
{
    __shared__ float t[32][33];
    int b = blockIdx.x;
    const float* in; h16* out; int R, C, local;
    if (b < 1536) { in = W_align; out = g_WalT; R = 2048; C = 768; local = b; }
    else          { in = Wfc;     out = g_WfcT; R = 6144; C = 768; local = b - 1536; }
    const int tx = C / 32;
    const int cx = local % tx, ry = local / tx;
    const int c0 = cx * 32, r0 = ry * 32;
    for (int i = threadIdx.y; i < 32; i += 8)
        t[i][threadIdx.x] = in[(long)(r0 + i) * C + c0 + threadIdx.x];
    __syncthreads();
    if (threadIdx.x < 16) {
        for (int i = threadIdx.y; i < 32; i += 8) {
            __half2 h = __floats2half2_rn(t[2 * threadIdx.x][i], t[2 * threadIdx.x + 1][i]);
            long o = (long)(c0 + i) * R + r0 + 2 * threadIdx.x;
            *reinterpret_cast<uint32_t*>(out + o) = reinterpret_cast<uint32_t&>(h);
        }
    }
}

// ---------------- transposed conversions, late set (W_a1, W_a2, W_dense) ----------------
__global__ void cvtT_late(const float* __restrict__ W_a1, const float* __restrict__ W_a2,
                          const float* __restrict__ W_dense)
{
    __shared__ float t[32][33];
    int b = blockIdx.x;
    const float* in; h16* out; int R, C, local;
    if (b < 2304)      { in = W_a1;    out = g_Wa1T; R = 1536; C = 1536; local = b; }
    else if (b < 3456) { in = W_a2;    out = g_Wa2T; R = 1536; C = 768;  local = b - 2304; }
    else               { in = W_dense; out = g_WdT;  R = 768;  C = 768;  local = b - 3456; }
    const int tx = C / 32;
    const int cx = local % tx, ry = local / tx;
    const int c0 = cx * 32, r0 = ry * 32;
    for (int i = threadIdx.y; i < 32; i += 8)
        t[i][threadIdx.x] = in[(long)(r0 + i) * C + c0 + threadIdx.x];
    __syncthreads();
    if (threadIdx.x < 16) {
        for (int i = threadIdx.y; i < 32; i += 8) {
            __half2 h = __floats2half2_rn(t[2 * threadIdx.x][i], t[2 * threadIdx.x + 1][i]);
            long o = (long)(c0 + i) * R + r0 + 2 * threadIdx.x;
            *reinterpret_cast<uint32_t*>(out + o) = reinterpret_cast<uint32_t&>(h);
        }
    }
}

// ---------------- seq -> cat[:, 0:768] fp16 (grid-stride) ----------------
__global__ void seq_cvt_kernel(const float* __restrict__ seq)
{
    long i0 = ((long)blockIdx.x * blockDim.x + threadIdx.x) * 4;
    long stride = (long)gridDim.x * blockDim.x * 4;
    const long total = (long)UU * DH;
    for (long i = i0; i < total; i += stride) {
        long row = i / DH, col = i - row * DH;
        float4 v = *reinterpret_cast<const float4*>(seq + i);
        __half2 h0 = __floats2half2_rn(v.x, v.y);
        __half2 h1 = __floats2half2_rn(v.z, v.w);
        *reinterpret_cast<uint2*>(g_cat + row * 2 * DH + col) =
            make_uint2(reinterpret_cast<uint32_t&>(h0), reinterpret_cast<uint32_t&>(h1));
    }
}

// ---------------- unary score + masked softmax pooling -> fp16 pool ----------------
__global__ void pool_kernel(const float* __restrict__ W_un, const float* __restrict__ b_un,
                            const int* __restrict__ starts, const int* __restrict__ ends)
{
    int sp = blockIdx.x, t = threadIdx.x;
    int lane = t & 31, w = t >> 5;
    int n = sp >> 3;
    int base = n * LSEQ + starts[sp];
    __shared__ float sS[JR];
    __shared__ float sProb[JR];

    for (int j = w; j < JR; j += 8) {
        int u = base + j; if (u > UU - 1) u = UU - 1;
        const float* fr = g_fused + (long)u * DH;
        float acc = 0.f;
        for (int k = lane; k < DH; k += 32) acc += fr[k] * W_un[k];
        for (int o = 16; o; o >>= 1) acc += __shfl_xor_sync(0xffffffffu, acc, o);
        if (lane == 0) sS[j] = acc + b_un[0];
    }
    __syncthreads();
    if (t == 0) {
        int width = ends[sp] - starts[sp] + 1;
        float mx = -1e30f;
        for (int j = 0; j < JR; j++) {
            float v = sS[j] + ((j < width) ? 0.f : -10000.f);
            sS[j] = v; mx = fmaxf(mx, v);
        }
        float sum = 0.f;
        for (int j = 0; j < JR; j++) { float e = expf(sS[j] - mx); sProb[j] = e; sum += e; }
        float inv = 1.f / sum;
        for (int j = 0; j < JR; j++) sProb[j] *= inv;
    }
    __syncthreads();
    for (int d = t; d < DH; d += 256) {
        float acc = 0.f;
        for (int j = 0; j < JR; j++) {
            int u = base + j; if (u > UU - 1) u = UU - 1;
            acc += sProb[j] * g_fused[(long)u * DH + d];
        }
        g_pool16[(long)sp * DH + d] = __float2half(acc);
    }
}

// ---------------- classifier ----------------
__global__ void cls_kernel(const float* __restrict__ W_cls, const float* __restrict__ b_cls,
                           float* __restrict__ out)
{
    int row = blockIdx.x, t = threadIdx.x;
    int lane = t & 31, c = t >> 5;
    const float* hr = g_hid + (long)row * DH;
    float acc = 0.f;
    for (int k = lane; k < DH; k += 32) acc += hr[k] * W_cls[k * 4 + c];
    for (int o = 16; o; o >>= 1) acc += __shfl_xor_sync(0xffffffffu, acc, o);
    if (lane == 0) out[row * 4 + c] = acc + b_cls[c];
}

// ---------------- launcher ----------------
extern "C" void kernel_launch(void* const* d_in, const int* in_sizes, int n_in,
                              void* d_out, int out_size)
{
    const float* enc_img  = (const float*)d_in[0];
    const float* seq      = (const float*)d_in[1];
    const int*   starts   = (const int*)d_in[3];
    const int*   ends     = (const int*)d_in[4];
    const float* W_align  = (const float*)d_in[5];
    const float* b_align  = (const float*)d_in[6];
    const float* Wq       = (const float*)d_in[7];
    const float* Wk       = (const float*)d_in[8];
    const float* Wv       = (const float*)d_in[9];
    const float* Wfc      = (const float*)d_in[10];
    const float* ln_g     = (const float*)d_in[11];
    const float* ln_b     = (const float*)d_in[12];
    const float* W_a1     = (const float*)d_in[13];
    const float* b_a1     = (const float*)d_in[14];
    const float* W_a2     = (const float*)d_in[15];
    const float* b_a2     = (const float*)d_in[16];
    const float* W_un     = (const float*)d_in[17];
    const float* b_un     = (const float*)d_in[18];
    const float* W_dense  = (const float*)d_in[19];
    const float* b_dense  = (const float*)d_in[20];
    const float* W_cls    = (const float*)d_in[21];
    const float* b_cls    = (const float*)d_in[22];

    h16 *enc, *walT, *wq, *wk, *wv, *wfT, *c1, *bqk, *wvfT, *kc, *vc, *cat, *wa1T, *f1, *wa2T;
    h16 *pp, *vt, *wdT, *pool16;
    float *pAO, *pFused, *pHid;
    cudaGetSymbolAddress((void**)&enc,  g_enc);
    cudaGetSymbolAddress((void**)&walT, g_WalT);
    cudaGetSymbolAddress((void**)&wq,   g_Wq);
    cudaGetSymbolAddress((void**)&wk,   g_Wk);
    cudaGetSymbolAddress((void**)&wv,   g_Wv);
    cudaGetSymbolAddress((void**)&wfT,  g_WfcT);
    cudaGetSymbolAddress((void**)&c1,   g_C1);
    cudaGetSymbolAddress((void**)&bqk,  g_Bqk);
    cudaGetSymbolAddress((void**)&wvfT, g_WvfT);
    cudaGetSymbolAddress((void**)&kc,   g_KC16);
    cudaGetSymbolAddress((void**)&vc,   g_VC16);
    cudaGetSymbolAddress((void**)&pp,   g_Pp);
    cudaGetSymbolAddress((void**)&vt,   g_Vt);
    cudaGetSymbolAddress((void**)&pAO,  g_attout);
    cudaGetSymbolAddress((void**)&cat,  g_cat);
    cudaGetSymbolAddress((void**)&wa1T, g_Wa1T);
    cudaGetSymbolAddress((void**)&f1,   g_f1);
    cudaGetSymbolAddress((void**)&wa2T, g_Wa2T);
    cudaGetSymbolAddress((void**)&wdT,  g_WdT);
    cudaGetSymbolAddress((void**)&pool16, g_pool16);
    cudaGetSymbolAddress((void**)&pFused, g_fused);
    cudaGetSymbolAddress((void**)&pHid, g_hid);

    cudaFuncSetAttribute(mm_g123, cudaFuncAttributeMaxDynamicSharedMemorySize, MM_SMEM);
    cudaFuncSetAttribute(mm_g45,  cudaFuncAttributeMaxDynamicSharedMemorySize, MM_SMEM);
    cudaFuncSetAttribute(mm_scores_softmax, cudaFuncAttributeMaxDynamicSharedMemorySize, MM_SMEM);
    cudaFuncSetAttribute(mmgemm<true,  true >, cudaFuncAttributeMaxDynamicSharedMemorySize, MM_SMEM);
    cudaFuncSetAttribute(mmgemm<false, false>, cudaFuncAttributeMaxDynamicSharedMemorySize, MM_SMEM);
    cudaFuncSetAttribute(mmgemm<false, true >, cudaFuncAttributeMaxDynamicSharedMemorySize, MM_SMEM);

    // static side stream + events (created once, on the uncaptured correctness call)
    static cudaStream_t s1 = nullptr;
    static cudaEvent_t evRoot = nullptr, evSide = nullptr, evG45 = nullptr, evTr = nullptr;
    if (s1 == nullptr) {
        cudaStreamCreateWithFlags(&s1, cudaStreamNonBlocking);
        cudaEventCreateWithFlags(&evRoot, cudaEventDisableTiming);
        cudaEventCreateWithFlags(&evSide, cudaEventDisableTiming);
        cudaEventCreateWithFlags(&evG45,  cudaEventDisableTiming);
        cudaEventCreateWithFlags(&evTr,   cudaEventDisableTiming);
    }

    const dim3 blk(256);

    // ---- fork side stream off main ----
    cudaEventRecord(evRoot, 0);
    cudaStreamWaitEvent(s1, evRoot, 0);

    // ---- side: independent conversions ----
    seq_cvt_kernel<<<1536, 256, 0, s1>>>(seq);
    cvtT_late<<<4032, dim3(32, 8), 0, s1>>>(W_a1, W_a2, W_dense);
    cudaEventRecord(evSide, s1);

    // ---- main: conversions + big GEMMs ----
    cvt_all<<<2048, 256>>>(enc_img, Wq, Wk, Wv);
    cvtT_early<<<6144, dim3(32, 8)>>>(W_align, Wfc);
    mm_g123<<<dim3(6, 7, 17), blk, MM_SMEM>>>(
        enc, walT, c1, b_align, wq, wk, bqk, wfT, wv, wvfT);
    mm_g45<<<dim3(6, 7, 16), blk, MM_SMEM>>>(c1, bqk, wvfT, kc, vc);
    cudaEventRecord(evG45, 0);

    // ---- side: V transpose (needs g45) concurrent with scores on main ----
    cudaStreamWaitEvent(s1, evG45, 0);
    transpose_v<<<dim3(DH / 32, 2, NB * HH), dim3(32, 8), 0, s1>>>();
    cudaEventRecord(evTr, s1);

    // ---- main: scores (needs cat from side seq_cvt) ----
    cudaStreamWaitEvent(0, evSide, 0);
    mm_scores_softmax<<<dim3(1, 1, NB * HH), blk, MM_SMEM>>>(cat, kc);

    // ---- main: attention out (needs Vt from side) ----
    cudaStreamWaitEvent(0, evTr, 0);
    mmgemm<false, false><<<dim3(6, 1, NB), blk, MM_SMEM>>>(
        pp, KP, (long)LSEQ * KP, vt, KP, (long)DH * KP,
        pAO, nullptr, DH, (long)LSEQ * DH, nullptr, LSEQ, DH, KP, DH);
    ln_cat<<<UU / 16, 256>>>(seq, ln_g, ln_b);

    // ---- fusion MLP on 2048 tokens ----
    mmgemm<true, true><<<dim3(12, 16, 1), blk, MM_SMEM>>>(
        cat, 2 * DH, 0, wa1T, 2 * DH, 0,
        nullptr, f1, 2 * DH, 0, b_a1, UU, 2 * DH, 2 * DH, 2 * DH);
    mmgemm<false, false><<<dim3(6, 16, 1), blk, MM_SMEM>>>(
        f1, 2 * DH, 0, wa2T, 2 * DH, 0,
        pFused, nullptr, DH, 0, b_a2, UU, DH, 2 * DH, DH);

    // ---- pooling + head ----
    pool_kernel<<<NM, 256>>>(W_un, b_un, starts, ends);
    mmgemm<false, true><<<dim3(6, 1, 1), blk, MM_SMEM>>>(
        pool16, DH, 0, wdT, DH, 0,
        pHid, nullptr, DH, 0, b_dense, NM, DH, DH, DH);
    cls_kernel<<<NM, 128>>>(W_cls, b_cls, (float*)d_out);
}

// round 14
// speedup vs baseline: 5.8310x; 1.0089x over previous
#include <cuda_runtime.h>
#include <cuda_fp16.h>
#include <math.h>
#include <stdint.h>

// ---------------- problem constants ----------------
#define NB    16
#define LSEQ  128
#define DH    768
#define MSP   8
#define HH    8
#define JR    30
#define RR    49
#define IMGD  2048
#define NM    128
#define UU    2048
#define NR    784
#define KP    448

typedef __half h16;

// ---------------- scratch ----------------
__device__ h16 g_enc[NR * IMGD];
__device__ h16 g_WalT[DH * IMGD];
__device__ h16 g_Wq[DH * HH * DH];
__device__ h16 g_Wk[DH * HH * DH];
__device__ h16 g_Wv[DH * HH * DH];
__device__ h16 g_WfcT[DH * HH * DH];
__device__ h16 g_C1[NR * DH];
__device__ h16 g_Bqk[HH * DH * DH];
__device__ h16 g_WvfT[HH * DH * DH];
__device__ h16 g_KC16[HH * NR * DH];
__device__ h16 g_VC16[HH * NR * DH];
__device__ h16 g_Pp[NB * LSEQ * KP];
__device__ h16 g_Vt[NB * DH * KP];
__device__ float g_attout[UU * DH];
__device__ h16 g_cat[UU * 2 * DH];
__device__ h16 g_Wa1T[2*DH * 2*DH];
__device__ h16 g_f1[UU * 2 * DH];
__device__ h16 g_Wa2T[DH * 2*DH];
__device__ h16 g_WdT[DH * DH];
__device__ float g_fused[UU * DH];
__device__ h16 g_pool16[NM * DH];
__device__ float g_hid[NM * DH];

// ---------------- helpers ----------------
__device__ __forceinline__ uint32_t smem_u32(const void* p) {
    uint32_t a;
    asm("{ .reg .u64 t; cvta.to.shared.u64 t, %1; cvt.u32.u64 %0, t; }" : "=r"(a) : "l"(p));
    return a;
}

__device__ __forceinline__ void ldm_x4(uint32_t* r, uint32_t addr) {
    asm volatile("ldmatrix.sync.aligned.m8n8.x4.shared.b16 {%0,%1,%2,%3}, [%4];"
                 : "=r"(r[0]), "=r"(r[1]), "=r"(r[2]), "=r"(r[3]) : "r"(addr));
}

__device__ __forceinline__ void mma16816(float* c, const uint32_t* a, uint32_t b0, uint32_t b1) {
    asm volatile(
        "mma.sync.aligned.m16n8k16.row.col.f32.f16.f16.f32 "
        "{%0,%1,%2,%3}, {%4,%5,%6,%7}, {%8,%9}, {%0,%1,%2,%3};"
        : "+f"(c[0]), "+f"(c[1]), "+f"(c[2]), "+f"(c[3])
        : "r"(a[0]), "r"(a[1]), "r"(a[2]), "r"(a[3]), "r"(b0), "r"(b1));
}

__device__ __forceinline__ void cpa16(uint32_t dst, const void* src) {
    asm volatile("cp.async.ca.shared.global [%0], [%1], 16;" :: "r"(dst), "l"(src));
}
__device__ __forceinline__ void cpa_commit() {
    asm volatile("cp.async.commit_group;" ::: "memory");
}
template<int N_>
__device__ __forceinline__ void cpa_wait() {
    asm volatile("cp.async.wait_group %0;" :: "n"(N_) : "memory");
}

__device__ __forceinline__ uint2 cvt8lo(float4 a, float4 b) {
    __half2 h0 = __floats2half2_rn(a.x, a.y);
    __half2 h1 = __floats2half2_rn(a.z, a.w);
    (void)b;
    return make_uint2(reinterpret_cast<uint32_t&>(h0), reinterpret_cast<uint32_t&>(h1));
}

// ---------------- fp16 tensor-core GEMM core v4 ----------------
#define BM 128
#define BN 128
#define BK 64
#define T_B 16384
#define STAGE_B 32768
#define MM_SMEM (2 * STAGE_B)

template<bool OUT_F16, bool TANH_ACT>
__device__ __forceinline__ void mm_body(
    const h16* __restrict__ A, int lda,
    const h16* __restrict__ B, int ldb,
    float* __restrict__ Cf, h16* __restrict__ Ch, int ldc,
    const float* __restrict__ bias, int M, int N, int K, int nst)
{
    extern __shared__ char dsm[];
    const uint32_t u_sm = smem_u32(dsm);

    const int tid = threadIdx.x, lane = tid & 31, wid = tid >> 5;
    const int wr = wid >> 1, wc = wid & 1;
    const int m0 = blockIdx.y * BM, n0 = blockIdx.x * BN;

    float acc[2][8][4];
#pragma unroll
    for (int i = 0; i < 2; i++)
#pragma unroll
        for (int j = 0; j < 8; j++)
#pragma unroll
            for (int e = 0; e < 4; e++) acc[i][j][e] = 0.f;

    const int lrow = lane & 15;
    const int khalf = lane >> 4;
    const int xk = lrow & 7;
    const uint32_t rA = (uint32_t)((wr * 32 + lrow) * 128);
    const uint32_t rB = (uint32_t)(T_B) + (uint32_t)((wc * 64 + lrow) * 128);

    auto load_stage = [&](int st, int k0) {
        const uint32_t sbase = u_sm + (uint32_t)(st * STAGE_B);
#pragma unroll
        for (int i = 0; i < 8; i++) {
            int u = tid + i * 256;
            int v = u & 1023;
            int r = v >> 3;
            int g = v & 7;
            const h16* src;
            uint32_t toff;
            if (u < 1024) { int ga = m0 + r; if (ga > M - 1) ga = M - 1;
                            src = A + (long)ga * lda + k0 + g * 8; toff = 0; }
            else          { int gb = n0 + r; if (gb > N - 1) gb = N - 1;
                            src = B + (long)gb * ldb + k0 + g * 8; toff = T_B; }
            uint32_t doff = toff + (uint32_t)(r * 128) + (uint32_t)(((g ^ (r & 7)) << 4));
            cpa16(sbase + doff, src);
        }
    };

    const int nch = K / BK;
    load_stage(0, 0);  cpa_commit();

    for (int ch = 0; ch < nch; ch++) {
        cpa_wait<0>();
        __syncthreads();
        if (ch + 1 < nch) {
            load_stage((ch + 1) & 1, (ch + 1) * BK);
            cpa_commit();
        }

        const uint32_t so = u_sm + (uint32_t)((ch & 1) * STAGE_B);
#pragma unroll
        for (int ks = 0; ks < 4; ks++) {
            const uint32_t sw = (uint32_t)((((ks * 2) | khalf) ^ xk) << 4);
            uint32_t bh[4][4];
#pragma unroll
            for (int nt = 0; nt < 4; nt++)
                ldm_x4(bh[nt], so + rB + (uint32_t)(nt * 2048) + sw);
#pragma unroll
            for (int mi = 0; mi < 2; mi++) {
                uint32_t ah[4];
                ldm_x4(ah, so + rA + (uint32_t)(mi * 2048) + sw);
#pragma unroll
                for (int nt = 0; nt < 4; nt++) {
#pragma unroll
                    for (int j = 0; j < 2; j++)
                        mma16816(acc[mi][nt * 2 + j], ah, bh[nt][j], bh[nt][j + 2]);
                }
            }
        }
    }

    const int er = m0 + wr * 32 + (lane >> 2);
    const int ec = n0 + wc * 64 + (lane & 3) * 2;
#pragma unroll
    for (int mi = 0; mi < 2; mi++) {
#pragma unroll
        for (int nj = 0; nj < 8; nj++) {
            const int col = ec + nj * 8;
            if (col >= nst) continue;
            float bv0 = 0.f, bv1 = 0.f;
            if (bias) { bv0 = bias[col]; bv1 = bias[col + 1]; }
#pragma unroll
            for (int half = 0; half < 2; half++) {
                const int row = er + mi * 16 + half * 8;
                if (row >= M) continue;
                float v0 = acc[mi][nj][half * 2 + 0] + bv0;
                float v1 = acc[mi][nj][half * 2 + 1] + bv1;
                if (TANH_ACT) { v0 = tanhf(v0); v1 = tanhf(v1); }
                const long base = (long)row * ldc + col;
                if (OUT_F16) {
                    __half2 h = __floats2half2_rn(v0, v1);
                    *reinterpret_cast<uint32_t*>(Ch + base) = reinterpret_cast<uint32_t&>(h);
                } else {
                    *reinterpret_cast<float2*>(Cf + base) = make_float2(v0, v1);
                }
            }
        }
    }
}

template<bool OUT_F16, bool TANH_ACT>
__global__ __launch_bounds__(256, 2)
void mmgemm(const h16* __restrict__ A, int lda, long sA,
            const h16* __restrict__ B, int ldb, long sB,
            float* __restrict__ Cf, h16* __restrict__ Ch,
            int ldc, long sC, const float* __restrict__ bias,
            int M, int N, int K, int nst)
{
    const long za = (long)blockIdx.z * sA, zb = (long)blockIdx.z * sB, zc = (long)blockIdx.z * sC;
    mm_body<OUT_F16, TANH_ACT>(
        A + za, lda, B + zb, ldb,
        Cf ? Cf + zc : nullptr, Ch ? Ch + zc : nullptr, ldc, bias, M, N, K, nst);
}

__global__ __launch_bounds__(256, 2)
void mm_g123(const h16* __restrict__ enc, const h16* __restrict__ walT,
             h16* __restrict__ c1, const float* __restrict__ b_align,
             const h16* __restrict__ wq, const h16* __restrict__ wk, h16* __restrict__ bqk,
             const h16* __restrict__ wfT, const h16* __restrict__ wv, h16* __restrict__ wvfT)
{
    int z = blockIdx.z;
    if (z == 0) {
        mm_body<true, false>(enc, IMGD, walT, IMGD, nullptr, c1, DH, b_align, NR, DH, IMGD, DH);
    } else {
        if (blockIdx.y * BM >= DH) return;
        z -= 1;
        const int set = z >> 3, h = z & 7;
        const long co = (long)h * DH;
        const long cc = (long)h * DH * DH;
        if (set == 0)
            mm_body<true, false>(wq + co, HH * DH, wk + co, HH * DH,
                                 nullptr, bqk + cc, DH, nullptr, DH, DH, DH, DH);
        else
            mm_body<true, false>(wfT + co, HH * DH, wv + co, HH * DH,
                                 nullptr, wvfT + cc, DH, nullptr, DH, DH, DH, DH);
    }
}

__global__ __launch_bounds__(256, 2)
void mm_g45(const h16* __restrict__ c1, const h16* __restrict__ bqk,
            const h16* __restrict__ wvfT, h16* __restrict__ kc, h16* __restrict__ vc)
{
    int z = blockIdx.z;
    const long NRD = (long)NR * DH;
    const long HD2 = (long)DH * DH;
    if (z < HH)
        mm_body<true, false>(c1, DH, bqk + (long)z * HD2, DH,
                             nullptr, kc + (long)z * NRD, DH, nullptr, NR, DH, DH, DH);
    else {
        z -= HH;
        mm_body<true, false>(c1, DH, wvfT + (long)z * HD2, DH,
                             nullptr, vc + (long)z * NRD, DH, nullptr, NR, DH, DH, DH);
    }
}

// ---------------- scores GEMM + fused softmax ----------------
__global__ __launch_bounds__(256, 2)
void mm_scores_softmax(const h16* __restrict__ cat, const h16* __restrict__ kc)
{
    extern __shared__ char dsm[];
    const uint32_t u_sm = smem_u32(dsm);
    const int z = blockIdx.z, n = z >> 3, hh = z & 7;
    const h16* A = cat + (long)n * LSEQ * 2 * DH;
    const h16* B = kc + ((long)hh * NR + (long)n * RR) * DH;
    const int lda = 2 * DH, ldb = DH;
    const int N = RR, K = DH;

    const int tid = threadIdx.x, lane = tid & 31, wid = tid >> 5;
    const int wr = wid >> 1, wc = wid & 1;

    float acc[2][8][4];
#pragma unroll
    for (int i = 0; i < 2; i++)
#pragma unroll
        for (int j = 0; j < 8; j++)
#pragma unroll
            for (int e = 0; e < 4; e++) acc[i][j][e] = 0.f;

    const int lrow = lane & 15;
    const int khalf = lane >> 4;
    const int xk = lrow & 7;
    const uint32_t rA = (uint32_t)((wr * 32 + lrow) * 128);
    const uint32_t rB = (uint32_t)(T_B) + (uint32_t)((wc * 64 + lrow) * 128);

    auto load_stage = [&](int st, int k0) {
        const uint32_t sbase = u_sm + (uint32_t)(st * STAGE_B);
#pragma unroll
        for (int i = 0; i < 8; i++) {
            int u = tid + i * 256;
            int v = u & 1023;
            int r = v >> 3;
            int g = v & 7;
            const h16* src;
            uint32_t toff;
            if (u < 1024) { src = A + (long)r * lda + k0 + g * 8; toff = 0; }
            else          { int gb = r; if (gb > N - 1) gb = N - 1;
                            src = B + (long)gb * ldb + k0 + g * 8; toff = T_B; }
            uint32_t doff = toff + (uint32_t)(r * 128) + (uint32_t)(((g ^ (r & 7)) << 4));
            cpa16(sbase + doff, src);
        }
    };

    const int nch = K / BK;
    load_stage(0, 0);  cpa_commit();

    for (int ch = 0; ch < nch; ch++) {
        cpa_wait<0>();
        __syncthreads();
        if (ch + 1 < nch) {
            load_stage((ch + 1) & 1, (ch + 1) * BK);
            cpa_commit();
        }
        const uint32_t so = u_sm + (uint32_t)((ch & 1) * STAGE_B);
#pragma unroll
        for (int ks = 0; ks < 4; ks++) {
            const uint32_t sw = (uint32_t)((((ks * 2) | khalf) ^ xk) << 4);
            uint32_t bh[4][4];
#pragma unroll
            for (int nt = 0; nt < 4; nt++)
                ldm_x4(bh[nt], so + rB + (uint32_t)(nt * 2048) + sw);
#pragma unroll
            for (int mi = 0; mi < 2; mi++) {
                uint32_t ah[4];
                ldm_x4(ah, so + rA + (uint32_t)(mi * 2048) + sw);
#pragma unroll
                for (int nt = 0; nt < 4; nt++) {
#pragma unroll
                    for (int j = 0; j < 2; j++)
                        mma16816(acc[mi][nt * 2 + j], ah, bh[nt][j], bh[nt][j + 2]);
                }
            }
        }
    }

    float* S = reinterpret_cast<float*>(dsm);
    __syncthreads();
    if (wc == 0) {
        const int er0 = wr * 32 + (lane >> 2);
        const int ec0 = (lane & 3) * 2;
#pragma unroll
        for (int mi = 0; mi < 2; mi++) {
#pragma unroll
            for (int nj = 0; nj < 8; nj++) {
                const int col = ec0 + nj * 8;
#pragma unroll
                for (int half = 0; half < 2; half++) {
                    const int row = er0 + mi * 16 + half * 8;
                    S[row * 65 + col]     = acc[mi][nj][half * 2 + 0];
                    S[row * 65 + col + 1] = acc[mi][nj][half * 2 + 1];
                }
            }
        }
    }
    __syncthreads();

    if (tid < 128) {
        const int t = tid;
        const float scale = rsqrtf((float)DH);
        float ex[RR];
        float mx = -1e30f;
#pragma unroll
        for (int r = 0; r < RR; r++) { float v = S[t * 65 + r] * scale; ex[r] = v; mx = fmaxf(mx, v); }
        float sum = 0.f;
#pragma unroll
        for (int r = 0; r < RR; r++) { float e = expf(ex[r] - mx); ex[r] = e; sum += e; }
        const float inv = 1.f / sum;
        h16* out = g_Pp + ((long)n * LSEQ + t) * KP + hh * RR;
#pragma unroll
        for (int r = 0; r < RR; r++) out[r] = __float2half(ex[r] * inv);
        if (hh == 0) {
            h16* pad = g_Pp + ((long)n * LSEQ + t) * KP + HH * RR;
            for (int i = 0; i < KP - HH * RR; i++) pad[i] = (h16)0.f;
        }
    }
}

// ---------------- VC fp16 -> Vt [n][d][h*49+r] ----------------
__global__ void transpose_v()
{
    __shared__ h16 tile[32][33];
    const int z = blockIdx.z, n = z >> 3, h = z & 7;
    const int d0 = blockIdx.x * 32, r0 = blockIdx.y * 32;
    const int tx = threadIdx.x, ty = threadIdx.y;
    for (int i = ty; i < 32; i += 8) {
        int r = r0 + i;
        h16 v = (h16)0.f;
        if (r < RR) v = g_VC16[((long)h * NR + (long)n * RR + r) * DH + d0 + tx];
        tile[i][tx] = v;
    }
    __syncthreads();
    for (int i = ty; i < 32; i += 8) {
        int r = r0 + tx;
        if (r < RR)
            g_Vt[((long)n * DH + d0 + i) * KP + h * RR + r] = tile[tx][i];
    }
}

// ---------------- residual + LN -> cat[:, 768:1536] fp16 ----------------
__global__ __launch_bounds__(256) void ln_cat(const float* __restrict__ seq,
                                              const float* __restrict__ gam,
                                              const float* __restrict__ bet)
{
    const int wid = threadIdx.x >> 5, lane = threadIdx.x & 31;
    for (int rr = 0; rr < 2; rr++) {
        const long u = (long)blockIdx.x * 16 + wid * 2 + rr;
        const float* ao = g_attout + u * DH;
        const float* sq = seq + u * DH;
        float s = 0.f;
        for (int k = lane; k < DH; k += 32) s += ao[k] + sq[k];
        for (int o = 16; o; o >>= 1) s += __shfl_xor_sync(0xffffffffu, s, o);
        float mu = s * (1.f / DH);
        float v = 0.f;
        for (int k = lane; k < DH; k += 32) { float d = ao[k] + sq[k] - mu; v += d * d; }
        for (int o = 16; o; o >>= 1) v += __shfl_xor_sync(0xffffffffu, v, o);
        float rstd = rsqrtf(v * (1.f / DH) + 1e-5f);
        h16* dst = g_cat + u * 2 * DH + DH;
        for (int k = lane * 2; k < DH; k += 64) {
            float a = (ao[k]     + sq[k]     - mu) * rstd * gam[k]     + bet[k];
            float b = (ao[k + 1] + sq[k + 1] - mu) * rstd * gam[k + 1] + bet[k + 1];
            __half2 h = __floats2half2_rn(a, b);
            *reinterpret_cast<uint32_t*>(dst + k) = reinterpret_cast<uint32_t&>(h);
        }
    }
}

// ---------------- merged straight conversions, 8-elem ILP ----------------
#define N_ENC (NR * IMGD)
#define N_W   (DH * HH * DH)
__global__ void cvt_all(const float* __restrict__ enc_img, const float* __restrict__ Wq,
                        const float* __restrict__ Wk, const float* __restrict__ Wv)
{
    const long total = (long)N_ENC + 3L * N_W;
    long i0 = ((long)blockIdx.x * blockDim.x + threadIdx.x) * 8;
    long stride = (long)gridDim.x * blockDim.x * 8;
    for (long i = i0; i < total; i += stride) {
        const float* src; h16* dst; long off;
        if (i < N_ENC)                { src = enc_img; dst = g_enc; off = i; }
        else if (i < N_ENC + N_W)     { src = Wq; dst = g_Wq; off = i - N_ENC; }
        else if (i < N_ENC + 2L*N_W)  { src = Wk; dst = g_Wk; off = i - N_ENC - N_W; }
        else                          { src = Wv; dst = g_Wv; off = i - N_ENC - 2L*N_W; }
        float4 a = *reinterpret_cast<const float4*>(src + off);
        float4 b = *reinterpret_cast<const float4*>(src + off + 4);
        __half2 h0 = __floats2half2_rn(a.x, a.y);
        __half2 h1 = __floats2half2_rn(a.z, a.w);
        __half2 h2 = __floats2half2_rn(b.x, b.y);
        __half2 h3 = __floats2half2_rn(b.z, b.w);
        uint4 o;
        o.x = reinterpret_cast<uint32_t&>(h0);
        o.y = reinterpret_cast<uint32_t&>(h1);
        o.z = reinterpret_cast<uint32_t&>(h2);
        o.w = reinterpret_cast<uint32_t&>(h3);
        *reinterpret_cast<uint4*>(dst + off) = o;
    }
}

// ---------------- transposed conversions, early (W_align, Wfc) ----------------
__global__ void cvtT_early(const float* __restrict__ W_align, const float* __restrict__ Wfc)
{
    __shared__ float t[32][33];
    int b = blockIdx.x;
    const float* in; h16* out; int R, C, local;
    if (b < 1536) { in = W_align; out = g_WalT; R = 2048; C = 768; local = b; }
    else          { in = Wfc;     out = g_WfcT; R = 6144; C = 768; local = b - 1536; }
    const int tx = C / 32;
    const int cx = local % tx, ry = local / tx;
    const int c0 = cx * 32, r0 = ry * 32;
    for (int i = threadIdx.y; i < 32; i += 8)
        t[i][threadIdx.x] = in[(long)(r0 + i) * C + c0 + threadIdx.x];
    __syncthreads();
    if (threadIdx.x < 16) {
        for (int i = threadIdx.y; i < 32; i += 8) {
            __half2 h = __floats2half2_rn(t[2 * threadIdx.x][i], t[2 * threadIdx.x + 1][i]);
            long o = (long)(c0 + i) * R + r0 + 2 * threadIdx.x;
            *reinterpret_cast<uint32_t*>(out + o) = reinterpret_cast<uint32_t&>(h);
        }
    }
}

// ---------------- transposed conversions, late (W_a1, W_a2, W_dense) ----------------
__global__ void cvtT_late(const float* __restrict__ W_a1, const float* __restrict__ W_a2,
                          const float* __restrict__ W_dense)
{
    __shared__ float t[32][33];
    int b = blockIdx.x;
    const float* in; h16* out; int R, C, local;
    if (b < 2304)      { in = W_a1;    out = g_Wa1T; R = 1536; C = 1536; local = b; }
    else if (b < 3456) { in = W_a2;    out = g_Wa2T; R = 1536; C = 768;  local = b - 2304; }
    else               { in = W_dense; out = g_WdT;  R = 768;  C = 768;  local = b - 3456; }
    const int tx = C / 32;
    const int cx = local % tx, ry = local / tx;
    const int c0 = cx * 32, r0 = ry * 32;
    for (int i = threadIdx.y; i < 32; i += 8)
        t[i][threadIdx.x] = in[(long)(r0 + i) * C + c0 + threadIdx.x];
    __syncthreads();
    if (threadIdx.x < 16) {
        for (int i = threadIdx.y; i < 32; i += 8) {
            __half2 h = __floats2half2_rn(t[2 * threadIdx.x][i], t[2 * threadIdx.x + 1][i]);
            long o = (long)(c0 + i) * R + r0 + 2 * threadIdx.x;
            *reinterpret_cast<uint32_t*>(out + o) = reinterpret_cast<uint32_t&>(h);
        }
    }
}

// ---------------- seq -> cat[:, 0:768] fp16 ----------------
__global__ void seq_cvt_kernel(const float* __restrict__ seq)
{
    long i0 = ((long)blockIdx.x * blockDim.x + threadIdx.x) * 4;
    long stride = (long)gridDim.x * blockDim.x * 4;
    const long total = (long)UU * DH;
    for (long i = i0; i < total; i += stride) {
        long row = i / DH, col = i - row * DH;
        float4 v = *reinterpret_cast<const float4*>(seq + i);
        __half2 h0 = __floats2half2_rn(v.x, v.y);
        __half2 h1 = __floats2half2_rn(v.z, v.w);
        *reinterpret_cast<uint2*>(g_cat + row * 2 * DH + col) =
            make_uint2(reinterpret_cast<uint32_t&>(h0), reinterpret_cast<uint32_t&>(h1));
    }
}

// ---------------- pooling -> fp16 ----------------
__global__ void pool_kernel(const float* __restrict__ W_un, const float* __restrict__ b_un,
                            const int* __restrict__ starts, const int* __restrict__ ends)
{
    int sp = blockIdx.x, t = threadIdx.x;
    int lane = t & 31, w = t >> 5;
    int n = sp >> 3;
    int base = n * LSEQ + starts[sp];
    __shared__ float sS[JR];
    __shared__ float sProb[JR];

    for (int j = w; j < JR; j += 8) {
        int u = base + j; if (u > UU - 1) u = UU - 1;
        const float* fr = g_fused + (long)u * DH;
        float acc = 0.f;
        for (int k = lane; k < DH; k += 32) acc += fr[k] * W_un[k];
        for (int o = 16; o; o >>= 1) acc += __shfl_xor_sync(0xffffffffu, acc, o);
        if (lane == 0) sS[j] = acc + b_un[0];
    }
    __syncthreads();
    if (t == 0) {
        int width = ends[sp] - starts[sp] + 1;
        float mx = -1e30f;
        for (int j = 0; j < JR; j++) {
            float v = sS[j] + ((j < width) ? 0.f : -10000.f);
            sS[j] = v; mx = fmaxf(mx, v);
        }
        float sum = 0.f;
        for (int j = 0; j < JR; j++) { float e = expf(sS[j] - mx); sProb[j] = e; sum += e; }
        float inv = 1.f / sum;
        for (int j = 0; j < JR; j++) sProb[j] *= inv;
    }
    __syncthreads();
    for (int d = t; d < DH; d += 256) {
        float acc = 0.f;
        for (int j = 0; j < JR; j++) {
            int u = base + j; if (u > UU - 1) u = UU - 1;
            acc += sProb[j] * g_fused[(long)u * DH + d];
        }
        g_pool16[(long)sp * DH + d] = __float2half(acc);
    }
}

// ---------------- classifier ----------------
__global__ void cls_kernel(const float* __restrict__ W_cls, const float* __restrict__ b_cls,
                           float* __restrict__ out)
{
    int row = blockIdx.x, t = threadIdx.x;
    int lane = t & 31, c = t >> 5;
    const float* hr = g_hid + (long)row * DH;
    float acc = 0.f;
    for (int k = lane; k < DH; k += 32) acc += hr[k] * W_cls[k * 4 + c];
    for (int o = 16; o; o >>= 1) acc += __shfl_xor_sync(0xffffffffu, acc, o);
    if (lane == 0) out[row * 4 + c] = acc + b_cls[c];
}

// ---------------- launcher ----------------
extern "C" void kernel_launch(void* const* d_in, const int* in_sizes, int n_in,
                              void* d_out, int out_size)
{
    const float* enc_img  = (const float*)d_in[0];
    const float* seq      = (const float*)d_in[1];
    const int*   starts   = (const int*)d_in[3];
    const int*   ends     = (const int*)d_in[4];
    const float* W_align  = (const float*)d_in[5];
    const float* b_align  = (const float*)d_in[6];
    const float* Wq       = (const float*)d_in[7];
    const float* Wk       = (const float*)d_in[8];
    const float* Wv       = (const float*)d_in[9];
    const float* Wfc      = (const float*)d_in[10];
    const float* ln_g     = (const float*)d_in[11];
    const float* ln_b     = (const float*)d_in[12];
    const float* W_a1     = (const float*)d_in[13];
    const float* b_a1     = (const float*)d_in[14];
    const float* W_a2     = (const float*)d_in[15];
    const float* b_a2     = (const float*)d_in[16];
    const float* W_un     = (const float*)d_in[17];
    const float* b_un     = (const float*)d_in[18];
    const float* W_dense  = (const float*)d_in[19];
    const float* b_dense  = (const float*)d_in[20];
    const float* W_cls    = (const float*)d_in[21];
    const float* b_cls    = (const float*)d_in[22];

    h16 *enc, *walT, *wq, *wk, *wv, *wfT, *c1, *bqk, *wvfT, *kc, *vc, *cat, *wa1T, *f1, *wa2T;
    h16 *pp, *vt, *wdT, *pool16;
    float *pAO, *pFused, *pHid;
    cudaGetSymbolAddress((void**)&enc,  g_enc);
    cudaGetSymbolAddress((void**)&walT, g_WalT);
    cudaGetSymbolAddress((void**)&wq,   g_Wq);
    cudaGetSymbolAddress((void**)&wk,   g_Wk);
    cudaGetSymbolAddress((void**)&wv,   g_Wv);
    cudaGetSymbolAddress((void**)&wfT,  g_WfcT);
    cudaGetSymbolAddress((void**)&c1,   g_C1);
    cudaGetSymbolAddress((void**)&bqk,  g_Bqk);
    cudaGetSymbolAddress((void**)&wvfT, g_WvfT);
    cudaGetSymbolAddress((void**)&kc,   g_KC16);
    cudaGetSymbolAddress((void**)&vc,   g_VC16);
    cudaGetSymbolAddress((void**)&pp,   g_Pp);
    cudaGetSymbolAddress((void**)&vt,   g_Vt);
    cudaGetSymbolAddress((void**)&pAO,  g_attout);
    cudaGetSymbolAddress((void**)&cat,  g_cat);
    cudaGetSymbolAddress((void**)&wa1T, g_Wa1T);
    cudaGetSymbolAddress((void**)&f1,   g_f1);
    cudaGetSymbolAddress((void**)&wa2T, g_Wa2T);
    cudaGetSymbolAddress((void**)&wdT,  g_WdT);
    cudaGetSymbolAddress((void**)&pool16, g_pool16);
    cudaGetSymbolAddress((void**)&pFused, g_fused);
    cudaGetSymbolAddress((void**)&pHid, g_hid);

    cudaFuncSetAttribute(mm_g123, cudaFuncAttributeMaxDynamicSharedMemorySize, MM_SMEM);
    cudaFuncSetAttribute(mm_g45,  cudaFuncAttributeMaxDynamicSharedMemorySize, MM_SMEM);
    cudaFuncSetAttribute(mm_scores_softmax, cudaFuncAttributeMaxDynamicSharedMemorySize, MM_SMEM);
    cudaFuncSetAttribute(mmgemm<true,  true >, cudaFuncAttributeMaxDynamicSharedMemorySize, MM_SMEM);
    cudaFuncSetAttribute(mmgemm<false, false>, cudaFuncAttributeMaxDynamicSharedMemorySize, MM_SMEM);
    cudaFuncSetAttribute(mmgemm<false, true >, cudaFuncAttributeMaxDynamicSharedMemorySize, MM_SMEM);

    static cudaStream_t s1 = nullptr;
    static cudaEvent_t evRoot = nullptr, evEarly = nullptr, evLate = nullptr,
                       evG45 = nullptr, evTr = nullptr;
    if (s1 == nullptr) {
        cudaStreamCreateWithFlags(&s1, cudaStreamNonBlocking);
        cudaEventCreateWithFlags(&evRoot,  cudaEventDisableTiming);
        cudaEventCreateWithFlags(&evEarly, cudaEventDisableTiming);
        cudaEventCreateWithFlags(&evLate,  cudaEventDisableTiming);
        cudaEventCreateWithFlags(&evG45,   cudaEventDisableTiming);
        cudaEventCreateWithFlags(&evTr,    cudaEventDisableTiming);
    }

    const dim3 blk(256);

    // ---- fork ----
    cudaEventRecord(evRoot, 0);
    cudaStreamWaitEvent(s1, evRoot, 0);

    // ---- side: transposed conversions (early first), then the rest ----
    cvtT_early<<<6144, dim3(32, 8), 0, s1>>>(W_align, Wfc);
    cudaEventRecord(evEarly, s1);
    seq_cvt_kernel<<<1536, 256, 0, s1>>>(seq);
    cvtT_late<<<4032, dim3(32, 8), 0, s1>>>(W_a1, W_a2, W_dense);
    cudaEventRecord(evLate, s1);

    // ---- main: straight conversions concurrently, then big GEMMs ----
    cvt_all<<<2048, 256>>>(enc_img, Wq, Wk, Wv);
    cudaStreamWaitEvent(0, evEarly, 0);
    mm_g123<<<dim3(6, 7, 17), blk, MM_SMEM>>>(
        enc, walT, c1, b_align, wq, wk, bqk, wfT, wv, wvfT);
    mm_g45<<<dim3(6, 7, 16), blk, MM_SMEM>>>(c1, bqk, wvfT, kc, vc);
    cudaEventRecord(evG45, 0);

    // ---- side: V transpose after g45, concurrent with scores ----
    cudaStreamWaitEvent(s1, evG45, 0);
    transpose_v<<<dim3(DH / 32, 2, NB * HH), dim3(32, 8), 0, s1>>>();
    cudaEventRecord(evTr, s1);

    // ---- main: scores (needs seq half of cat) ----
    cudaStreamWaitEvent(0, evLate, 0);
    mm_scores_softmax<<<dim3(1, 1, NB * HH), blk, MM_SMEM>>>(cat, kc);

    // ---- main: attention out (needs Vt) ----
    cudaStreamWaitEvent(0, evTr, 0);
    mmgemm<false, false><<<dim3(6, 1, NB), blk, MM_SMEM>>>(
        pp, KP, (long)LSEQ * KP, vt, KP, (long)DH * KP,
        pAO, nullptr, DH, (long)LSEQ * DH, nullptr, LSEQ, DH, KP, DH);
    ln_cat<<<UU / 16, 256>>>(seq, ln_g, ln_b);

    // ---- fusion MLP ----
    mmgemm<true, true><<<dim3(12, 16, 1), blk, MM_SMEM>>>(
        cat, 2 * DH, 0, wa1T, 2 * DH, 0,
        nullptr, f1, 2 * DH, 0, b_a1, UU, 2 * DH, 2 * DH, 2 * DH);
    mmgemm<false, false><<<dim3(6, 16, 1), blk, MM_SMEM>>>(
        f1, 2 * DH, 0, wa2T, 2 * DH, 0,
        pFused, nullptr, DH, 0, b_a2, UU, DH, 2 * DH, DH);

    // ---- pooling + head ----
    pool_kernel<<<NM, 256>>>(W_un, b_un, starts, ends);
    mmgemm<false, true><<<dim3(6, 1, 1), blk, MM_SMEM>>>(
        pool16, DH, 0, wdT, DH, 0,
        pHid, nullptr, DH, 0, b_dense, NM, DH, DH, DH);
    cls_kernel<<<NM, 128>>>(W_cls, b_cls, (float*)d_out);
}